// round 1
// baseline (speedup 1.0000x reference)
#include <cuda_runtime.h>

#define BB 16
#define CC 32
#define NN 500
#define TT 64
#define LL 4

// ---------------- scratch (static __device__, no allocations) ----------------
__device__ __align__(16) float g_h[4][16384000];      // layer outputs h1..h4
__device__ __align__(16) float g_y0[16384000];
__device__ __align__(16) float g_z1[16384000];
__device__ __align__(16) float g_z2[16384000];
__device__ __align__(16) float g_logits[16 * 5 * 500 * 64];
__device__ float g_bnsum[32 * 16], g_bnsq[32 * 16];
__device__ float g_scale[32], g_shift[32];
__device__ __align__(16) float g_rwt[4][32 * 32];     // [c][o]
__device__ __align__(16) float g_awt[4][96 * 32];     // [ck][o]
__device__ __align__(16) float g_gwt[4][96 * 32];
__device__ __align__(16) float g_gcwt[4][96 * 32];    // [ic][o]
__device__ __align__(16) float g_w1t[32 * 64];        // [c][d]
__device__ __align__(16) float g_w2t[64 * 64];        // [k][d]

// ---------------- weight transposes ----------------
__global__ void prep_weights(const float* __restrict__ rw, const float* __restrict__ aw,
                             const float* __restrict__ gw, const float* __restrict__ gcw,
                             const float* __restrict__ w1, const float* __restrict__ w2) {
    int tid = blockIdx.x * blockDim.x + threadIdx.x;
    int nt = gridDim.x * blockDim.x;
    for (int l = 0; l < 4; l++) {
        for (int i = tid; i < 32 * 32; i += nt) {
            int o = i / 32, c = i % 32;
            g_rwt[l][c * 32 + o] = rw[l * 1024 + o * 32 + c];
        }
        for (int i = tid; i < 32 * 96; i += nt) {
            int o = i / 96, ck = i % 96;
            g_awt[l][ck * 32 + o]  = aw[l * 3072 + i];
            g_gwt[l][ck * 32 + o]  = gw[l * 3072 + i];
            g_gcwt[l][ck * 32 + o] = gcw[l * 3072 + i];
        }
    }
    for (int i = tid; i < 64 * 32; i += nt) { int d = i / 32, c = i % 32; g_w1t[c * 64 + d] = w1[i]; }
    for (int i = tid; i < 64 * 64; i += nt) { int d = i / 64, k = i % 64; g_w2t[k * 64 + d] = w2[i]; }
}

// ---------------- batchnorm stats ----------------
__global__ void bn_partial(const float* __restrict__ x, int layer) {
    const float* hin = (layer == 0) ? x : g_h[layer - 1];
    int c = blockIdx.x, b = blockIdx.y;
    const float* p = hin + (size_t)(b * 32 + c) * 32000;
    float s = 0.f, q = 0.f;
    for (int i = threadIdx.x; i < 32000; i += 256) {
        float v = __ldg(p + i);
        s += v; q += v * v;
    }
    for (int o = 16; o; o >>= 1) {
        s += __shfl_down_sync(0xffffffffu, s, o);
        q += __shfl_down_sync(0xffffffffu, q, o);
    }
    __shared__ float ss[8], qq[8];
    int w = threadIdx.x >> 5;
    if ((threadIdx.x & 31) == 0) { ss[w] = s; qq[w] = q; }
    __syncthreads();
    if (threadIdx.x == 0) {
        float S = 0.f, Q = 0.f;
        for (int i = 0; i < 8; i++) { S += ss[i]; Q += qq[i]; }
        g_bnsum[c * 16 + b] = S;
        g_bnsq[c * 16 + b] = Q;
    }
}

__global__ void bn_finalize(const float* __restrict__ gamma, const float* __restrict__ beta) {
    int c = threadIdx.x;
    float S = 0.f, Q = 0.f;
    for (int b = 0; b < 16; b++) { S += g_bnsum[c * 16 + b]; Q += g_bnsq[c * 16 + b]; }
    const float inv = 1.0f / 512000.0f;
    float m = S * inv;
    float var = Q * inv - m * m;
    float rstd = rsqrtf(var + 1e-5f);
    float sc = gamma[c] * rstd;
    g_scale[c] = sc;
    g_shift[c] = beta[c] - m * sc;
}

// ---------------- fused: bn+relu, res 1x1, causal convs, gate, gc pre-projection ----------------
__global__ __launch_bounds__(256) void st_front(
    const float* __restrict__ x, int layer,
    const float* __restrict__ rb, const float* __restrict__ ab,
    const float* __restrict__ gb, const float* __restrict__ gcb) {
    const float* hin = (layer == 0) ? x : g_h[layer - 1];

    __shared__ __align__(16) float xs[32][64];
    __shared__ __align__(16) float ysh[96][64];   // ysh[c*3+kk][t] = y[c][t+kk-2]
    __shared__ __align__(16) float x1s[32][64];

    int tid = threadIdx.x;
    int b = blockIdx.x / 500, n = blockIdx.x % 500;
    const float* base = hin + ((size_t)b * 32 * 500 + n) * 64;

    for (int i = tid; i < 96 * 64; i += 256) (&ysh[0][0])[i] = 0.f;
    __syncthreads();
    for (int i = tid; i < 2048; i += 256) {
        int c = i >> 6, t = i & 63;
        float xv = __ldg(base + (size_t)c * 32000 + t);
        xs[c][t] = xv;
        float y = fmaxf(g_scale[c] * xv + g_shift[c], 0.f);
        ysh[c * 3 + 2][t] = y;
        if (t < 63) ysh[c * 3 + 1][t + 1] = y;
        if (t < 62) ysh[c * 3 + 0][t + 2] = y;
    }
    __syncthreads();

    int o = tid >> 3;
    int t0 = (tid & 7) * 8;
    const float* rwt = g_rwt[layer];
    const float* awt = g_awt[layer];
    const float* gwt = g_gwt[layer];

    float racc[8], aacc[8], gacc[8];
#pragma unroll
    for (int j = 0; j < 8; j++) { racc[j] = 0.f; aacc[j] = 0.f; gacc[j] = 0.f; }

#pragma unroll 4
    for (int c = 0; c < 32; c++) {
        float w = rwt[c * 32 + o];
        float v[8];
        *(float4*)&v[0] = *(const float4*)&xs[c][t0];
        *(float4*)&v[4] = *(const float4*)&xs[c][t0 + 4];
#pragma unroll
        for (int j = 0; j < 8; j++) racc[j] += w * v[j];
    }
#pragma unroll 4
    for (int ck = 0; ck < 96; ck++) {
        float wa = awt[ck * 32 + o];
        float wg = gwt[ck * 32 + o];
        float v[8];
        *(float4*)&v[0] = *(const float4*)&ysh[ck][t0];
        *(float4*)&v[4] = *(const float4*)&ysh[ck][t0 + 4];
#pragma unroll
        for (int j = 0; j < 8; j++) { aacc[j] += wa * v[j]; gacc[j] += wg * v[j]; }
    }

    float rbv = rb[o], abv = ab[o], gbv = gb[o];
#pragma unroll
    for (int j = 0; j < 8; j++) {
        float a = aacc[j] + abv + racc[j] + rbv;
        float g = gacc[j] + gbv;
        x1s[o][t0 + j] = tanhf(a) * (1.f / (1.f + expf(-g)));
    }
    __syncthreads();

    const float* gcwt = g_gcwt[layer];
    float y0a[8], z1a[8], z2a[8];
#pragma unroll
    for (int j = 0; j < 8; j++) { y0a[j] = 0.f; z1a[j] = 0.f; z2a[j] = 0.f; }
#pragma unroll 4
    for (int c = 0; c < 32; c++) {
        float w0 = gcwt[c * 32 + o];
        float w1 = gcwt[(32 + c) * 32 + o];
        float w2 = gcwt[(64 + c) * 32 + o];
        float v[8];
        *(float4*)&v[0] = *(const float4*)&x1s[c][t0];
        *(float4*)&v[4] = *(const float4*)&x1s[c][t0 + 4];
#pragma unroll
        for (int j = 0; j < 8; j++) {
            y0a[j] += w0 * v[j];
            z1a[j] += w1 * v[j];
            z2a[j] += w2 * v[j];
        }
    }
    float gcbv = gcb[o];
    size_t oidx = (((size_t)b * 32 + o) * 500 + n) * 64 + t0;
    float ob[8];
#pragma unroll
    for (int j = 0; j < 8; j++) ob[j] = y0a[j] + gcbv;
    *(float4*)(g_y0 + oidx) = *(float4*)&ob[0];
    *(float4*)(g_y0 + oidx + 4) = *(float4*)&ob[4];
    *(float4*)(g_z1 + oidx) = *(float4*)&z1a[0];
    *(float4*)(g_z1 + oidx + 4) = *(float4*)&z1a[4];
    *(float4*)(g_z2 + oidx) = *(float4*)&z2a[0];
    *(float4*)(g_z2 + oidx + 4) = *(float4*)&z2a[4];
}

// ---------------- graph diffusion GEMM: h = y0 + A1^T z1 + A2^T z2 ----------------
__global__ __launch_bounds__(128) void graph_gemm(const float* __restrict__ A, int layer) {
    __shared__ __align__(16) float As[8][128];
    __shared__ __align__(16) float Zs[8][64];
    int tid = threadIdx.x;
    int m0 = blockIdx.x * 128;
    int bo = blockIdx.y;
    int ty = tid >> 3, tx = tid & 7;
    int lr = tid >> 4;
    int lcA = (tid & 15) * 8;
    int lcZ = (tid & 15) * 4;
    size_t zbase = (size_t)bo * 32000;

    float acc[8][8];
#pragma unroll
    for (int i = 0; i < 8; i++)
#pragma unroll
        for (int j = 0; j < 8; j++) acc[i][j] = 0.f;

    for (int e = 0; e < 2; e++) {
        const float* Ae = A + (size_t)e * 250000;
        const float* Ze = (e ? g_z2 : g_z1) + zbase;
        for (int kt = 0; kt < 63; kt++) {
            int v = kt * 8 + lr;
            int w = m0 + lcA;
            if (v < 500 && w + 7 < 500) {
                const float* p = Ae + (size_t)v * 500 + w;
                *(float4*)&As[lr][lcA] = __ldg((const float4*)p);
                *(float4*)&As[lr][lcA + 4] = __ldg((const float4*)(p + 4));
            } else {
#pragma unroll
                for (int q = 0; q < 8; q++)
                    As[lr][lcA + q] = (v < 500 && (w + q) < 500) ? __ldg(Ae + (size_t)v * 500 + w + q) : 0.f;
            }
            if (v < 500)
                *(float4*)&Zs[lr][lcZ] = __ldg((const float4*)(Ze + (size_t)v * 64 + lcZ));
            else
                *(float4*)&Zs[lr][lcZ] = make_float4(0.f, 0.f, 0.f, 0.f);
            __syncthreads();
#pragma unroll
            for (int k = 0; k < 8; k++) {
                float a[8], bv[8];
                *(float4*)&a[0] = *(const float4*)&As[k][ty * 8];
                *(float4*)&a[4] = *(const float4*)&As[k][ty * 8 + 4];
                *(float4*)&bv[0] = *(const float4*)&Zs[k][tx * 8];
                *(float4*)&bv[4] = *(const float4*)&Zs[k][tx * 8 + 4];
#pragma unroll
                for (int i = 0; i < 8; i++)
#pragma unroll
                    for (int j = 0; j < 8; j++) acc[i][j] += a[i] * bv[j];
            }
            __syncthreads();
        }
    }

    float* hout = g_h[layer];
#pragma unroll
    for (int i = 0; i < 8; i++) {
        int w = m0 + ty * 8 + i;
        if (w < 500) {
            size_t idx = zbase + (size_t)w * 64 + tx * 8;
            float4 ya = *(const float4*)(g_y0 + idx);
            float4 yb = *(const float4*)(g_y0 + idx + 4);
            float4 ra, rb2;
            ra.x = acc[i][0] + ya.x; ra.y = acc[i][1] + ya.y;
            ra.z = acc[i][2] + ya.z; ra.w = acc[i][3] + ya.w;
            rb2.x = acc[i][4] + yb.x; rb2.y = acc[i][5] + yb.y;
            rb2.z = acc[i][6] + yb.z; rb2.w = acc[i][7] + yb.w;
            *(float4*)(hout + idx) = ra;
            *(float4*)(hout + idx + 4) = rb2;
        }
    }
}

// ---------------- attention logits: e3[b,l,n,t] ----------------
__global__ __launch_bounds__(256) void attn_logits(
    const float* __restrict__ x,
    const float* __restrict__ b1, const float* __restrict__ b2,
    const float* __restrict__ w3, const float* __restrict__ b3) {
    __shared__ __align__(16) float vbuf[32][64];
    __shared__ __align__(16) float e1s[64][64];
    __shared__ __align__(16) float red[16][64];
    int tid = threadIdx.x;
    int b = blockIdx.x / 500, n = blockIdx.x % 500;
    int ty = tid >> 4, tx = tid & 15;
    float b3v = b3[0];

    for (int l = 0; l < 5; l++) {
        const float* hl = (l == 0) ? x : g_h[l - 1];
        const float* base = hl + ((size_t)b * 32 * 500 + n) * 64;
        __syncthreads();
        for (int i = tid; i < 2048; i += 256) {
            int c = i >> 6, t = i & 63;
            vbuf[c][t] = fmaxf(__ldg(base + (size_t)c * 32000 + t), 0.f);
        }
        __syncthreads();

        float acc1[4][4];
#pragma unroll
        for (int i = 0; i < 4; i++)
#pragma unroll
            for (int j = 0; j < 4; j++) acc1[i][j] = 0.f;
#pragma unroll 4
        for (int k = 0; k < 32; k++) {
            float w[4], v[4];
            *(float4*)w = *(const float4*)&g_w1t[k * 64 + ty * 4];
            *(float4*)v = *(const float4*)&vbuf[k][tx * 4];
#pragma unroll
            for (int i = 0; i < 4; i++)
#pragma unroll
                for (int j = 0; j < 4; j++) acc1[i][j] += w[i] * v[j];
        }
#pragma unroll
        for (int i = 0; i < 4; i++) {
            float bb = b1[ty * 4 + i];
#pragma unroll
            for (int j = 0; j < 4; j++) e1s[ty * 4 + i][tx * 4 + j] = fmaxf(acc1[i][j] + bb, 0.f);
        }
        __syncthreads();

        float acc2[4][4];
#pragma unroll
        for (int i = 0; i < 4; i++)
#pragma unroll
            for (int j = 0; j < 4; j++) acc2[i][j] = 0.f;
#pragma unroll 4
        for (int k = 0; k < 64; k++) {
            float w[4], v[4];
            *(float4*)w = *(const float4*)&g_w2t[k * 64 + ty * 4];
            *(float4*)v = *(const float4*)&e1s[k][tx * 4];
#pragma unroll
            for (int i = 0; i < 4; i++)
#pragma unroll
                for (int j = 0; j < 4; j++) acc2[i][j] += w[i] * v[j];
        }
        float p[4] = {0.f, 0.f, 0.f, 0.f};
#pragma unroll
        for (int i = 0; i < 4; i++) {
            float bb = b2[ty * 4 + i];
            float wc = w3[ty * 4 + i];
#pragma unroll
            for (int j = 0; j < 4; j++) p[j] += wc * fmaxf(acc2[i][j] + bb, 0.f);
        }
#pragma unroll
        for (int j = 0; j < 4; j++) red[ty][tx * 4 + j] = p[j];
        __syncthreads();
        if (tid < 64) {
            float s = b3v;
#pragma unroll
            for (int q = 0; q < 16; q++) s += red[q][tid];
            g_logits[(((size_t)b * 5 + l) * 500 + n) * 64 + tid] = s;
        }
    }
}

// ---------------- softmax over L+1 and weighted sum ----------------
__global__ __launch_bounds__(256) void attn_out(const float* __restrict__ x, float* __restrict__ out) {
    __shared__ float wts[5][64];
    int tid = threadIdx.x;
    int b = blockIdx.x / 500, n = blockIdx.x % 500;
    if (tid < 64) {
        float lg[5];
        float m = -1e30f;
#pragma unroll
        for (int l = 0; l < 5; l++) {
            lg[l] = g_logits[(((size_t)b * 5 + l) * 500 + n) * 64 + tid];
            m = fmaxf(m, lg[l]);
        }
        float s = 0.f;
#pragma unroll
        for (int l = 0; l < 5; l++) { lg[l] = expf(lg[l] - m); s += lg[l]; }
        float inv = 1.f / s;
#pragma unroll
        for (int l = 0; l < 5; l++) wts[l][tid] = lg[l] * inv;
    }
    __syncthreads();
    size_t base = ((size_t)b * 32 * 500 + n) * 64;
    for (int i = tid; i < 2048; i += 256) {
        int c = i >> 6, t = i & 63;
        size_t idx = base + (size_t)c * 32000 + t;
        float s = wts[0][t] * fmaxf(__ldg(x + idx), 0.f);
        s += wts[1][t] * fmaxf(g_h[0][idx], 0.f);
        s += wts[2][t] * fmaxf(g_h[1][idx], 0.f);
        s += wts[3][t] * fmaxf(g_h[2][idx], 0.f);
        s += wts[4][t] * fmaxf(g_h[3][idx], 0.f);
        out[idx] = s;
    }
}

// ---------------- launch ----------------
extern "C" void kernel_launch(void* const* d_in, const int* in_sizes, int n_in,
                              void* d_out, int out_size) {
    (void)in_sizes; (void)n_in; (void)out_size;
    const float* x        = (const float*)d_in[0];
    const float* supports = (const float*)d_in[1];
    const float* bn_gamma = (const float*)d_in[2];
    const float* bn_beta  = (const float*)d_in[3];
    const float* res_w    = (const float*)d_in[4];
    const float* res_b    = (const float*)d_in[5];
    const float* aff_w    = (const float*)d_in[6];
    const float* aff_b    = (const float*)d_in[7];
    const float* gate_w   = (const float*)d_in[8];
    const float* gate_b   = (const float*)d_in[9];
    const float* gc_w     = (const float*)d_in[10];
    const float* gc_b     = (const float*)d_in[11];
    const float* attn_b1  = (const float*)d_in[13];
    const float* attn_b2  = (const float*)d_in[15];
    const float* attn_w3  = (const float*)d_in[16];
    const float* attn_b3  = (const float*)d_in[17];
    const float* attn_w1  = (const float*)d_in[12];
    const float* attn_w2  = (const float*)d_in[14];
    float* out = (float*)d_out;

    prep_weights<<<32, 256>>>(res_w, aff_w, gate_w, gc_w, attn_w1, attn_w2);

    for (int l = 0; l < 4; l++) {
        bn_partial<<<dim3(32, 16), 256>>>(x, l);
        bn_finalize<<<1, 32>>>(bn_gamma + l * 32, bn_beta + l * 32);
        st_front<<<8000, 256>>>(x, l, res_b + l * 32, aff_b + l * 32,
                                gate_b + l * 32, gc_b + l * 32);
        graph_gemm<<<dim3(4, 512), 128>>>(supports, l);
    }
    attn_logits<<<8000, 256>>>(x, attn_b1, attn_b2, attn_w3, attn_b3);
    attn_out<<<8000, 256>>>(x, out);
}

// round 2
// speedup vs baseline: 1.6414x; 1.6414x over previous
#include <cuda_runtime.h>
#include <cstdint>

// ---------------- scratch (static __device__, no allocations) ----------------
// n-major activation layout: [b][n][c*64+t], b-stride 1,024,000
__device__ __align__(16) float g_h[4][16384000];
__device__ __align__(16) float g_y0[16384000];
__device__ __align__(16) float g_z1[16384000];
__device__ __align__(16) float g_z2[16384000];
__device__ __align__(16) float g_logits[16 * 5 * 500 * 64];
__device__ float g_bnsum[32 * 16], g_bnsq[32 * 16];
__device__ float g_scale[32], g_shift[32];
// packed transposed weights per layer: [rwt 1024 | awt 3072 | gwt 3072 | gcwt 3072]
__device__ __align__(16) float g_wpack[4][10240];
__device__ __align__(16) float g_w1t[32 * 64];   // [c][d]
__device__ __align__(16) float g_w2t[64 * 64];   // [k][d]

// ---------------- weight transposes / packing ----------------
__global__ void prep_weights(const float* __restrict__ rw, const float* __restrict__ aw,
                             const float* __restrict__ gw, const float* __restrict__ gcw,
                             const float* __restrict__ w1, const float* __restrict__ w2) {
    int tid = blockIdx.x * blockDim.x + threadIdx.x;
    int nt = gridDim.x * blockDim.x;
    for (int l = 0; l < 4; l++) {
        float* wp = g_wpack[l];
        for (int i = tid; i < 1024; i += nt) {
            int c = i >> 5, o = i & 31;
            wp[c * 32 + o] = rw[l * 1024 + o * 32 + c];
        }
        for (int i = tid; i < 3072; i += nt) {
            int ck = i >> 5, o = i & 31;
            wp[1024 + ck * 32 + o] = aw[l * 3072 + o * 96 + ck];
            wp[4096 + ck * 32 + o] = gw[l * 3072 + o * 96 + ck];
            wp[7168 + ck * 32 + o] = gcw[l * 3072 + o * 96 + ck];
        }
    }
    for (int i = tid; i < 64 * 32; i += nt) { int d = i / 32, c = i % 32; g_w1t[c * 64 + d] = w1[i]; }
    for (int i = tid; i < 64 * 64; i += nt) { int d = i / 64, k = i % 64; g_w2t[k * 64 + d] = w2[i]; }
}

// ---------------- batchnorm stats ----------------
__global__ void bn_partial(const float* __restrict__ x, int layer) {
    int c = blockIdx.x, b = blockIdx.y;
    float s = 0.f, q = 0.f;
    if (layer == 0) {
        const float* p = x + (size_t)(b * 32 + c) * 32000;
        for (int i = threadIdx.x; i < 32000; i += 256) {
            float v = __ldg(p + i);
            s += v; q += v * v;
        }
    } else {
        const float* p = g_h[layer - 1] + (size_t)b * 1024000 + c * 64;
        for (int i = threadIdx.x; i < 32000; i += 256) {
            float v = __ldg(p + (size_t)(i >> 6) * 2048 + (i & 63));
            s += v; q += v * v;
        }
    }
    for (int o = 16; o; o >>= 1) {
        s += __shfl_down_sync(0xffffffffu, s, o);
        q += __shfl_down_sync(0xffffffffu, q, o);
    }
    __shared__ float ss[8], qq[8];
    int w = threadIdx.x >> 5;
    if ((threadIdx.x & 31) == 0) { ss[w] = s; qq[w] = q; }
    __syncthreads();
    if (threadIdx.x == 0) {
        float S = 0.f, Q = 0.f;
        for (int i = 0; i < 8; i++) { S += ss[i]; Q += qq[i]; }
        g_bnsum[c * 16 + b] = S;
        g_bnsq[c * 16 + b] = Q;
    }
}

__global__ void bn_finalize(const float* __restrict__ gamma, const float* __restrict__ beta) {
    int c = threadIdx.x;
    float S = 0.f, Q = 0.f;
    for (int b = 0; b < 16; b++) { S += g_bnsum[c * 16 + b]; Q += g_bnsq[c * 16 + b]; }
    const float inv = 1.0f / 512000.0f;
    float m = S * inv;
    float var = Q * inv - m * m;
    float rstd = rsqrtf(var + 1e-5f);
    float sc = gamma[c] * rstd;
    g_scale[c] = sc;
    g_shift[c] = beta[c] - m * sc;
}

// ---------------- fused front: bn+relu, res 1x1, causal convs, gate, gc pre-projection ----------------
// dynamic smem: [weights 10240 | xs 2048 | ys 32*72 | x1 2048] floats = 66560 B
__global__ __launch_bounds__(256) void st_front(
    const float* __restrict__ x, int layer,
    const float* __restrict__ rb, const float* __restrict__ ab,
    const float* __restrict__ gb, const float* __restrict__ gcb) {
    extern __shared__ float sm[];
    float* sw = sm;            // weights
    float* xs = sm + 10240;    // xs[c*64+t]
    float* ys = sm + 12288;    // ys[c*72 + i], i = t+2, 2 left-pad, right-pad to 72
    float* x1 = sm + 14592;    // x1[c*64+t]

    int tid = threadIdx.x;
    int b = blockIdx.x / 500, n = blockIdx.x % 500;

    // stage weights + zero ys
    {
        const float4* wp = (const float4*)g_wpack[layer];
        float4* swd = (float4*)sw;
        for (int i = tid; i < 2560; i += 256) swd[i] = wp[i];
        for (int i = tid; i < 2304; i += 256) ys[i] = 0.f;
    }
    __syncthreads();

    // load activations + bn+relu
    if (layer == 0) {
        const float* xb = x + (size_t)b * 1024000 + n * 64;
        for (int i = tid; i < 2048; i += 256) {
            int c = i >> 6, t = i & 63;
            float xv = __ldg(xb + (size_t)c * 32000 + t);
            xs[i] = xv;
            ys[c * 72 + t + 2] = fmaxf(g_scale[c] * xv + g_shift[c], 0.f);
        }
    } else {
        const float* hb = g_h[layer - 1] + ((size_t)b * 500 + n) * 2048;
        for (int i = tid; i < 2048; i += 256) {
            int c = i >> 6, t = i & 63;
            float xv = hb[i];
            xs[i] = xv;
            ys[c * 72 + t + 2] = fmaxf(g_scale[c] * xv + g_shift[c], 0.f);
        }
    }
    __syncthreads();

    int o = tid >> 3;
    int t0 = (tid & 7) * 8;
    const float* rs  = sw;
    const float* as_ = sw + 1024;
    const float* gs  = sw + 4096;

    float racc[8], aacc[8], gacc[8];
#pragma unroll
    for (int j = 0; j < 8; j++) { racc[j] = 0.f; aacc[j] = 0.f; gacc[j] = 0.f; }

#pragma unroll 4
    for (int c = 0; c < 32; c++) {
        float w = rs[c * 32 + o];
        float v[8];
        *(float4*)&v[0] = *(const float4*)&xs[c * 64 + t0];
        *(float4*)&v[4] = *(const float4*)&xs[c * 64 + t0 + 4];
#pragma unroll
        for (int j = 0; j < 8; j++) racc[j] += w * v[j];
    }
#pragma unroll 2
    for (int c = 0; c < 32; c++) {
        float v[12];
        *(float4*)&v[0] = *(const float4*)&ys[c * 72 + t0];
        *(float4*)&v[4] = *(const float4*)&ys[c * 72 + t0 + 4];
        *(float4*)&v[8] = *(const float4*)&ys[c * 72 + t0 + 8];
#pragma unroll
        for (int kk = 0; kk < 3; kk++) {
            float wa = as_[(c * 3 + kk) * 32 + o];
            float wg = gs[(c * 3 + kk) * 32 + o];
#pragma unroll
            for (int j = 0; j < 8; j++) {
                aacc[j] += wa * v[kk + j];
                gacc[j] += wg * v[kk + j];
            }
        }
    }

    float rbv = rb[o], abv = ab[o], gbv = gb[o];
#pragma unroll
    for (int j = 0; j < 8; j++) {
        float a = aacc[j] + abv + racc[j] + rbv;
        float g = gacc[j] + gbv;
        x1[o * 64 + t0 + j] = tanhf(a) * (1.f / (1.f + expf(-g)));
    }
    __syncthreads();

    const float* cs = sw + 7168;
    float y0a[8], z1a[8], z2a[8];
#pragma unroll
    for (int j = 0; j < 8; j++) { y0a[j] = 0.f; z1a[j] = 0.f; z2a[j] = 0.f; }
#pragma unroll 4
    for (int c = 0; c < 32; c++) {
        float w0 = cs[c * 32 + o];
        float w1 = cs[(32 + c) * 32 + o];
        float w2 = cs[(64 + c) * 32 + o];
        float v[8];
        *(float4*)&v[0] = *(const float4*)&x1[c * 64 + t0];
        *(float4*)&v[4] = *(const float4*)&x1[c * 64 + t0 + 4];
#pragma unroll
        for (int j = 0; j < 8; j++) {
            y0a[j] += w0 * v[j];
            z1a[j] += w1 * v[j];
            z2a[j] += w2 * v[j];
        }
    }
    float gcbv = gcb[o];
    size_t oidx = ((size_t)b * 500 + n) * 2048 + o * 64 + t0;
    float ob[8];
#pragma unroll
    for (int j = 0; j < 8; j++) ob[j] = y0a[j] + gcbv;
    *(float4*)(g_y0 + oidx) = *(float4*)&ob[0];
    *(float4*)(g_y0 + oidx + 4) = *(float4*)&ob[4];
    *(float4*)(g_z1 + oidx) = *(float4*)&z1a[0];
    *(float4*)(g_z1 + oidx + 4) = *(float4*)&z1a[4];
    *(float4*)(g_z2 + oidx) = *(float4*)&z2a[0];
    *(float4*)(g_z2 + oidx + 4) = *(float4*)&z2a[4];
}

// ---------------- graph diffusion with tf32 tensor cores ----------------
__device__ __forceinline__ float to_tf32(float x) {
    asm("cvt.rna.tf32.f32 %0, %1;" : "=f"(x) : "f"(x));
    return x;
}
__device__ __forceinline__ void mma_tf32(float& d0, float& d1, float& d2, float& d3,
                                         uint32_t a0, uint32_t a1, uint32_t a2, uint32_t a3,
                                         uint32_t b0, uint32_t b1) {
    asm volatile(
        "mma.sync.aligned.m16n8k8.row.col.f32.tf32.tf32.f32 "
        "{%0,%1,%2,%3},{%4,%5,%6,%7},{%8,%9},{%0,%1,%2,%3};"
        : "+f"(d0), "+f"(d1), "+f"(d2), "+f"(d3)
        : "r"(a0), "r"(a1), "r"(a2), "r"(a3), "r"(b0), "r"(b1));
}

// out[b](500x2048) = A1^T Z1[b] + A2^T Z2[b] + Y0[b]
__global__ __launch_bounds__(256) void graph_mma(const float* __restrict__ A, int layer) {
    __shared__ __align__(16) float As[2][16][136];
    __shared__ __align__(16) float Zs[2][16][136];

    int tid = threadIdx.x;
    int m0 = blockIdx.x * 128;
    int n0 = blockIdx.y * 128;
    int bb = blockIdx.z;
    int lane = tid & 31, wid = tid >> 5;
    int wm = wid & 1, wn = wid >> 1;
    int mbase = wm * 64, nbase = wn * 32;
    int gid = lane >> 2, tig = lane & 3;

    int r = tid >> 4;              // smem row to load (0..15)
    int cseg = (tid & 15) * 8;     // smem col segment (8 floats)

    float acc[4][4][4];
#pragma unroll
    for (int i = 0; i < 4; i++)
#pragma unroll
        for (int j = 0; j < 4; j++)
#pragma unroll
            for (int k = 0; k < 4; k++) acc[i][j][k] = 0.f;

    auto load_stage = [&](int st, int buf) {
        int e = st >> 5;
        int v = ((st & 31) << 4) + r;
        float va[8], vz[8];
        if (v < 500) {
            const float* ap = A + (size_t)e * 250000 + (size_t)v * 500 + m0 + cseg;
            if (m0 + cseg + 7 < 500) {
                *(float4*)&va[0] = __ldg((const float4*)ap);
                *(float4*)&va[4] = __ldg((const float4*)(ap + 4));
            } else {
#pragma unroll
                for (int q = 0; q < 8; q++)
                    va[q] = (m0 + cseg + q < 500) ? __ldg(ap + q) : 0.f;
            }
            const float* zb = (e ? g_z2 : g_z1);
            const float* zp = zb + ((size_t)bb * 500 + v) * 2048 + n0 + cseg;
            *(float4*)&vz[0] = __ldg((const float4*)zp);
            *(float4*)&vz[4] = __ldg((const float4*)(zp + 4));
        } else {
#pragma unroll
            for (int q = 0; q < 8; q++) { va[q] = 0.f; vz[q] = 0.f; }
        }
#pragma unroll
        for (int q = 0; q < 8; q++) { va[q] = to_tf32(va[q]); vz[q] = to_tf32(vz[q]); }
        *(float4*)&As[buf][r][cseg]     = *(float4*)&va[0];
        *(float4*)&As[buf][r][cseg + 4] = *(float4*)&va[4];
        *(float4*)&Zs[buf][r][cseg]     = *(float4*)&vz[0];
        *(float4*)&Zs[buf][r][cseg + 4] = *(float4*)&vz[4];
    };

    load_stage(0, 0);
    __syncthreads();

    for (int st = 0; st < 64; st++) {
        int cur = st & 1;
        if (st + 1 < 64) load_stage(st + 1, cur ^ 1);
#pragma unroll
        for (int kk = 0; kk < 16; kk += 8) {
            uint32_t bf[4][2];
#pragma unroll
            for (int nt = 0; nt < 4; nt++) {
                bf[nt][0] = __float_as_uint(Zs[cur][kk + tig][nbase + nt * 8 + gid]);
                bf[nt][1] = __float_as_uint(Zs[cur][kk + tig + 4][nbase + nt * 8 + gid]);
            }
#pragma unroll
            for (int mt = 0; mt < 4; mt++) {
                int mr = mbase + mt * 16 + gid;
                uint32_t a0 = __float_as_uint(As[cur][kk + tig][mr]);
                uint32_t a1 = __float_as_uint(As[cur][kk + tig][mr + 8]);
                uint32_t a2 = __float_as_uint(As[cur][kk + tig + 4][mr]);
                uint32_t a3 = __float_as_uint(As[cur][kk + tig + 4][mr + 8]);
#pragma unroll
                for (int nt = 0; nt < 4; nt++)
                    mma_tf32(acc[mt][nt][0], acc[mt][nt][1], acc[mt][nt][2], acc[mt][nt][3],
                             a0, a1, a2, a3, bf[nt][0], bf[nt][1]);
            }
        }
        __syncthreads();
    }

    // epilogue: h = acc + y0
    float* hout = g_h[layer];
    size_t bbase = (size_t)bb * 1024000;
#pragma unroll
    for (int mt = 0; mt < 4; mt++) {
#pragma unroll
        for (int nt = 0; nt < 4; nt++) {
            int w0 = m0 + mbase + mt * 16 + gid;
            int j = n0 + nbase + nt * 8 + 2 * tig;
            if (w0 < 500) {
                size_t idx = bbase + (size_t)w0 * 2048 + j;
                float2 y = *(const float2*)(g_y0 + idx);
                float2 rres;
                rres.x = acc[mt][nt][0] + y.x;
                rres.y = acc[mt][nt][1] + y.y;
                *(float2*)(hout + idx) = rres;
            }
            if (w0 + 8 < 500) {
                size_t idx = bbase + (size_t)(w0 + 8) * 2048 + j;
                float2 y = *(const float2*)(g_y0 + idx);
                float2 rres;
                rres.x = acc[mt][nt][2] + y.x;
                rres.y = acc[mt][nt][3] + y.y;
                *(float2*)(hout + idx) = rres;
            }
        }
    }
}

// ---------------- attention logits ----------------
__global__ __launch_bounds__(256) void attn_logits(
    const float* __restrict__ x,
    const float* __restrict__ b1, const float* __restrict__ b2,
    const float* __restrict__ w3, const float* __restrict__ b3) {
    __shared__ __align__(16) float vbuf[32][64];
    __shared__ __align__(16) float e1s[64][64];
    __shared__ __align__(16) float red[16][64];
    int tid = threadIdx.x;
    int b = blockIdx.x / 500, n = blockIdx.x % 500;
    int ty = tid >> 4, tx = tid & 15;
    float b3v = b3[0];

    for (int l = 0; l < 5; l++) {
        __syncthreads();
        if (l == 0) {
            const float* xb = x + (size_t)b * 1024000 + n * 64;
            for (int i = tid; i < 2048; i += 256) {
                int c = i >> 6, t = i & 63;
                vbuf[c][t] = fmaxf(__ldg(xb + (size_t)c * 32000 + t), 0.f);
            }
        } else {
            const float* hb = g_h[l - 1] + ((size_t)b * 500 + n) * 2048;
            for (int i = tid; i < 2048; i += 256)
                (&vbuf[0][0])[i] = fmaxf(hb[i], 0.f);
        }
        __syncthreads();

        float acc1[4][4];
#pragma unroll
        for (int i = 0; i < 4; i++)
#pragma unroll
            for (int j = 0; j < 4; j++) acc1[i][j] = 0.f;
#pragma unroll 4
        for (int k = 0; k < 32; k++) {
            float w[4], v[4];
            *(float4*)w = *(const float4*)&g_w1t[k * 64 + ty * 4];
            *(float4*)v = *(const float4*)&vbuf[k][tx * 4];
#pragma unroll
            for (int i = 0; i < 4; i++)
#pragma unroll
                for (int j = 0; j < 4; j++) acc1[i][j] += w[i] * v[j];
        }
#pragma unroll
        for (int i = 0; i < 4; i++) {
            float bb = b1[ty * 4 + i];
#pragma unroll
            for (int j = 0; j < 4; j++) e1s[ty * 4 + i][tx * 4 + j] = fmaxf(acc1[i][j] + bb, 0.f);
        }
        __syncthreads();

        float acc2[4][4];
#pragma unroll
        for (int i = 0; i < 4; i++)
#pragma unroll
            for (int j = 0; j < 4; j++) acc2[i][j] = 0.f;
#pragma unroll 4
        for (int k = 0; k < 64; k++) {
            float w[4], v[4];
            *(float4*)w = *(const float4*)&g_w2t[k * 64 + ty * 4];
            *(float4*)v = *(const float4*)&e1s[k][tx * 4];
#pragma unroll
            for (int i = 0; i < 4; i++)
#pragma unroll
                for (int j = 0; j < 4; j++) acc2[i][j] += w[i] * v[j];
        }
        float p[4] = {0.f, 0.f, 0.f, 0.f};
#pragma unroll
        for (int i = 0; i < 4; i++) {
            float bb = b2[ty * 4 + i];
            float wc = w3[ty * 4 + i];
#pragma unroll
            for (int j = 0; j < 4; j++) p[j] += wc * fmaxf(acc2[i][j] + bb, 0.f);
        }
#pragma unroll
        for (int j = 0; j < 4; j++) red[ty][tx * 4 + j] = p[j];
        __syncthreads();
        if (tid < 64) {
            float s = b3v;
#pragma unroll
            for (int q = 0; q < 16; q++) s += red[q][tid];
            g_logits[(((size_t)b * 5 + l) * 500 + n) * 64 + tid] = s;
        }
    }
}

// ---------------- softmax over L+1 and weighted sum ----------------
__global__ __launch_bounds__(256) void attn_out(const float* __restrict__ x, float* __restrict__ out) {
    __shared__ float wts[5][64];
    int tid = threadIdx.x;
    int b = blockIdx.x / 500, n = blockIdx.x % 500;
    if (tid < 64) {
        float lg[5];
        float m = -1e30f;
#pragma unroll
        for (int l = 0; l < 5; l++) {
            lg[l] = g_logits[(((size_t)b * 5 + l) * 500 + n) * 64 + tid];
            m = fmaxf(m, lg[l]);
        }
        float s = 0.f;
#pragma unroll
        for (int l = 0; l < 5; l++) { lg[l] = expf(lg[l] - m); s += lg[l]; }
        float inv = 1.f / s;
#pragma unroll
        for (int l = 0; l < 5; l++) wts[l][tid] = lg[l] * inv;
    }
    __syncthreads();
    size_t hbase = ((size_t)b * 500 + n) * 2048;
    const float* xb = x + (size_t)b * 1024000 + n * 64;
    for (int i = tid; i < 2048; i += 256) {
        int c = i >> 6, t = i & 63;
        float s = wts[0][t] * fmaxf(__ldg(xb + (size_t)c * 32000 + t), 0.f);
        s += wts[1][t] * fmaxf(g_h[0][hbase + i], 0.f);
        s += wts[2][t] * fmaxf(g_h[1][hbase + i], 0.f);
        s += wts[3][t] * fmaxf(g_h[2][hbase + i], 0.f);
        s += wts[4][t] * fmaxf(g_h[3][hbase + i], 0.f);
        out[((size_t)(b * 32 + c) * 500 + n) * 64 + t] = s;
    }
}

// ---------------- launch ----------------
extern "C" void kernel_launch(void* const* d_in, const int* in_sizes, int n_in,
                              void* d_out, int out_size) {
    (void)in_sizes; (void)n_in; (void)out_size;
    const float* x        = (const float*)d_in[0];
    const float* supports = (const float*)d_in[1];
    const float* bn_gamma = (const float*)d_in[2];
    const float* bn_beta  = (const float*)d_in[3];
    const float* res_w    = (const float*)d_in[4];
    const float* res_b    = (const float*)d_in[5];
    const float* aff_w    = (const float*)d_in[6];
    const float* aff_b    = (const float*)d_in[7];
    const float* gate_w   = (const float*)d_in[8];
    const float* gate_b   = (const float*)d_in[9];
    const float* gc_w     = (const float*)d_in[10];
    const float* gc_b     = (const float*)d_in[11];
    const float* attn_w1  = (const float*)d_in[12];
    const float* attn_b1  = (const float*)d_in[13];
    const float* attn_w2  = (const float*)d_in[14];
    const float* attn_b2  = (const float*)d_in[15];
    const float* attn_w3  = (const float*)d_in[16];
    const float* attn_b3  = (const float*)d_in[17];
    float* out = (float*)d_out;

    cudaFuncSetAttribute(st_front, cudaFuncAttributeMaxDynamicSharedMemorySize, 66560);

    prep_weights<<<32, 256>>>(res_w, aff_w, gate_w, gc_w, attn_w1, attn_w2);

    for (int l = 0; l < 4; l++) {
        bn_partial<<<dim3(32, 16), 256>>>(x, l);
        bn_finalize<<<1, 32>>>(bn_gamma + l * 32, bn_beta + l * 32);
        st_front<<<8000, 256, 66560>>>(x, l, res_b + l * 32, aff_b + l * 32,
                                       gate_b + l * 32, gc_b + l * 32);
        graph_mma<<<dim3(4, 16, 16), 256>>>(supports, l);
    }
    attn_logits<<<8000, 256>>>(x, attn_b1, attn_b2, attn_w3, attn_b3);
    attn_out<<<8000, 256>>>(x, out);
}

// round 4
// speedup vs baseline: 1.8363x; 1.1188x over previous
#include <cuda_runtime.h>
#include <cstdint>

// ---------------- scratch (static __device__, no allocations) ----------------
// n-major activation layout: [b][n][c*64+t], b-stride 1,024,000
__device__ __align__(16) float g_h[4][16384000];
__device__ __align__(16) float g_y0[16384000];
__device__ __align__(16) float g_z1[16384000];
__device__ __align__(16) float g_z2[16384000];
__device__ __align__(16) float g_logits[16 * 5 * 500 * 64];
__device__ float g_bnsum[32 * 16], g_bnsq[32 * 16];
__device__ float g_scale[32], g_shift[32];
// packed transposed weights per layer: [rwt 1024 | awt 3072 | gwt 3072 | gcwt 3072]
__device__ __align__(16) float g_wpack[4][10240];
__device__ __align__(16) float g_w1t[32 * 64];   // [c][d]
__device__ __align__(16) float g_w2t[64 * 64];   // [k][d]

// ---------------- packed f32x2 helpers ----------------
typedef unsigned long long u64;
__device__ __forceinline__ u64 pk2(float lo, float hi) {
    u64 r; asm("mov.b64 %0,{%1,%2};" : "=l"(r) : "f"(lo), "f"(hi)); return r;
}
__device__ __forceinline__ u64 pkb(float v) { return pk2(v, v); }
__device__ __forceinline__ void fma2(u64& d, u64 a, u64 b) {
    asm("fma.rn.f32x2 %0,%1,%2,%0;" : "+l"(d) : "l"(a), "l"(b));
}
__device__ __forceinline__ float2 up2(u64 v) {
    float2 f; asm("mov.b64 {%0,%1},%2;" : "=f"(f.x), "=f"(f.y) : "l"(v)); return f;
}

// ---------------- weight transposes / packing ----------------
__global__ void prep_weights(const float* __restrict__ rw, const float* __restrict__ aw,
                             const float* __restrict__ gw, const float* __restrict__ gcw,
                             const float* __restrict__ w1, const float* __restrict__ w2) {
    int tid = blockIdx.x * blockDim.x + threadIdx.x;
    int nt = gridDim.x * blockDim.x;
    for (int l = 0; l < 4; l++) {
        float* wp = g_wpack[l];
        for (int i = tid; i < 1024; i += nt) {
            int c = i >> 5, o = i & 31;
            wp[c * 32 + o] = rw[l * 1024 + o * 32 + c];
        }
        for (int i = tid; i < 3072; i += nt) {
            int ck = i >> 5, o = i & 31;
            wp[1024 + ck * 32 + o] = aw[l * 3072 + o * 96 + ck];
            wp[4096 + ck * 32 + o] = gw[l * 3072 + o * 96 + ck];
            wp[7168 + ck * 32 + o] = gcw[l * 3072 + o * 96 + ck];
        }
    }
    for (int i = tid; i < 64 * 32; i += nt) { int d = i / 32, c = i % 32; g_w1t[c * 64 + d] = w1[i]; }
    for (int i = tid; i < 64 * 64; i += nt) { int d = i / 64, k = i % 64; g_w2t[k * 64 + d] = w2[i]; }
}

// ---------------- batchnorm stats ----------------
__global__ void bn_partial(const float* __restrict__ x, int layer) {
    int c = blockIdx.x, b = blockIdx.y;
    float s = 0.f, q = 0.f;
    if (layer == 0) {
        const float* p = x + (size_t)(b * 32 + c) * 32000;
        for (int i = threadIdx.x; i < 32000; i += 256) {
            float v = __ldg(p + i);
            s += v; q += v * v;
        }
    } else {
        const float* p = g_h[layer - 1] + (size_t)b * 1024000 + c * 64;
        for (int i = threadIdx.x; i < 32000; i += 256) {
            float v = __ldg(p + (size_t)(i >> 6) * 2048 + (i & 63));
            s += v; q += v * v;
        }
    }
    for (int o = 16; o; o >>= 1) {
        s += __shfl_down_sync(0xffffffffu, s, o);
        q += __shfl_down_sync(0xffffffffu, q, o);
    }
    __shared__ float ss[8], qq[8];
    int w = threadIdx.x >> 5;
    if ((threadIdx.x & 31) == 0) { ss[w] = s; qq[w] = q; }
    __syncthreads();
    if (threadIdx.x == 0) {
        float S = 0.f, Q = 0.f;
        for (int i = 0; i < 8; i++) { S += ss[i]; Q += qq[i]; }
        g_bnsum[c * 16 + b] = S;
        g_bnsq[c * 16 + b] = Q;
    }
}

__global__ void bn_finalize(const float* __restrict__ gamma, const float* __restrict__ beta) {
    int c = threadIdx.x;
    float S = 0.f, Q = 0.f;
    for (int b = 0; b < 16; b++) { S += g_bnsum[c * 16 + b]; Q += g_bnsq[c * 16 + b]; }
    const float inv = 1.0f / 512000.0f;
    float m = S * inv;
    float var = Q * inv - m * m;
    float rstd = rsqrtf(var + 1e-5f);
    float sc = gamma[c] * rstd;
    g_scale[c] = sc;
    g_shift[c] = beta[c] - m * sc;
}

// ---------------- fused front: bn+relu, res 1x1, causal convs, gate, gc pre-projection ----------------
// block = 4 n-positions, 256 threads = 4 nl x (8 og x 8 tg). Each thread: 4 o x 8 t.
// dyn smem floats: [weights 10240 | xs 4*2048 (reused for x1) | ys 4*2304] = 27648 fl = 110592 B
__global__ __launch_bounds__(256) void st_front(
    const float* __restrict__ x, int layer,
    const float* __restrict__ rb, const float* __restrict__ ab,
    const float* __restrict__ gb, const float* __restrict__ gcb) {
    extern __shared__ float sm[];
    float* sw = sm;             // 10240 weights
    float* xs = sm + 10240;     // 4 x 2048 (raw x; later x1)
    float* ys = sm + 18432;     // 4 x (32*72), index i=t+2

    int tid = threadIdx.x;
    int b = blockIdx.x / 125, n0 = (blockIdx.x % 125) * 4;

    // stage weights
    {
        const float4* wp = (const float4*)g_wpack[layer];
        float4* swd = (float4*)sw;
        for (int i = tid; i < 2560; i += 256) swd[i] = wp[i];
    }
    // zero ys pads: cols {0,1} (left) and {66..71} (right) — DISJOINT from data cols 2..65
    for (int i = tid; i < 1024; i += 256) {
        int nl = i >> 8, r = (i >> 3) & 31, p = i & 7;
        int col = (p < 2) ? p : (p + 64);
        ys[nl * 2304 + r * 72 + col] = 0.f;
    }

    // load activations + bn+relu
    if (layer == 0) {
        const float* xb = x + (size_t)b * 1024000;
        for (int i = tid; i < 8192; i += 256) {
            int nl = i >> 11, idx = i & 2047;
            int c = idx >> 6, t = idx & 63;
            float xv = __ldg(xb + (size_t)c * 32000 + (n0 + nl) * 64 + t);
            xs[nl * 2048 + idx] = xv;
            ys[nl * 2304 + c * 72 + t + 2] = fmaxf(g_scale[c] * xv + g_shift[c], 0.f);
        }
    } else {
        const float* hb = g_h[layer - 1] + ((size_t)b * 500 + n0) * 2048;
        for (int i = tid; i < 8192; i += 256) {
            int nl = i >> 11, idx = i & 2047;
            int c = idx >> 6, t = idx & 63;
            float xv = hb[(size_t)nl * 2048 + idx];
            xs[nl * 2048 + idx] = xv;
            ys[nl * 2304 + c * 72 + t + 2] = fmaxf(g_scale[c] * xv + g_shift[c], 0.f);
        }
    }
    __syncthreads();

    int nl = tid >> 6;
    int wt = tid & 63;
    int og = wt >> 3, tg = wt & 7;
    int o0 = og * 4, t0 = tg * 8;
    const float* xsn = xs + nl * 2048;
    const float* ysn = ys + nl * 2304;
    const float* rs  = sw;
    const float* as_ = sw + 1024;
    const float* gs  = sw + 4096;

    // aff accumulates res too (tanh(aff + res)); init with biases
    u64 ua[4][4], ug[4][4];
#pragma unroll
    for (int i = 0; i < 4; i++) {
        u64 ba = pkb(ab[o0 + i] + rb[o0 + i]);
        u64 bg = pkb(gb[o0 + i]);
#pragma unroll
        for (int j = 0; j < 4; j++) { ua[i][j] = ba; ug[i][j] = bg; }
    }

#pragma unroll 2
    for (int c = 0; c < 32; c++) {
        // res
        float4 wr = *(const float4*)&rs[c * 32 + o0];
        float4 xa = *(const float4*)&xsn[c * 64 + t0];
        float4 xb2 = *(const float4*)&xsn[c * 64 + t0 + 4];
        u64 px[4] = { pk2(xa.x, xa.y), pk2(xa.z, xa.w), pk2(xb2.x, xb2.y), pk2(xb2.z, xb2.w) };
        float wri[4] = { wr.x, wr.y, wr.z, wr.w };
#pragma unroll
        for (int i = 0; i < 4; i++) {
            u64 w2 = pkb(wri[i]);
#pragma unroll
            for (int j = 0; j < 4; j++) fma2(ua[i][j], w2, px[j]);
        }
        // conv window
        float v[12];
        *(float4*)&v[0] = *(const float4*)&ysn[c * 72 + t0];
        *(float4*)&v[4] = *(const float4*)&ysn[c * 72 + t0 + 4];
        *(float4*)&v[8] = *(const float4*)&ysn[c * 72 + t0 + 8];
#pragma unroll
        for (int kk = 0; kk < 3; kk++) {
            u64 pw[4];
#pragma unroll
            for (int j = 0; j < 4; j++) pw[j] = pk2(v[kk + 2 * j], v[kk + 2 * j + 1]);
            float4 wa = *(const float4*)&as_[(c * 3 + kk) * 32 + o0];
            float4 wg = *(const float4*)&gs[(c * 3 + kk) * 32 + o0];
            float wai[4] = { wa.x, wa.y, wa.z, wa.w };
            float wgi[4] = { wg.x, wg.y, wg.z, wg.w };
#pragma unroll
            for (int i = 0; i < 4; i++) {
                u64 a2 = pkb(wai[i]);
                u64 g2 = pkb(wgi[i]);
#pragma unroll
                for (int j = 0; j < 4; j++) { fma2(ua[i][j], a2, pw[j]); fma2(ug[i][j], g2, pw[j]); }
            }
        }
    }

    // x1 = tanh(aff+res) * sigmoid(gate)
    float x1v[4][8];
#pragma unroll
    for (int i = 0; i < 4; i++)
#pragma unroll
        for (int j = 0; j < 4; j++) {
            float2 a = up2(ua[i][j]);
            float2 g = up2(ug[i][j]);
            x1v[i][2 * j]     = tanhf(a.x) * (1.f / (1.f + expf(-g.x)));
            x1v[i][2 * j + 1] = tanhf(a.y) * (1.f / (1.f + expf(-g.y)));
        }
    __syncthreads();   // everyone done reading xs
    float* x1n = xs + nl * 2048;
#pragma unroll
    for (int i = 0; i < 4; i++) {
        *(float4*)&x1n[(o0 + i) * 64 + t0]     = *(float4*)&x1v[i][0];
        *(float4*)&x1n[(o0 + i) * 64 + t0 + 4] = *(float4*)&x1v[i][4];
    }
    __syncthreads();

    // gc pre-projection: y0 = W0 x1 + b, z1 = W1 x1, z2 = W2 x1
    const float* cs = sw + 7168;
    u64 uy[4][4], uz1[4][4], uz2[4][4];
#pragma unroll
    for (int i = 0; i < 4; i++) {
        u64 by = pkb(gcb[o0 + i]);
#pragma unroll
        for (int j = 0; j < 4; j++) { uy[i][j] = by; uz1[i][j] = 0ull; uz2[i][j] = 0ull; }
    }
#pragma unroll 2
    for (int c = 0; c < 32; c++) {
        float4 xa = *(const float4*)&x1n[c * 64 + t0];
        float4 xb2 = *(const float4*)&x1n[c * 64 + t0 + 4];
        u64 px[4] = { pk2(xa.x, xa.y), pk2(xa.z, xa.w), pk2(xb2.x, xb2.y), pk2(xb2.z, xb2.w) };
        float4 w0 = *(const float4*)&cs[c * 32 + o0];
        float4 w1 = *(const float4*)&cs[(32 + c) * 32 + o0];
        float4 w2 = *(const float4*)&cs[(64 + c) * 32 + o0];
        float w0i[4] = { w0.x, w0.y, w0.z, w0.w };
        float w1i[4] = { w1.x, w1.y, w1.z, w1.w };
        float w2i[4] = { w2.x, w2.y, w2.z, w2.w };
#pragma unroll
        for (int i = 0; i < 4; i++) {
            u64 a0 = pkb(w0i[i]), a1 = pkb(w1i[i]), a2 = pkb(w2i[i]);
#pragma unroll
            for (int j = 0; j < 4; j++) {
                fma2(uy[i][j], a0, px[j]);
                fma2(uz1[i][j], a1, px[j]);
                fma2(uz2[i][j], a2, px[j]);
            }
        }
    }

    size_t obase = ((size_t)b * 500 + n0 + nl) * 2048 + t0;
#pragma unroll
    for (int i = 0; i < 4; i++) {
        size_t oidx = obase + (size_t)(o0 + i) * 64;
        float buf[8];
#pragma unroll
        for (int j = 0; j < 4; j++) { float2 f = up2(uy[i][j]); buf[2 * j] = f.x; buf[2 * j + 1] = f.y; }
        *(float4*)(g_y0 + oidx) = *(float4*)&buf[0];
        *(float4*)(g_y0 + oidx + 4) = *(float4*)&buf[4];
#pragma unroll
        for (int j = 0; j < 4; j++) { float2 f = up2(uz1[i][j]); buf[2 * j] = f.x; buf[2 * j + 1] = f.y; }
        *(float4*)(g_z1 + oidx) = *(float4*)&buf[0];
        *(float4*)(g_z1 + oidx + 4) = *(float4*)&buf[4];
#pragma unroll
        for (int j = 0; j < 4; j++) { float2 f = up2(uz2[i][j]); buf[2 * j] = f.x; buf[2 * j + 1] = f.y; }
        *(float4*)(g_z2 + oidx) = *(float4*)&buf[0];
        *(float4*)(g_z2 + oidx + 4) = *(float4*)&buf[4];
    }
}

// ---------------- graph diffusion with tf32 tensor cores ----------------
__device__ __forceinline__ float to_tf32(float x) {
    asm("cvt.rna.tf32.f32 %0, %1;" : "=f"(x) : "f"(x));
    return x;
}
__device__ __forceinline__ void mma_tf32(float& d0, float& d1, float& d2, float& d3,
                                         uint32_t a0, uint32_t a1, uint32_t a2, uint32_t a3,
                                         uint32_t b0, uint32_t b1) {
    asm volatile(
        "mma.sync.aligned.m16n8k8.row.col.f32.tf32.tf32.f32 "
        "{%0,%1,%2,%3},{%4,%5,%6,%7},{%8,%9},{%0,%1,%2,%3};"
        : "+f"(d0), "+f"(d1), "+f"(d2), "+f"(d3)
        : "r"(a0), "r"(a1), "r"(a2), "r"(a3), "r"(b0), "r"(b1));
}

// out[b](500x2048) = A1^T Z1[b] + A2^T Z2[b] + Y0[b]
__global__ __launch_bounds__(256) void graph_mma(const float* __restrict__ A, int layer) {
    __shared__ __align__(16) float As[2][16][136];
    __shared__ __align__(16) float Zs[2][16][136];

    int tid = threadIdx.x;
    int m0 = blockIdx.x * 128;
    int n0 = blockIdx.y * 128;
    int bb = blockIdx.z;
    int lane = tid & 31, wid = tid >> 5;
    int wm = wid & 1, wn = wid >> 1;
    int mbase = wm * 64, nbase = wn * 32;
    int gid = lane >> 2, tig = lane & 3;

    int r = tid >> 4;
    int cseg = (tid & 15) * 8;

    float acc[4][4][4];
#pragma unroll
    for (int i = 0; i < 4; i++)
#pragma unroll
        for (int j = 0; j < 4; j++)
#pragma unroll
            for (int k = 0; k < 4; k++) acc[i][j][k] = 0.f;

    auto load_stage = [&](int st, int buf) {
        int e = st >> 5;
        int v = ((st & 31) << 4) + r;
        float va[8], vz[8];
        if (v < 500) {
            const float* ap = A + (size_t)e * 250000 + (size_t)v * 500 + m0 + cseg;
            if (m0 + cseg + 7 < 500) {
                *(float4*)&va[0] = __ldg((const float4*)ap);
                *(float4*)&va[4] = __ldg((const float4*)(ap + 4));
            } else {
#pragma unroll
                for (int q = 0; q < 8; q++)
                    va[q] = (m0 + cseg + q < 500) ? __ldg(ap + q) : 0.f;
            }
            const float* zb = (e ? g_z2 : g_z1);
            const float* zp = zb + ((size_t)bb * 500 + v) * 2048 + n0 + cseg;
            *(float4*)&vz[0] = __ldg((const float4*)zp);
            *(float4*)&vz[4] = __ldg((const float4*)(zp + 4));
        } else {
#pragma unroll
            for (int q = 0; q < 8; q++) { va[q] = 0.f; vz[q] = 0.f; }
        }
#pragma unroll
        for (int q = 0; q < 8; q++) { va[q] = to_tf32(va[q]); vz[q] = to_tf32(vz[q]); }
        *(float4*)&As[buf][r][cseg]     = *(float4*)&va[0];
        *(float4*)&As[buf][r][cseg + 4] = *(float4*)&va[4];
        *(float4*)&Zs[buf][r][cseg]     = *(float4*)&vz[0];
        *(float4*)&Zs[buf][r][cseg + 4] = *(float4*)&vz[4];
    };

    load_stage(0, 0);
    __syncthreads();

    for (int st = 0; st < 64; st++) {
        int cur = st & 1;
        if (st + 1 < 64) load_stage(st + 1, cur ^ 1);
#pragma unroll
        for (int kk = 0; kk < 16; kk += 8) {
            uint32_t bf[4][2];
#pragma unroll
            for (int nt = 0; nt < 4; nt++) {
                bf[nt][0] = __float_as_uint(Zs[cur][kk + tig][nbase + nt * 8 + gid]);
                bf[nt][1] = __float_as_uint(Zs[cur][kk + tig + 4][nbase + nt * 8 + gid]);
            }
#pragma unroll
            for (int mt = 0; mt < 4; mt++) {
                int mr = mbase + mt * 16 + gid;
                uint32_t a0 = __float_as_uint(As[cur][kk + tig][mr]);
                uint32_t a1 = __float_as_uint(As[cur][kk + tig][mr + 8]);
                uint32_t a2 = __float_as_uint(As[cur][kk + tig + 4][mr]);
                uint32_t a3 = __float_as_uint(As[cur][kk + tig + 4][mr + 8]);
#pragma unroll
                for (int nt = 0; nt < 4; nt++)
                    mma_tf32(acc[mt][nt][0], acc[mt][nt][1], acc[mt][nt][2], acc[mt][nt][3],
                             a0, a1, a2, a3, bf[nt][0], bf[nt][1]);
            }
        }
        __syncthreads();
    }

    float* hout = g_h[layer];
    size_t bbase = (size_t)bb * 1024000;
#pragma unroll
    for (int mt = 0; mt < 4; mt++) {
#pragma unroll
        for (int nt = 0; nt < 4; nt++) {
            int w0 = m0 + mbase + mt * 16 + gid;
            int j = n0 + nbase + nt * 8 + 2 * tig;
            if (w0 < 500) {
                size_t idx = bbase + (size_t)w0 * 2048 + j;
                float2 y = *(const float2*)(g_y0 + idx);
                float2 rres;
                rres.x = acc[mt][nt][0] + y.x;
                rres.y = acc[mt][nt][1] + y.y;
                *(float2*)(hout + idx) = rres;
            }
            if (w0 + 8 < 500) {
                size_t idx = bbase + (size_t)(w0 + 8) * 2048 + j;
                float2 y = *(const float2*)(g_y0 + idx);
                float2 rres;
                rres.x = acc[mt][nt][2] + y.x;
                rres.y = acc[mt][nt][3] + y.y;
                *(float2*)(hout + idx) = rres;
            }
        }
    }
}

// ---------------- attention logits ----------------
__global__ __launch_bounds__(256) void attn_logits(
    const float* __restrict__ x,
    const float* __restrict__ b1, const float* __restrict__ b2,
    const float* __restrict__ w3, const float* __restrict__ b3) {
    __shared__ __align__(16) float vbuf[32][64];
    __shared__ __align__(16) float e1s[64][64];
    __shared__ __align__(16) float red[16][64];
    int tid = threadIdx.x;
    int b = blockIdx.x / 500, n = blockIdx.x % 500;
    int ty = tid >> 4, tx = tid & 15;
    float b3v = b3[0];

    for (int l = 0; l < 5; l++) {
        __syncthreads();
        if (l == 0) {
            const float* xb = x + (size_t)b * 1024000 + n * 64;
            for (int i = tid; i < 2048; i += 256) {
                int c = i >> 6, t = i & 63;
                vbuf[c][t] = fmaxf(__ldg(xb + (size_t)c * 32000 + t), 0.f);
            }
        } else {
            const float* hb = g_h[l - 1] + ((size_t)b * 500 + n) * 2048;
            for (int i = tid; i < 2048; i += 256)
                (&vbuf[0][0])[i] = fmaxf(hb[i], 0.f);
        }
        __syncthreads();

        u64 a1p[4][2];
#pragma unroll
        for (int i = 0; i < 4; i++) { a1p[i][0] = 0ull; a1p[i][1] = 0ull; }
#pragma unroll 4
        for (int k = 0; k < 32; k++) {
            float4 w = *(const float4*)&g_w1t[k * 64 + ty * 4];
            float4 v = *(const float4*)&vbuf[k][tx * 4];
            u64 pv0 = pk2(v.x, v.y), pv1 = pk2(v.z, v.w);
            float wi[4] = { w.x, w.y, w.z, w.w };
#pragma unroll
            for (int i = 0; i < 4; i++) {
                u64 wp = pkb(wi[i]);
                fma2(a1p[i][0], wp, pv0);
                fma2(a1p[i][1], wp, pv1);
            }
        }
#pragma unroll
        for (int i = 0; i < 4; i++) {
            float bb = b1[ty * 4 + i];
            float2 f0 = up2(a1p[i][0]), f1 = up2(a1p[i][1]);
            e1s[ty * 4 + i][tx * 4 + 0] = fmaxf(f0.x + bb, 0.f);
            e1s[ty * 4 + i][tx * 4 + 1] = fmaxf(f0.y + bb, 0.f);
            e1s[ty * 4 + i][tx * 4 + 2] = fmaxf(f1.x + bb, 0.f);
            e1s[ty * 4 + i][tx * 4 + 3] = fmaxf(f1.y + bb, 0.f);
        }
        __syncthreads();

        u64 a2p[4][2];
#pragma unroll
        for (int i = 0; i < 4; i++) { a2p[i][0] = 0ull; a2p[i][1] = 0ull; }
#pragma unroll 4
        for (int k = 0; k < 64; k++) {
            float4 w = *(const float4*)&g_w2t[k * 64 + ty * 4];
            float4 v = *(const float4*)&e1s[k][tx * 4];
            u64 pv0 = pk2(v.x, v.y), pv1 = pk2(v.z, v.w);
            float wi[4] = { w.x, w.y, w.z, w.w };
#pragma unroll
            for (int i = 0; i < 4; i++) {
                u64 wp = pkb(wi[i]);
                fma2(a2p[i][0], wp, pv0);
                fma2(a2p[i][1], wp, pv1);
            }
        }
        float p[4] = {0.f, 0.f, 0.f, 0.f};
#pragma unroll
        for (int i = 0; i < 4; i++) {
            float bb = b2[ty * 4 + i];
            float wc = w3[ty * 4 + i];
            float2 f0 = up2(a2p[i][0]), f1 = up2(a2p[i][1]);
            p[0] += wc * fmaxf(f0.x + bb, 0.f);
            p[1] += wc * fmaxf(f0.y + bb, 0.f);
            p[2] += wc * fmaxf(f1.x + bb, 0.f);
            p[3] += wc * fmaxf(f1.y + bb, 0.f);
        }
#pragma unroll
        for (int j = 0; j < 4; j++) red[ty][tx * 4 + j] = p[j];
        __syncthreads();
        if (tid < 64) {
            float s = b3v;
#pragma unroll
            for (int q = 0; q < 16; q++) s += red[q][tid];
            g_logits[(((size_t)b * 5 + l) * 500 + n) * 64 + tid] = s;
        }
    }
}

// ---------------- softmax over L+1 and weighted sum ----------------
__global__ __launch_bounds__(256) void attn_out(const float* __restrict__ x, float* __restrict__ out) {
    __shared__ float wts[5][64];
    int tid = threadIdx.x;
    int b = blockIdx.x / 500, n = blockIdx.x % 500;
    if (tid < 64) {
        float lg[5];
        float m = -1e30f;
#pragma unroll
        for (int l = 0; l < 5; l++) {
            lg[l] = g_logits[(((size_t)b * 5 + l) * 500 + n) * 64 + tid];
            m = fmaxf(m, lg[l]);
        }
        float s = 0.f;
#pragma unroll
        for (int l = 0; l < 5; l++) { lg[l] = expf(lg[l] - m); s += lg[l]; }
        float inv = 1.f / s;
#pragma unroll
        for (int l = 0; l < 5; l++) wts[l][tid] = lg[l] * inv;
    }
    __syncthreads();
    size_t hbase = ((size_t)b * 500 + n) * 2048;
    const float* xb = x + (size_t)b * 1024000 + n * 64;
    for (int i = tid; i < 2048; i += 256) {
        int c = i >> 6, t = i & 63;
        float s = wts[0][t] * fmaxf(__ldg(xb + (size_t)c * 32000 + t), 0.f);
        s += wts[1][t] * fmaxf(g_h[0][hbase + i], 0.f);
        s += wts[2][t] * fmaxf(g_h[1][hbase + i], 0.f);
        s += wts[3][t] * fmaxf(g_h[2][hbase + i], 0.f);
        s += wts[4][t] * fmaxf(g_h[3][hbase + i], 0.f);
        out[((size_t)(b * 32 + c) * 500 + n) * 64 + t] = s;
    }
}

// ---------------- launch ----------------
extern "C" void kernel_launch(void* const* d_in, const int* in_sizes, int n_in,
                              void* d_out, int out_size) {
    (void)in_sizes; (void)n_in; (void)out_size;
    const float* x        = (const float*)d_in[0];
    const float* supports = (const float*)d_in[1];
    const float* bn_gamma = (const float*)d_in[2];
    const float* bn_beta  = (const float*)d_in[3];
    const float* res_w    = (const float*)d_in[4];
    const float* res_b    = (const float*)d_in[5];
    const float* aff_w    = (const float*)d_in[6];
    const float* aff_b    = (const float*)d_in[7];
    const float* gate_w   = (const float*)d_in[8];
    const float* gate_b   = (const float*)d_in[9];
    const float* gc_w     = (const float*)d_in[10];
    const float* gc_b     = (const float*)d_in[11];
    const float* attn_w1  = (const float*)d_in[12];
    const float* attn_b1  = (const float*)d_in[13];
    const float* attn_w2  = (const float*)d_in[14];
    const float* attn_b2  = (const float*)d_in[15];
    const float* attn_w3  = (const float*)d_in[16];
    const float* attn_b3  = (const float*)d_in[17];
    float* out = (float*)d_out;

    cudaFuncSetAttribute(st_front, cudaFuncAttributeMaxDynamicSharedMemorySize, 110592);

    prep_weights<<<32, 256>>>(res_w, aff_w, gate_w, gc_w, attn_w1, attn_w2);

    for (int l = 0; l < 4; l++) {
        bn_partial<<<dim3(32, 16), 256>>>(x, l);
        bn_finalize<<<1, 32>>>(bn_gamma + l * 32, bn_beta + l * 32);
        st_front<<<2000, 256, 110592>>>(x, l, res_b + l * 32, aff_b + l * 32,
                                        gate_b + l * 32, gc_b + l * 32);
        graph_mma<<<dim3(4, 16, 16), 256>>>(supports, l);
    }
    attn_logits<<<8000, 256>>>(x, attn_b1, attn_b2, attn_w3, attn_b3);
    attn_out<<<8000, 256>>>(x, out);
}

// round 5
// speedup vs baseline: 2.1400x; 1.1654x over previous
#include <cuda_runtime.h>
#include <cstdint>

// ---------------- scratch (static __device__, no allocations) ----------------
// n-major activation layout: [b][n][c*64+t], b-stride 1,024,000
__device__ __align__(16) float g_h[4][16384000];
__device__ __align__(16) float g_y0[16384000];
__device__ __align__(16) float g_z1[16384000];
__device__ __align__(16) float g_z2[16384000];
__device__ __align__(16) float g_logits[16 * 5 * 500 * 64];
__device__ float g_bnsum[32 * 16], g_bnsq[32 * 16];
__device__ float g_scale[32], g_shift[32];
// packed transposed weights per layer: [rwt 1024 | awt 3072 | gwt 3072 | gcwt 3072]
__device__ __align__(16) float g_wpack[4][10240];
__device__ __align__(16) float g_w1t[32 * 64];   // [c][d]
__device__ __align__(16) float g_w2t[64 * 64];   // [k][d]

// ---------------- packed f32x2 helpers ----------------
typedef unsigned long long u64;
__device__ __forceinline__ u64 pk2(float lo, float hi) {
    u64 r; asm("mov.b64 %0,{%1,%2};" : "=l"(r) : "f"(lo), "f"(hi)); return r;
}
__device__ __forceinline__ u64 pkb(float v) { return pk2(v, v); }
__device__ __forceinline__ void fma2(u64& d, u64 a, u64 b) {
    asm("fma.rn.f32x2 %0,%1,%2,%0;" : "+l"(d) : "l"(a), "l"(b));
}
__device__ __forceinline__ float2 up2(u64 v) {
    float2 f; asm("mov.b64 {%0,%1},%2;" : "=f"(f.x), "=f"(f.y) : "l"(v)); return f;
}

// ---------------- weight transposes / packing ----------------
__global__ void prep_weights(const float* __restrict__ rw, const float* __restrict__ aw,
                             const float* __restrict__ gw, const float* __restrict__ gcw,
                             const float* __restrict__ w1, const float* __restrict__ w2) {
    int tid = blockIdx.x * blockDim.x + threadIdx.x;
    int nt = gridDim.x * blockDim.x;
    for (int l = 0; l < 4; l++) {
        float* wp = g_wpack[l];
        for (int i = tid; i < 1024; i += nt) {
            int c = i >> 5, o = i & 31;
            wp[c * 32 + o] = rw[l * 1024 + o * 32 + c];
        }
        for (int i = tid; i < 3072; i += nt) {
            int ck = i >> 5, o = i & 31;
            wp[1024 + ck * 32 + o] = aw[l * 3072 + o * 96 + ck];
            wp[4096 + ck * 32 + o] = gw[l * 3072 + o * 96 + ck];
            wp[7168 + ck * 32 + o] = gcw[l * 3072 + o * 96 + ck];
        }
    }
    for (int i = tid; i < 64 * 32; i += nt) { int d = i / 32, c = i % 32; g_w1t[c * 64 + d] = w1[i]; }
    for (int i = tid; i < 64 * 64; i += nt) { int d = i / 64, k = i % 64; g_w2t[k * 64 + d] = w2[i]; }
}

// ---------------- batchnorm stats ----------------
__global__ void bn_partial(const float* __restrict__ x, int layer) {
    int c = blockIdx.x, b = blockIdx.y;
    float s = 0.f, q = 0.f;
    if (layer == 0) {
        const float* p = x + (size_t)(b * 32 + c) * 32000;
        for (int i = threadIdx.x; i < 32000; i += 256) {
            float v = __ldg(p + i);
            s += v; q += v * v;
        }
    } else {
        const float* p = g_h[layer - 1] + (size_t)b * 1024000 + c * 64;
        for (int i = threadIdx.x; i < 32000; i += 256) {
            float v = __ldg(p + (size_t)(i >> 6) * 2048 + (i & 63));
            s += v; q += v * v;
        }
    }
    for (int o = 16; o; o >>= 1) {
        s += __shfl_down_sync(0xffffffffu, s, o);
        q += __shfl_down_sync(0xffffffffu, q, o);
    }
    __shared__ float ss[8], qq[8];
    int w = threadIdx.x >> 5;
    if ((threadIdx.x & 31) == 0) { ss[w] = s; qq[w] = q; }
    __syncthreads();
    if (threadIdx.x == 0) {
        float S = 0.f, Q = 0.f;
        for (int i = 0; i < 8; i++) { S += ss[i]; Q += qq[i]; }
        g_bnsum[c * 16 + b] = S;
        g_bnsq[c * 16 + b] = Q;
    }
}

__global__ void bn_finalize(const float* __restrict__ gamma, const float* __restrict__ beta) {
    int c = threadIdx.x;
    float S = 0.f, Q = 0.f;
    for (int b = 0; b < 16; b++) { S += g_bnsum[c * 16 + b]; Q += g_bnsq[c * 16 + b]; }
    const float inv = 1.0f / 512000.0f;
    float m = S * inv;
    float var = Q * inv - m * m;
    float rstd = rsqrtf(var + 1e-5f);
    float sc = gamma[c] * rstd;
    g_scale[c] = sc;
    g_shift[c] = beta[c] - m * sc;
}

// ---------------- fused front: bn+relu, res 1x1, causal convs, gate, gc pre-projection ----------------
// block = 4 n-positions, 256 threads = 4 nl x (8 og x 8 tg). Each thread: 4 o x 8 t.
// dyn smem floats: [weights 10240 | xs 4*2048 (reused for x1) | ys 4*2304] = 27648 fl = 110592 B
// __launch_bounds__(256, 2): cap regs at 128 so 2 blocks/SM co-reside.
__global__ __launch_bounds__(256, 2) void st_front(
    const float* __restrict__ x, int layer,
    const float* __restrict__ rb, const float* __restrict__ ab,
    const float* __restrict__ gb, const float* __restrict__ gcb) {
    extern __shared__ float sm[];
    float* sw = sm;             // 10240 weights
    float* xs = sm + 10240;     // 4 x 2048 (raw x; later x1)
    float* ys = sm + 18432;     // 4 x (32*72), index i=t+2

    int tid = threadIdx.x;
    int b = blockIdx.x / 125, n0 = (blockIdx.x % 125) * 4;

    // stage weights
    {
        const float4* wp = (const float4*)g_wpack[layer];
        float4* swd = (float4*)sw;
        for (int i = tid; i < 2560; i += 256) swd[i] = wp[i];
    }
    // zero ys pads: cols {0,1} (left) and {66..71} (right) — DISJOINT from data cols 2..65
    for (int i = tid; i < 1024; i += 256) {
        int nl = i >> 8, r = (i >> 3) & 31, p = i & 7;
        int col = (p < 2) ? p : (p + 64);
        ys[nl * 2304 + r * 72 + col] = 0.f;
    }

    // load activations + bn+relu
    if (layer == 0) {
        const float* xb = x + (size_t)b * 1024000;
        for (int i = tid; i < 8192; i += 256) {
            int nl = i >> 11, idx = i & 2047;
            int c = idx >> 6, t = idx & 63;
            float xv = __ldg(xb + (size_t)c * 32000 + (n0 + nl) * 64 + t);
            xs[nl * 2048 + idx] = xv;
            ys[nl * 2304 + c * 72 + t + 2] = fmaxf(g_scale[c] * xv + g_shift[c], 0.f);
        }
    } else {
        const float* hb = g_h[layer - 1] + ((size_t)b * 500 + n0) * 2048;
        for (int i = tid; i < 8192; i += 256) {
            int nl = i >> 11, idx = i & 2047;
            int c = idx >> 6, t = idx & 63;
            float xv = hb[(size_t)nl * 2048 + idx];
            xs[nl * 2048 + idx] = xv;
            ys[nl * 2304 + c * 72 + t + 2] = fmaxf(g_scale[c] * xv + g_shift[c], 0.f);
        }
    }
    __syncthreads();

    int nl = tid >> 6;
    int wt = tid & 63;
    int og = wt >> 3, tg = wt & 7;
    int o0 = og * 4, t0 = tg * 8;
    const float* xsn = xs + nl * 2048;
    const float* ysn = ys + nl * 2304;
    const float* rs  = sw;
    const float* as_ = sw + 1024;
    const float* gs  = sw + 4096;

    // aff accumulates res too (tanh(aff + res)); init with biases
    u64 ua[4][4], ug[4][4];
#pragma unroll
    for (int i = 0; i < 4; i++) {
        u64 ba = pkb(ab[o0 + i] + rb[o0 + i]);
        u64 bg = pkb(gb[o0 + i]);
#pragma unroll
        for (int j = 0; j < 4; j++) { ua[i][j] = ba; ug[i][j] = bg; }
    }

#pragma unroll 2
    for (int c = 0; c < 32; c++) {
        // res
        float4 wr = *(const float4*)&rs[c * 32 + o0];
        float4 xa = *(const float4*)&xsn[c * 64 + t0];
        float4 xb2 = *(const float4*)&xsn[c * 64 + t0 + 4];
        u64 px[4] = { pk2(xa.x, xa.y), pk2(xa.z, xa.w), pk2(xb2.x, xb2.y), pk2(xb2.z, xb2.w) };
        float wri[4] = { wr.x, wr.y, wr.z, wr.w };
#pragma unroll
        for (int i = 0; i < 4; i++) {
            u64 w2 = pkb(wri[i]);
#pragma unroll
            for (int j = 0; j < 4; j++) fma2(ua[i][j], w2, px[j]);
        }
        // conv window
        float v[12];
        *(float4*)&v[0] = *(const float4*)&ysn[c * 72 + t0];
        *(float4*)&v[4] = *(const float4*)&ysn[c * 72 + t0 + 4];
        *(float4*)&v[8] = *(const float4*)&ysn[c * 72 + t0 + 8];
#pragma unroll
        for (int kk = 0; kk < 3; kk++) {
            u64 pw[4];
#pragma unroll
            for (int j = 0; j < 4; j++) pw[j] = pk2(v[kk + 2 * j], v[kk + 2 * j + 1]);
            float4 wa = *(const float4*)&as_[(c * 3 + kk) * 32 + o0];
            float4 wg = *(const float4*)&gs[(c * 3 + kk) * 32 + o0];
            float wai[4] = { wa.x, wa.y, wa.z, wa.w };
            float wgi[4] = { wg.x, wg.y, wg.z, wg.w };
#pragma unroll
            for (int i = 0; i < 4; i++) {
                u64 a2 = pkb(wai[i]);
                u64 g2 = pkb(wgi[i]);
#pragma unroll
                for (int j = 0; j < 4; j++) { fma2(ua[i][j], a2, pw[j]); fma2(ug[i][j], g2, pw[j]); }
            }
        }
    }

    // x1 = tanh(aff+res) * sigmoid(gate)
    float x1v[4][8];
#pragma unroll
    for (int i = 0; i < 4; i++)
#pragma unroll
        for (int j = 0; j < 4; j++) {
            float2 a = up2(ua[i][j]);
            float2 g = up2(ug[i][j]);
            x1v[i][2 * j]     = tanhf(a.x) * (1.f / (1.f + expf(-g.x)));
            x1v[i][2 * j + 1] = tanhf(a.y) * (1.f / (1.f + expf(-g.y)));
        }
    __syncthreads();   // everyone done reading xs
    float* x1n = xs + nl * 2048;
#pragma unroll
    for (int i = 0; i < 4; i++) {
        *(float4*)&x1n[(o0 + i) * 64 + t0]     = *(float4*)&x1v[i][0];
        *(float4*)&x1n[(o0 + i) * 64 + t0 + 4] = *(float4*)&x1v[i][4];
    }
    __syncthreads();

    // gc pre-projection: y0 = W0 x1 + b, z1 = W1 x1, z2 = W2 x1
    // Split over two t-half chunks (jc) to halve live accumulators (24 u64 vs 48).
    const float* cs = sw + 7168;
    float gcbv[4];
#pragma unroll
    for (int i = 0; i < 4; i++) gcbv[i] = gcb[o0 + i];
    size_t obase0 = ((size_t)b * 500 + n0 + nl) * 2048 + t0;

#pragma unroll
    for (int jc = 0; jc < 2; jc++) {
        u64 uy[4][2], uz1[4][2], uz2[4][2];
#pragma unroll
        for (int i = 0; i < 4; i++) {
            u64 by = pkb(gcbv[i]);
            uy[i][0] = by; uy[i][1] = by;
            uz1[i][0] = 0ull; uz1[i][1] = 0ull;
            uz2[i][0] = 0ull; uz2[i][1] = 0ull;
        }
#pragma unroll 2
        for (int c = 0; c < 32; c++) {
            float4 xa = *(const float4*)&x1n[c * 64 + t0 + jc * 4];
            u64 px0 = pk2(xa.x, xa.y), px1 = pk2(xa.z, xa.w);
            float4 w0 = *(const float4*)&cs[c * 32 + o0];
            float4 w1 = *(const float4*)&cs[(32 + c) * 32 + o0];
            float4 w2 = *(const float4*)&cs[(64 + c) * 32 + o0];
            float w0i[4] = { w0.x, w0.y, w0.z, w0.w };
            float w1i[4] = { w1.x, w1.y, w1.z, w1.w };
            float w2i[4] = { w2.x, w2.y, w2.z, w2.w };
#pragma unroll
            for (int i = 0; i < 4; i++) {
                u64 a0 = pkb(w0i[i]), a1 = pkb(w1i[i]), a2 = pkb(w2i[i]);
                fma2(uy[i][0], a0, px0);  fma2(uy[i][1], a0, px1);
                fma2(uz1[i][0], a1, px0); fma2(uz1[i][1], a1, px1);
                fma2(uz2[i][0], a2, px0); fma2(uz2[i][1], a2, px1);
            }
        }
#pragma unroll
        for (int i = 0; i < 4; i++) {
            size_t oidx = obase0 + (size_t)(o0 + i) * 64 + jc * 4;
            float buf[4];
            float2 f;
            f = up2(uy[i][0]);  buf[0] = f.x; buf[1] = f.y;
            f = up2(uy[i][1]);  buf[2] = f.x; buf[3] = f.y;
            *(float4*)(g_y0 + oidx) = *(float4*)buf;
            f = up2(uz1[i][0]); buf[0] = f.x; buf[1] = f.y;
            f = up2(uz1[i][1]); buf[2] = f.x; buf[3] = f.y;
            *(float4*)(g_z1 + oidx) = *(float4*)buf;
            f = up2(uz2[i][0]); buf[0] = f.x; buf[1] = f.y;
            f = up2(uz2[i][1]); buf[2] = f.x; buf[3] = f.y;
            *(float4*)(g_z2 + oidx) = *(float4*)buf;
        }
    }
}

// ---------------- graph diffusion with tf32 tensor cores ----------------
__device__ __forceinline__ float to_tf32(float x) {
    asm("cvt.rna.tf32.f32 %0, %1;" : "=f"(x) : "f"(x));
    return x;
}
__device__ __forceinline__ void mma_tf32(float& d0, float& d1, float& d2, float& d3,
                                         uint32_t a0, uint32_t a1, uint32_t a2, uint32_t a3,
                                         uint32_t b0, uint32_t b1) {
    asm volatile(
        "mma.sync.aligned.m16n8k8.row.col.f32.tf32.tf32.f32 "
        "{%0,%1,%2,%3},{%4,%5,%6,%7},{%8,%9},{%0,%1,%2,%3};"
        : "+f"(d0), "+f"(d1), "+f"(d2), "+f"(d3)
        : "r"(a0), "r"(a1), "r"(a2), "r"(a3), "r"(b0), "r"(b1));
}

// out[b](500x2048) = A1^T Z1[b] + A2^T Z2[b] + Y0[b]
__global__ __launch_bounds__(256) void graph_mma(const float* __restrict__ A, int layer) {
    __shared__ __align__(16) float As[2][16][136];
    __shared__ __align__(16) float Zs[2][16][136];

    int tid = threadIdx.x;
    int m0 = blockIdx.x * 128;
    int n0 = blockIdx.y * 128;
    int bb = blockIdx.z;
    int lane = tid & 31, wid = tid >> 5;
    int wm = wid & 1, wn = wid >> 1;
    int mbase = wm * 64, nbase = wn * 32;
    int gid = lane >> 2, tig = lane & 3;

    int r = tid >> 4;
    int cseg = (tid & 15) * 8;

    float acc[4][4][4];
#pragma unroll
    for (int i = 0; i < 4; i++)
#pragma unroll
        for (int j = 0; j < 4; j++)
#pragma unroll
            for (int k = 0; k < 4; k++) acc[i][j][k] = 0.f;

    auto load_stage = [&](int st, int buf) {
        int e = st >> 5;
        int v = ((st & 31) << 4) + r;
        float va[8], vz[8];
        if (v < 500) {
            const float* ap = A + (size_t)e * 250000 + (size_t)v * 500 + m0 + cseg;
            if (m0 + cseg + 7 < 500) {
                *(float4*)&va[0] = __ldg((const float4*)ap);
                *(float4*)&va[4] = __ldg((const float4*)(ap + 4));
            } else {
#pragma unroll
                for (int q = 0; q < 8; q++)
                    va[q] = (m0 + cseg + q < 500) ? __ldg(ap + q) : 0.f;
            }
            const float* zb = (e ? g_z2 : g_z1);
            const float* zp = zb + ((size_t)bb * 500 + v) * 2048 + n0 + cseg;
            *(float4*)&vz[0] = __ldg((const float4*)zp);
            *(float4*)&vz[4] = __ldg((const float4*)(zp + 4));
        } else {
#pragma unroll
            for (int q = 0; q < 8; q++) { va[q] = 0.f; vz[q] = 0.f; }
        }
#pragma unroll
        for (int q = 0; q < 8; q++) { va[q] = to_tf32(va[q]); vz[q] = to_tf32(vz[q]); }
        *(float4*)&As[buf][r][cseg]     = *(float4*)&va[0];
        *(float4*)&As[buf][r][cseg + 4] = *(float4*)&va[4];
        *(float4*)&Zs[buf][r][cseg]     = *(float4*)&vz[0];
        *(float4*)&Zs[buf][r][cseg + 4] = *(float4*)&vz[4];
    };

    load_stage(0, 0);
    __syncthreads();

    for (int st = 0; st < 64; st++) {
        int cur = st & 1;
        if (st + 1 < 64) load_stage(st + 1, cur ^ 1);
#pragma unroll
        for (int kk = 0; kk < 16; kk += 8) {
            uint32_t bf[4][2];
#pragma unroll
            for (int nt = 0; nt < 4; nt++) {
                bf[nt][0] = __float_as_uint(Zs[cur][kk + tig][nbase + nt * 8 + gid]);
                bf[nt][1] = __float_as_uint(Zs[cur][kk + tig + 4][nbase + nt * 8 + gid]);
            }
#pragma unroll
            for (int mt = 0; mt < 4; mt++) {
                int mr = mbase + mt * 16 + gid;
                uint32_t a0 = __float_as_uint(As[cur][kk + tig][mr]);
                uint32_t a1 = __float_as_uint(As[cur][kk + tig][mr + 8]);
                uint32_t a2 = __float_as_uint(As[cur][kk + tig + 4][mr]);
                uint32_t a3 = __float_as_uint(As[cur][kk + tig + 4][mr + 8]);
#pragma unroll
                for (int nt = 0; nt < 4; nt++)
                    mma_tf32(acc[mt][nt][0], acc[mt][nt][1], acc[mt][nt][2], acc[mt][nt][3],
                             a0, a1, a2, a3, bf[nt][0], bf[nt][1]);
            }
        }
        __syncthreads();
    }

    float* hout = g_h[layer];
    size_t bbase = (size_t)bb * 1024000;
#pragma unroll
    for (int mt = 0; mt < 4; mt++) {
#pragma unroll
        for (int nt = 0; nt < 4; nt++) {
            int w0 = m0 + mbase + mt * 16 + gid;
            int j = n0 + nbase + nt * 8 + 2 * tig;
            if (w0 < 500) {
                size_t idx = bbase + (size_t)w0 * 2048 + j;
                float2 y = *(const float2*)(g_y0 + idx);
                float2 rres;
                rres.x = acc[mt][nt][0] + y.x;
                rres.y = acc[mt][nt][1] + y.y;
                *(float2*)(hout + idx) = rres;
            }
            if (w0 + 8 < 500) {
                size_t idx = bbase + (size_t)(w0 + 8) * 2048 + j;
                float2 y = *(const float2*)(g_y0 + idx);
                float2 rres;
                rres.x = acc[mt][nt][2] + y.x;
                rres.y = acc[mt][nt][3] + y.y;
                *(float2*)(hout + idx) = rres;
            }
        }
    }
}

// ---------------- attention logits ----------------
__global__ __launch_bounds__(256) void attn_logits(
    const float* __restrict__ x,
    const float* __restrict__ b1, const float* __restrict__ b2,
    const float* __restrict__ w3, const float* __restrict__ b3) {
    __shared__ __align__(16) float vbuf[32][64];
    __shared__ __align__(16) float e1s[64][64];
    __shared__ __align__(16) float red[16][64];
    __shared__ __align__(16) float sw1[32 * 64];
    __shared__ __align__(16) float sw2[64 * 64];
    int tid = threadIdx.x;
    int b = blockIdx.x / 500, n = blockIdx.x % 500;
    int ty = tid >> 4, tx = tid & 15;
    float b3v = b3[0];

    // stage attention weights once per block
    for (int i = tid; i < 512; i += 256) ((float4*)sw1)[i] = ((const float4*)g_w1t)[i];
    for (int i = tid; i < 1024; i += 256) ((float4*)sw2)[i] = ((const float4*)g_w2t)[i];

    for (int l = 0; l < 5; l++) {
        __syncthreads();
        if (l == 0) {
            const float* xb = x + (size_t)b * 1024000 + n * 64;
            for (int i = tid; i < 2048; i += 256) {
                int c = i >> 6, t = i & 63;
                vbuf[c][t] = fmaxf(__ldg(xb + (size_t)c * 32000 + t), 0.f);
            }
        } else {
            const float* hb = g_h[l - 1] + ((size_t)b * 500 + n) * 2048;
            for (int i = tid; i < 2048; i += 256)
                (&vbuf[0][0])[i] = fmaxf(hb[i], 0.f);
        }
        __syncthreads();

        u64 a1p[4][2];
#pragma unroll
        for (int i = 0; i < 4; i++) { a1p[i][0] = 0ull; a1p[i][1] = 0ull; }
#pragma unroll 4
        for (int k = 0; k < 32; k++) {
            float4 w = *(const float4*)&sw1[k * 64 + ty * 4];
            float4 v = *(const float4*)&vbuf[k][tx * 4];
            u64 pv0 = pk2(v.x, v.y), pv1 = pk2(v.z, v.w);
            float wi[4] = { w.x, w.y, w.z, w.w };
#pragma unroll
            for (int i = 0; i < 4; i++) {
                u64 wp = pkb(wi[i]);
                fma2(a1p[i][0], wp, pv0);
                fma2(a1p[i][1], wp, pv1);
            }
        }
#pragma unroll
        for (int i = 0; i < 4; i++) {
            float bb = b1[ty * 4 + i];
            float2 f0 = up2(a1p[i][0]), f1 = up2(a1p[i][1]);
            e1s[ty * 4 + i][tx * 4 + 0] = fmaxf(f0.x + bb, 0.f);
            e1s[ty * 4 + i][tx * 4 + 1] = fmaxf(f0.y + bb, 0.f);
            e1s[ty * 4 + i][tx * 4 + 2] = fmaxf(f1.x + bb, 0.f);
            e1s[ty * 4 + i][tx * 4 + 3] = fmaxf(f1.y + bb, 0.f);
        }
        __syncthreads();

        u64 a2p[4][2];
#pragma unroll
        for (int i = 0; i < 4; i++) { a2p[i][0] = 0ull; a2p[i][1] = 0ull; }
#pragma unroll 4
        for (int k = 0; k < 64; k++) {
            float4 w = *(const float4*)&sw2[k * 64 + ty * 4];
            float4 v = *(const float4*)&e1s[k][tx * 4];
            u64 pv0 = pk2(v.x, v.y), pv1 = pk2(v.z, v.w);
            float wi[4] = { w.x, w.y, w.z, w.w };
#pragma unroll
            for (int i = 0; i < 4; i++) {
                u64 wp = pkb(wi[i]);
                fma2(a2p[i][0], wp, pv0);
                fma2(a2p[i][1], wp, pv1);
            }
        }
        float p[4] = {0.f, 0.f, 0.f, 0.f};
#pragma unroll
        for (int i = 0; i < 4; i++) {
            float bb = b2[ty * 4 + i];
            float wc = w3[ty * 4 + i];
            float2 f0 = up2(a2p[i][0]), f1 = up2(a2p[i][1]);
            p[0] += wc * fmaxf(f0.x + bb, 0.f);
            p[1] += wc * fmaxf(f0.y + bb, 0.f);
            p[2] += wc * fmaxf(f1.x + bb, 0.f);
            p[3] += wc * fmaxf(f1.y + bb, 0.f);
        }
#pragma unroll
        for (int j = 0; j < 4; j++) red[ty][tx * 4 + j] = p[j];
        __syncthreads();
        if (tid < 64) {
            float s = b3v;
#pragma unroll
            for (int q = 0; q < 16; q++) s += red[q][tid];
            g_logits[(((size_t)b * 5 + l) * 500 + n) * 64 + tid] = s;
        }
    }
}

// ---------------- softmax over L+1 and weighted sum ----------------
__global__ __launch_bounds__(256) void attn_out(const float* __restrict__ x, float* __restrict__ out) {
    __shared__ float wts[5][64];
    int tid = threadIdx.x;
    int b = blockIdx.x / 500, n = blockIdx.x % 500;
    if (tid < 64) {
        float lg[5];
        float m = -1e30f;
#pragma unroll
        for (int l = 0; l < 5; l++) {
            lg[l] = g_logits[(((size_t)b * 5 + l) * 500 + n) * 64 + tid];
            m = fmaxf(m, lg[l]);
        }
        float s = 0.f;
#pragma unroll
        for (int l = 0; l < 5; l++) { lg[l] = expf(lg[l] - m); s += lg[l]; }
        float inv = 1.f / s;
#pragma unroll
        for (int l = 0; l < 5; l++) wts[l][tid] = lg[l] * inv;
    }
    __syncthreads();
    size_t hbase = ((size_t)b * 500 + n) * 2048;
    const float* xb = x + (size_t)b * 1024000 + n * 64;
    for (int i = tid; i < 2048; i += 256) {
        int c = i >> 6, t = i & 63;
        float s = wts[0][t] * fmaxf(__ldg(xb + (size_t)c * 32000 + t), 0.f);
        s += wts[1][t] * fmaxf(g_h[0][hbase + i], 0.f);
        s += wts[2][t] * fmaxf(g_h[1][hbase + i], 0.f);
        s += wts[3][t] * fmaxf(g_h[2][hbase + i], 0.f);
        s += wts[4][t] * fmaxf(g_h[3][hbase + i], 0.f);
        out[((size_t)(b * 32 + c) * 500 + n) * 64 + t] = s;
    }
}

// ---------------- launch ----------------
extern "C" void kernel_launch(void* const* d_in, const int* in_sizes, int n_in,
                              void* d_out, int out_size) {
    (void)in_sizes; (void)n_in; (void)out_size;
    const float* x        = (const float*)d_in[0];
    const float* supports = (const float*)d_in[1];
    const float* bn_gamma = (const float*)d_in[2];
    const float* bn_beta  = (const float*)d_in[3];
    const float* res_w    = (const float*)d_in[4];
    const float* res_b    = (const float*)d_in[5];
    const float* aff_w    = (const float*)d_in[6];
    const float* aff_b    = (const float*)d_in[7];
    const float* gate_w   = (const float*)d_in[8];
    const float* gate_b   = (const float*)d_in[9];
    const float* gc_w     = (const float*)d_in[10];
    const float* gc_b     = (const float*)d_in[11];
    const float* attn_w1  = (const float*)d_in[12];
    const float* attn_b1  = (const float*)d_in[13];
    const float* attn_w2  = (const float*)d_in[14];
    const float* attn_b2  = (const float*)d_in[15];
    const float* attn_w3  = (const float*)d_in[16];
    const float* attn_b3  = (const float*)d_in[17];
    float* out = (float*)d_out;

    cudaFuncSetAttribute(st_front, cudaFuncAttributeMaxDynamicSharedMemorySize, 110592);

    prep_weights<<<32, 256>>>(res_w, aff_w, gate_w, gc_w, attn_w1, attn_w2);

    for (int l = 0; l < 4; l++) {
        bn_partial<<<dim3(32, 16), 256>>>(x, l);
        bn_finalize<<<1, 32>>>(bn_gamma + l * 32, bn_beta + l * 32);
        st_front<<<2000, 256, 110592>>>(x, l, res_b + l * 32, aff_b + l * 32,
                                        gate_b + l * 32, gc_b + l * 32);
        graph_mma<<<dim3(4, 16, 16), 256>>>(supports, l);
    }
    attn_logits<<<8000, 256>>>(x, attn_b1, attn_b2, attn_w3, attn_b3);
    attn_out<<<8000, 256>>>(x, out);
}

// round 6
// speedup vs baseline: 2.6508x; 1.2387x over previous
#include <cuda_runtime.h>
#include <cuda_bf16.h>
#include <cstdint>

// ---------------- scratch (static __device__, no allocations) ----------------
// n-major activation layout: [b][n][c*64+t], b-stride 1,024,000
__device__ __align__(16) float g_h[4][16384000];
__device__ __align__(16) float g_y0[16384000];
__device__ __align__(16) __nv_bfloat16 g_z1h[16384000];
__device__ __align__(16) __nv_bfloat16 g_z2h[16384000];
__device__ __align__(16) uint32_t g_Asp[2][256][512];   // bf16x2 k-pair packed A, zero-padded
__device__ __align__(16) float g_logits[16 * 5 * 500 * 64];
__device__ float g_bnsum[32 * 16], g_bnsq[32 * 16];
__device__ float g_scale[32], g_shift[32];
// packed transposed weights per layer: [rwt 1024 | awt 3072 | gwt 3072 | gcwt 3072]
__device__ __align__(16) float g_wpack[4][10240];
__device__ __align__(16) float g_w1t[32 * 64];   // [c][d]
__device__ __align__(16) float g_w2t[64 * 64];   // [k][d]

// ---------------- packed f32x2 helpers ----------------
typedef unsigned long long u64;
__device__ __forceinline__ u64 pk2(float lo, float hi) {
    u64 r; asm("mov.b64 %0,{%1,%2};" : "=l"(r) : "f"(lo), "f"(hi)); return r;
}
__device__ __forceinline__ u64 pkb(float v) { return pk2(v, v); }
__device__ __forceinline__ void fma2(u64& d, u64 a, u64 b) {
    asm("fma.rn.f32x2 %0,%1,%2,%0;" : "+l"(d) : "l"(a), "l"(b));
}
__device__ __forceinline__ float2 up2(u64 v) {
    float2 f; asm("mov.b64 {%0,%1},%2;" : "=f"(f.x), "=f"(f.y) : "l"(v)); return f;
}
__device__ __forceinline__ uint32_t bf16x2_of(float lo, float hi) {
    uint32_t r; asm("cvt.rn.bf16x2.f32 %0,%1,%2;" : "=r"(r) : "f"(hi), "f"(lo)); return r;
}

// ---------------- weight transposes / packing ----------------
__global__ void prep_weights(const float* __restrict__ rw, const float* __restrict__ aw,
                             const float* __restrict__ gw, const float* __restrict__ gcw,
                             const float* __restrict__ w1, const float* __restrict__ w2,
                             const float* __restrict__ A) {
    int tid = blockIdx.x * blockDim.x + threadIdx.x;
    int nt = gridDim.x * blockDim.x;
    for (int l = 0; l < 4; l++) {
        float* wp = g_wpack[l];
        for (int i = tid; i < 1024; i += nt) {
            int c = i >> 5, o = i & 31;
            wp[c * 32 + o] = rw[l * 1024 + o * 32 + c];
        }
        for (int i = tid; i < 3072; i += nt) {
            int ck = i >> 5, o = i & 31;
            wp[1024 + ck * 32 + o] = aw[l * 3072 + o * 96 + ck];
            wp[4096 + ck * 32 + o] = gw[l * 3072 + o * 96 + ck];
            wp[7168 + ck * 32 + o] = gcw[l * 3072 + o * 96 + ck];
        }
    }
    for (int i = tid; i < 64 * 32; i += nt) { int d = i / 32, c = i % 32; g_w1t[c * 64 + d] = w1[i]; }
    for (int i = tid; i < 64 * 64; i += nt) { int d = i / 64, k = i % 64; g_w2t[k * 64 + d] = w2[i]; }
    // pack A supports into bf16x2 k-pairs: g_Asp[e][kp][m] = {A[e][2kp][m], A[e][2kp+1][m]}
    for (int i = tid; i < 2 * 256 * 512; i += nt) {
        int e = i >> 17, kp = (i >> 9) & 255, m = i & 511;
        int v0 = 2 * kp, v1 = v0 + 1;
        float lo = (v0 < 500 && m < 500) ? A[(size_t)e * 250000 + (size_t)v0 * 500 + m] : 0.f;
        float hi = (v1 < 500 && m < 500) ? A[(size_t)e * 250000 + (size_t)v1 * 500 + m] : 0.f;
        g_Asp[e][kp][m] = bf16x2_of(lo, hi);
    }
}

// ---------------- batchnorm stats ----------------
__global__ void bn_partial(const float* __restrict__ x, int layer) {
    int c = blockIdx.x, b = blockIdx.y;
    float s = 0.f, q = 0.f;
    if (layer == 0) {
        const float* p = x + (size_t)(b * 32 + c) * 32000;
        for (int i = threadIdx.x; i < 32000; i += 256) {
            float v = __ldg(p + i);
            s += v; q += v * v;
        }
    } else {
        const float* p = g_h[layer - 1] + (size_t)b * 1024000 + c * 64;
        for (int i = threadIdx.x; i < 32000; i += 256) {
            float v = __ldg(p + (size_t)(i >> 6) * 2048 + (i & 63));
            s += v; q += v * v;
        }
    }
    for (int o = 16; o; o >>= 1) {
        s += __shfl_down_sync(0xffffffffu, s, o);
        q += __shfl_down_sync(0xffffffffu, q, o);
    }
    __shared__ float ss[8], qq[8];
    int w = threadIdx.x >> 5;
    if ((threadIdx.x & 31) == 0) { ss[w] = s; qq[w] = q; }
    __syncthreads();
    if (threadIdx.x == 0) {
        float S = 0.f, Q = 0.f;
        for (int i = 0; i < 8; i++) { S += ss[i]; Q += qq[i]; }
        g_bnsum[c * 16 + b] = S;
        g_bnsq[c * 16 + b] = Q;
    }
}

__global__ void bn_finalize(const float* __restrict__ gamma, const float* __restrict__ beta) {
    int c = threadIdx.x;
    float S = 0.f, Q = 0.f;
    for (int b = 0; b < 16; b++) { S += g_bnsum[c * 16 + b]; Q += g_bnsq[c * 16 + b]; }
    const float inv = 1.0f / 512000.0f;
    float m = S * inv;
    float var = Q * inv - m * m;
    float rstd = rsqrtf(var + 1e-5f);
    float sc = gamma[c] * rstd;
    g_scale[c] = sc;
    g_shift[c] = beta[c] - m * sc;
}

// ---------------- fused front: bn+relu, res 1x1, causal convs, gate, gc pre-projection ----------------
__global__ __launch_bounds__(256, 2) void st_front(
    const float* __restrict__ x, int layer,
    const float* __restrict__ rb, const float* __restrict__ ab,
    const float* __restrict__ gb, const float* __restrict__ gcb) {
    extern __shared__ float sm[];
    float* sw = sm;             // 10240 weights
    float* xs = sm + 10240;     // 4 x 2048 (raw x; later x1)
    float* ys = sm + 18432;     // 4 x (32*72), index i=t+2

    int tid = threadIdx.x;
    int b = blockIdx.x / 125, n0 = (blockIdx.x % 125) * 4;

    {
        const float4* wp = (const float4*)g_wpack[layer];
        float4* swd = (float4*)sw;
        for (int i = tid; i < 2560; i += 256) swd[i] = wp[i];
    }
    // zero ys pads: cols {0,1} and {66..71} — disjoint from data cols 2..65
    for (int i = tid; i < 1024; i += 256) {
        int nl = i >> 8, r = (i >> 3) & 31, p = i & 7;
        int col = (p < 2) ? p : (p + 64);
        ys[nl * 2304 + r * 72 + col] = 0.f;
    }

    if (layer == 0) {
        const float* xb = x + (size_t)b * 1024000;
        for (int i = tid; i < 8192; i += 256) {
            int nl = i >> 11, idx = i & 2047;
            int c = idx >> 6, t = idx & 63;
            float xv = __ldg(xb + (size_t)c * 32000 + (n0 + nl) * 64 + t);
            xs[nl * 2048 + idx] = xv;
            ys[nl * 2304 + c * 72 + t + 2] = fmaxf(g_scale[c] * xv + g_shift[c], 0.f);
        }
    } else {
        const float* hb = g_h[layer - 1] + ((size_t)b * 500 + n0) * 2048;
        for (int i = tid; i < 8192; i += 256) {
            int nl = i >> 11, idx = i & 2047;
            int c = idx >> 6, t = idx & 63;
            float xv = hb[(size_t)nl * 2048 + idx];
            xs[nl * 2048 + idx] = xv;
            ys[nl * 2304 + c * 72 + t + 2] = fmaxf(g_scale[c] * xv + g_shift[c], 0.f);
        }
    }
    __syncthreads();

    int nl = tid >> 6;
    int wt = tid & 63;
    int og = wt >> 3, tg = wt & 7;
    int o0 = og * 4, t0 = tg * 8;
    const float* xsn = xs + nl * 2048;
    const float* ysn = ys + nl * 2304;
    const float* rs  = sw;
    const float* as_ = sw + 1024;
    const float* gs  = sw + 4096;

    u64 ua[4][4], ug[4][4];
#pragma unroll
    for (int i = 0; i < 4; i++) {
        u64 ba = pkb(ab[o0 + i] + rb[o0 + i]);
        u64 bg = pkb(gb[o0 + i]);
#pragma unroll
        for (int j = 0; j < 4; j++) { ua[i][j] = ba; ug[i][j] = bg; }
    }

#pragma unroll 2
    for (int c = 0; c < 32; c++) {
        float4 wr = *(const float4*)&rs[c * 32 + o0];
        float4 xa = *(const float4*)&xsn[c * 64 + t0];
        float4 xb2 = *(const float4*)&xsn[c * 64 + t0 + 4];
        u64 px[4] = { pk2(xa.x, xa.y), pk2(xa.z, xa.w), pk2(xb2.x, xb2.y), pk2(xb2.z, xb2.w) };
        float wri[4] = { wr.x, wr.y, wr.z, wr.w };
#pragma unroll
        for (int i = 0; i < 4; i++) {
            u64 w2 = pkb(wri[i]);
#pragma unroll
            for (int j = 0; j < 4; j++) fma2(ua[i][j], w2, px[j]);
        }
        float v[12];
        *(float4*)&v[0] = *(const float4*)&ysn[c * 72 + t0];
        *(float4*)&v[4] = *(const float4*)&ysn[c * 72 + t0 + 4];
        *(float4*)&v[8] = *(const float4*)&ysn[c * 72 + t0 + 8];
#pragma unroll
        for (int kk = 0; kk < 3; kk++) {
            u64 pw[4];
#pragma unroll
            for (int j = 0; j < 4; j++) pw[j] = pk2(v[kk + 2 * j], v[kk + 2 * j + 1]);
            float4 wa = *(const float4*)&as_[(c * 3 + kk) * 32 + o0];
            float4 wg = *(const float4*)&gs[(c * 3 + kk) * 32 + o0];
            float wai[4] = { wa.x, wa.y, wa.z, wa.w };
            float wgi[4] = { wg.x, wg.y, wg.z, wg.w };
#pragma unroll
            for (int i = 0; i < 4; i++) {
                u64 a2 = pkb(wai[i]);
                u64 g2 = pkb(wgi[i]);
#pragma unroll
                for (int j = 0; j < 4; j++) { fma2(ua[i][j], a2, pw[j]); fma2(ug[i][j], g2, pw[j]); }
            }
        }
    }

    float x1v[4][8];
#pragma unroll
    for (int i = 0; i < 4; i++)
#pragma unroll
        for (int j = 0; j < 4; j++) {
            float2 a = up2(ua[i][j]);
            float2 g = up2(ug[i][j]);
            x1v[i][2 * j]     = tanhf(a.x) * (1.f / (1.f + expf(-g.x)));
            x1v[i][2 * j + 1] = tanhf(a.y) * (1.f / (1.f + expf(-g.y)));
        }
    __syncthreads();
    float* x1n = xs + nl * 2048;
#pragma unroll
    for (int i = 0; i < 4; i++) {
        *(float4*)&x1n[(o0 + i) * 64 + t0]     = *(float4*)&x1v[i][0];
        *(float4*)&x1n[(o0 + i) * 64 + t0 + 4] = *(float4*)&x1v[i][4];
    }
    __syncthreads();

    const float* cs = sw + 7168;
    float gcbv[4];
#pragma unroll
    for (int i = 0; i < 4; i++) gcbv[i] = gcb[o0 + i];
    size_t obase0 = ((size_t)b * 500 + n0 + nl) * 2048 + t0;

#pragma unroll
    for (int jc = 0; jc < 2; jc++) {
        u64 uy[4][2], uz1[4][2], uz2[4][2];
#pragma unroll
        for (int i = 0; i < 4; i++) {
            u64 by = pkb(gcbv[i]);
            uy[i][0] = by; uy[i][1] = by;
            uz1[i][0] = 0ull; uz1[i][1] = 0ull;
            uz2[i][0] = 0ull; uz2[i][1] = 0ull;
        }
#pragma unroll 2
        for (int c = 0; c < 32; c++) {
            float4 xa = *(const float4*)&x1n[c * 64 + t0 + jc * 4];
            u64 px0 = pk2(xa.x, xa.y), px1 = pk2(xa.z, xa.w);
            float4 w0 = *(const float4*)&cs[c * 32 + o0];
            float4 w1 = *(const float4*)&cs[(32 + c) * 32 + o0];
            float4 w2 = *(const float4*)&cs[(64 + c) * 32 + o0];
            float w0i[4] = { w0.x, w0.y, w0.z, w0.w };
            float w1i[4] = { w1.x, w1.y, w1.z, w1.w };
            float w2i[4] = { w2.x, w2.y, w2.z, w2.w };
#pragma unroll
            for (int i = 0; i < 4; i++) {
                u64 a0 = pkb(w0i[i]), a1 = pkb(w1i[i]), a2 = pkb(w2i[i]);
                fma2(uy[i][0], a0, px0);  fma2(uy[i][1], a0, px1);
                fma2(uz1[i][0], a1, px0); fma2(uz1[i][1], a1, px1);
                fma2(uz2[i][0], a2, px0); fma2(uz2[i][1], a2, px1);
            }
        }
#pragma unroll
        for (int i = 0; i < 4; i++) {
            size_t oidx = obase0 + (size_t)(o0 + i) * 64 + jc * 4;
            float buf[4];
            float2 f;
            f = up2(uy[i][0]);  buf[0] = f.x; buf[1] = f.y;
            f = up2(uy[i][1]);  buf[2] = f.x; buf[3] = f.y;
            *(float4*)(g_y0 + oidx) = *(float4*)buf;
            float2 z0 = up2(uz1[i][0]), z1 = up2(uz1[i][1]);
            uint2 uz;
            uz.x = bf16x2_of(z0.x, z0.y); uz.y = bf16x2_of(z1.x, z1.y);
            *(uint2*)(g_z1h + oidx) = uz;
            z0 = up2(uz2[i][0]); z1 = up2(uz2[i][1]);
            uz.x = bf16x2_of(z0.x, z0.y); uz.y = bf16x2_of(z1.x, z1.y);
            *(uint2*)(g_z2h + oidx) = uz;
        }
    }
}

// ---------------- graph diffusion with bf16 tensor cores ----------------
__device__ __forceinline__ void mma_bf16(float& d0, float& d1, float& d2, float& d3,
                                         uint32_t a0, uint32_t a1, uint32_t a2, uint32_t a3,
                                         uint32_t b0, uint32_t b1) {
    asm volatile(
        "mma.sync.aligned.m16n8k16.row.col.f32.bf16.bf16.f32 "
        "{%0,%1,%2,%3},{%4,%5,%6,%7},{%8,%9},{%0,%1,%2,%3};"
        : "+f"(d0), "+f"(d1), "+f"(d2), "+f"(d3)
        : "r"(a0), "r"(a1), "r"(a2), "r"(a3), "r"(b0), "r"(b1));
}

// out[b](500x2048) = A1^T Z1[b] + A2^T Z2[b] + Y0[b]
__global__ __launch_bounds__(256) void graph_mma(int layer) {
    __shared__ __align__(16) uint32_t Asp[2][16][136];   // [kp][m] bf16x2 pairs
    __shared__ __align__(16) uint32_t Zsp[2][16][136];   // [kp][n] bf16x2 pairs

    int tid = threadIdx.x;
    int m0 = blockIdx.x * 128;
    int n0 = blockIdx.y * 128;
    int bb = blockIdx.z;
    int lane = tid & 31, wid = tid >> 5;
    int wm = wid & 1, wn = wid >> 1;
    int mbase = wm * 64, nbase = wn * 32;
    int g = lane >> 2, tig = lane & 3;

    int r = tid >> 4;              // kp row 0..15
    int seg = (tid & 15) * 8;      // 8-word segment

    float acc[4][4][4];
#pragma unroll
    for (int i = 0; i < 4; i++)
#pragma unroll
        for (int j = 0; j < 4; j++)
#pragma unroll
            for (int k = 0; k < 4; k++) acc[i][j][k] = 0.f;

    auto load_stage = [&](int st, int buf) {
        int e = st >> 4, s = st & 15;
        int kpg = s * 16 + r;                 // global pair index 0..255
        // A: straight copy (pre-packed, pre-padded)
        const uint4* ap = (const uint4*)&g_Asp[e][kpg][m0 + seg];
        *(uint4*)&Asp[buf][r][seg]     = ap[0];
        *(uint4*)&Asp[buf][r][seg + 4] = ap[1];
        // Z: load two k-rows, interleave-pack
        int v0 = 2 * kpg, v1 = v0 + 1;
        const __nv_bfloat16* zb = e ? g_z2h : g_z1h;
        size_t zoff = (size_t)bb * 1024000 + n0 + seg;
        uint4 lo = make_uint4(0, 0, 0, 0), hi = make_uint4(0, 0, 0, 0);
        if (v0 < 500) lo = *(const uint4*)(zb + zoff + (size_t)v0 * 2048);
        if (v1 < 500) hi = *(const uint4*)(zb + zoff + (size_t)v1 * 2048);
        uint4 o0, o1;
        o0.x = __byte_perm(lo.x, hi.x, 0x5410); o0.y = __byte_perm(lo.x, hi.x, 0x7632);
        o0.z = __byte_perm(lo.y, hi.y, 0x5410); o0.w = __byte_perm(lo.y, hi.y, 0x7632);
        o1.x = __byte_perm(lo.z, hi.z, 0x5410); o1.y = __byte_perm(lo.z, hi.z, 0x7632);
        o1.z = __byte_perm(lo.w, hi.w, 0x5410); o1.w = __byte_perm(lo.w, hi.w, 0x7632);
        *(uint4*)&Zsp[buf][r][seg]     = o0;
        *(uint4*)&Zsp[buf][r][seg + 4] = o1;
    };

    load_stage(0, 0);
    __syncthreads();

    for (int st = 0; st < 32; st++) {
        int cur = st & 1;
        if (st + 1 < 32) load_stage(st + 1, cur ^ 1);
#pragma unroll
        for (int ch = 0; ch < 2; ch++) {
            int k0 = ch * 8;
            uint32_t bfr[4][2];
#pragma unroll
            for (int nt = 0; nt < 4; nt++) {
                bfr[nt][0] = Zsp[cur][k0 + tig][nbase + nt * 8 + g];
                bfr[nt][1] = Zsp[cur][k0 + tig + 4][nbase + nt * 8 + g];
            }
#pragma unroll
            for (int mt = 0; mt < 4; mt++) {
                int mr = mbase + mt * 16 + g;
                uint32_t a0 = Asp[cur][k0 + tig][mr];
                uint32_t a1 = Asp[cur][k0 + tig][mr + 8];
                uint32_t a2 = Asp[cur][k0 + tig + 4][mr];
                uint32_t a3 = Asp[cur][k0 + tig + 4][mr + 8];
#pragma unroll
                for (int nt = 0; nt < 4; nt++)
                    mma_bf16(acc[mt][nt][0], acc[mt][nt][1], acc[mt][nt][2], acc[mt][nt][3],
                             a0, a1, a2, a3, bfr[nt][0], bfr[nt][1]);
            }
        }
        __syncthreads();
    }

    float* hout = g_h[layer];
    size_t bbase = (size_t)bb * 1024000;
#pragma unroll
    for (int mt = 0; mt < 4; mt++) {
#pragma unroll
        for (int nt = 0; nt < 4; nt++) {
            int w0 = m0 + mbase + mt * 16 + g;
            int j = n0 + nbase + nt * 8 + 2 * tig;
            if (w0 < 500) {
                size_t idx = bbase + (size_t)w0 * 2048 + j;
                float2 y = *(const float2*)(g_y0 + idx);
                float2 rres;
                rres.x = acc[mt][nt][0] + y.x;
                rres.y = acc[mt][nt][1] + y.y;
                *(float2*)(hout + idx) = rres;
            }
            if (w0 + 8 < 500) {
                size_t idx = bbase + (size_t)(w0 + 8) * 2048 + j;
                float2 y = *(const float2*)(g_y0 + idx);
                float2 rres;
                rres.x = acc[mt][nt][2] + y.x;
                rres.y = acc[mt][nt][3] + y.y;
                *(float2*)(hout + idx) = rres;
            }
        }
    }
}

// ---------------- attention logits ----------------
__global__ __launch_bounds__(256) void attn_logits(
    const float* __restrict__ x,
    const float* __restrict__ b1, const float* __restrict__ b2,
    const float* __restrict__ w3, const float* __restrict__ b3) {
    __shared__ __align__(16) float vbuf[32][64];
    __shared__ __align__(16) float e1s[64][64];
    __shared__ __align__(16) float red[16][64];
    __shared__ __align__(16) float sw1[32 * 64];
    __shared__ __align__(16) float sw2[64 * 64];
    int tid = threadIdx.x;
    int b = blockIdx.x / 500, n = blockIdx.x % 500;
    int ty = tid >> 4, tx = tid & 15;
    float b3v = b3[0];

    for (int i = tid; i < 512; i += 256) ((float4*)sw1)[i] = ((const float4*)g_w1t)[i];
    for (int i = tid; i < 1024; i += 256) ((float4*)sw2)[i] = ((const float4*)g_w2t)[i];

    for (int l = 0; l < 5; l++) {
        __syncthreads();
        if (l == 0) {
            const float* xb = x + (size_t)b * 1024000 + n * 64;
            for (int i = tid; i < 2048; i += 256) {
                int c = i >> 6, t = i & 63;
                vbuf[c][t] = fmaxf(__ldg(xb + (size_t)c * 32000 + t), 0.f);
            }
        } else {
            const float* hb = g_h[l - 1] + ((size_t)b * 500 + n) * 2048;
            for (int i = tid; i < 2048; i += 256)
                (&vbuf[0][0])[i] = fmaxf(hb[i], 0.f);
        }
        __syncthreads();

        u64 a1p[4][2];
#pragma unroll
        for (int i = 0; i < 4; i++) { a1p[i][0] = 0ull; a1p[i][1] = 0ull; }
#pragma unroll 4
        for (int k = 0; k < 32; k++) {
            float4 w = *(const float4*)&sw1[k * 64 + ty * 4];
            float4 v = *(const float4*)&vbuf[k][tx * 4];
            u64 pv0 = pk2(v.x, v.y), pv1 = pk2(v.z, v.w);
            float wi[4] = { w.x, w.y, w.z, w.w };
#pragma unroll
            for (int i = 0; i < 4; i++) {
                u64 wp = pkb(wi[i]);
                fma2(a1p[i][0], wp, pv0);
                fma2(a1p[i][1], wp, pv1);
            }
        }
#pragma unroll
        for (int i = 0; i < 4; i++) {
            float bb = b1[ty * 4 + i];
            float2 f0 = up2(a1p[i][0]), f1 = up2(a1p[i][1]);
            e1s[ty * 4 + i][tx * 4 + 0] = fmaxf(f0.x + bb, 0.f);
            e1s[ty * 4 + i][tx * 4 + 1] = fmaxf(f0.y + bb, 0.f);
            e1s[ty * 4 + i][tx * 4 + 2] = fmaxf(f1.x + bb, 0.f);
            e1s[ty * 4 + i][tx * 4 + 3] = fmaxf(f1.y + bb, 0.f);
        }
        __syncthreads();

        u64 a2p[4][2];
#pragma unroll
        for (int i = 0; i < 4; i++) { a2p[i][0] = 0ull; a2p[i][1] = 0ull; }
#pragma unroll 4
        for (int k = 0; k < 64; k++) {
            float4 w = *(const float4*)&sw2[k * 64 + ty * 4];
            float4 v = *(const float4*)&e1s[k][tx * 4];
            u64 pv0 = pk2(v.x, v.y), pv1 = pk2(v.z, v.w);
            float wi[4] = { w.x, w.y, w.z, w.w };
#pragma unroll
            for (int i = 0; i < 4; i++) {
                u64 wp = pkb(wi[i]);
                fma2(a2p[i][0], wp, pv0);
                fma2(a2p[i][1], wp, pv1);
            }
        }
        float p[4] = {0.f, 0.f, 0.f, 0.f};
#pragma unroll
        for (int i = 0; i < 4; i++) {
            float bb = b2[ty * 4 + i];
            float wc = w3[ty * 4 + i];
            float2 f0 = up2(a2p[i][0]), f1 = up2(a2p[i][1]);
            p[0] += wc * fmaxf(f0.x + bb, 0.f);
            p[1] += wc * fmaxf(f0.y + bb, 0.f);
            p[2] += wc * fmaxf(f1.x + bb, 0.f);
            p[3] += wc * fmaxf(f1.y + bb, 0.f);
        }
#pragma unroll
        for (int j = 0; j < 4; j++) red[ty][tx * 4 + j] = p[j];
        __syncthreads();
        if (tid < 64) {
            float s = b3v;
#pragma unroll
            for (int q = 0; q < 16; q++) s += red[q][tid];
            g_logits[(((size_t)b * 5 + l) * 500 + n) * 64 + tid] = s;
        }
    }
}

// ---------------- softmax over L+1 and weighted sum ----------------
__global__ __launch_bounds__(256) void attn_out(const float* __restrict__ x, float* __restrict__ out) {
    __shared__ float wts[5][64];
    int tid = threadIdx.x;
    int b = blockIdx.x / 500, n = blockIdx.x % 500;
    if (tid < 64) {
        float lg[5];
        float m = -1e30f;
#pragma unroll
        for (int l = 0; l < 5; l++) {
            lg[l] = g_logits[(((size_t)b * 5 + l) * 500 + n) * 64 + tid];
            m = fmaxf(m, lg[l]);
        }
        float s = 0.f;
#pragma unroll
        for (int l = 0; l < 5; l++) { lg[l] = expf(lg[l] - m); s += lg[l]; }
        float inv = 1.f / s;
#pragma unroll
        for (int l = 0; l < 5; l++) wts[l][tid] = lg[l] * inv;
    }
    __syncthreads();
    size_t hbase = ((size_t)b * 500 + n) * 2048;
    const float* xb = x + (size_t)b * 1024000 + n * 64;
    for (int i = tid; i < 2048; i += 256) {
        int c = i >> 6, t = i & 63;
        float s = wts[0][t] * fmaxf(__ldg(xb + (size_t)c * 32000 + t), 0.f);
        s += wts[1][t] * fmaxf(g_h[0][hbase + i], 0.f);
        s += wts[2][t] * fmaxf(g_h[1][hbase + i], 0.f);
        s += wts[3][t] * fmaxf(g_h[2][hbase + i], 0.f);
        s += wts[4][t] * fmaxf(g_h[3][hbase + i], 0.f);
        out[((size_t)(b * 32 + c) * 500 + n) * 64 + t] = s;
    }
}

// ---------------- launch ----------------
extern "C" void kernel_launch(void* const* d_in, const int* in_sizes, int n_in,
                              void* d_out, int out_size) {
    (void)in_sizes; (void)n_in; (void)out_size;
    const float* x        = (const float*)d_in[0];
    const float* supports = (const float*)d_in[1];
    const float* bn_gamma = (const float*)d_in[2];
    const float* bn_beta  = (const float*)d_in[3];
    const float* res_w    = (const float*)d_in[4];
    const float* res_b    = (const float*)d_in[5];
    const float* aff_w    = (const float*)d_in[6];
    const float* aff_b    = (const float*)d_in[7];
    const float* gate_w   = (const float*)d_in[8];
    const float* gate_b   = (const float*)d_in[9];
    const float* gc_w     = (const float*)d_in[10];
    const float* gc_b     = (const float*)d_in[11];
    const float* attn_w1  = (const float*)d_in[12];
    const float* attn_b1  = (const float*)d_in[13];
    const float* attn_w2  = (const float*)d_in[14];
    const float* attn_b2  = (const float*)d_in[15];
    const float* attn_w3  = (const float*)d_in[16];
    const float* attn_b3  = (const float*)d_in[17];
    float* out = (float*)d_out;

    cudaFuncSetAttribute(st_front, cudaFuncAttributeMaxDynamicSharedMemorySize, 110592);

    prep_weights<<<32, 256>>>(res_w, aff_w, gate_w, gc_w, attn_w1, attn_w2, supports);

    for (int l = 0; l < 4; l++) {
        bn_partial<<<dim3(32, 16), 256>>>(x, l);
        bn_finalize<<<1, 32>>>(bn_gamma + l * 32, bn_beta + l * 32);
        st_front<<<2000, 256, 110592>>>(x, l, res_b + l * 32, aff_b + l * 32,
                                        gate_b + l * 32, gc_b + l * 32);
        graph_mma<<<dim3(4, 16, 16), 256>>>(l);
    }
    attn_logits<<<8000, 256>>>(x, attn_b1, attn_b2, attn_w3, attn_b3);
    attn_out<<<8000, 256>>>(x, out);
}

// round 7
// speedup vs baseline: 2.9806x; 1.1244x over previous
#include <cuda_runtime.h>
#include <cuda_bf16.h>
#include <cstdint>

// ---------------- scratch (static __device__, no allocations) ----------------
// n-major activation layout: [b][n][c*64+t], b-stride 1,024,000
__device__ __align__(16) float g_h[4][16384000];
__device__ __align__(16) float g_y0[16384000];
__device__ __align__(16) __nv_bfloat16 g_z1h[16384000];
__device__ __align__(16) __nv_bfloat16 g_z2h[16384000];
__device__ __align__(16) uint32_t g_Asp[2][256][512];   // bf16x2 k-pair packed A, zero-padded
__device__ __align__(16) float g_logits[16 * 5 * 500 * 64];
__device__ float g_bnsum[32 * 16], g_bnsq[32 * 16];
__device__ float g_bnS[32], g_bnQ[32];                  // fused stats (layers >= 1)
__device__ float g_scale[32], g_shift[32];
// packed transposed weights per layer: [rwt 1024 | awt 3072 | gwt 3072 | gcwt 3072]
__device__ __align__(16) float g_wpack[4][10240];

// ---------------- packed f32x2 helpers ----------------
typedef unsigned long long u64;
__device__ __forceinline__ u64 pk2(float lo, float hi) {
    u64 r; asm("mov.b64 %0,{%1,%2};" : "=l"(r) : "f"(lo), "f"(hi)); return r;
}
__device__ __forceinline__ u64 pkb(float v) { return pk2(v, v); }
__device__ __forceinline__ void fma2(u64& d, u64 a, u64 b) {
    asm("fma.rn.f32x2 %0,%1,%2,%0;" : "+l"(d) : "l"(a), "l"(b));
}
__device__ __forceinline__ float2 up2(u64 v) {
    float2 f; asm("mov.b64 {%0,%1},%2;" : "=f"(f.x), "=f"(f.y) : "l"(v)); return f;
}
__device__ __forceinline__ uint32_t bf16x2_of(float lo, float hi) {
    uint32_t r; asm("cvt.rn.bf16x2.f32 %0,%1,%2;" : "=r"(r) : "f"(hi), "f"(lo)); return r;
}
__device__ __forceinline__ float to_tf32(float x) {
    asm("cvt.rna.tf32.f32 %0, %1;" : "=f"(x) : "f"(x));
    return x;
}
__device__ __forceinline__ uint32_t tf32_bits(float x) { return __float_as_uint(to_tf32(x)); }

// ---------------- weight transposes / packing ----------------
__global__ void prep_weights(const float* __restrict__ rw, const float* __restrict__ aw,
                             const float* __restrict__ gw, const float* __restrict__ gcw,
                             const float* __restrict__ A) {
    int tid = blockIdx.x * blockDim.x + threadIdx.x;
    int nt = gridDim.x * blockDim.x;
    for (int l = 0; l < 4; l++) {
        float* wp = g_wpack[l];
        for (int i = tid; i < 1024; i += nt) {
            int c = i >> 5, o = i & 31;
            wp[c * 32 + o] = rw[l * 1024 + o * 32 + c];
        }
        for (int i = tid; i < 3072; i += nt) {
            int ck = i >> 5, o = i & 31;
            wp[1024 + ck * 32 + o] = aw[l * 3072 + o * 96 + ck];
            wp[4096 + ck * 32 + o] = gw[l * 3072 + o * 96 + ck];
            wp[7168 + ck * 32 + o] = gcw[l * 3072 + o * 96 + ck];
        }
    }
    // pack A supports into bf16x2 k-pairs: g_Asp[e][kp][m] = {A[e][2kp][m], A[e][2kp+1][m]}
    for (int i = tid; i < 2 * 256 * 512; i += nt) {
        int e = i >> 17, kp = (i >> 9) & 255, m = i & 511;
        int v0 = 2 * kp, v1 = v0 + 1;
        float lo = (v0 < 500 && m < 500) ? A[(size_t)e * 250000 + (size_t)v0 * 500 + m] : 0.f;
        float hi = (v1 < 500 && m < 500) ? A[(size_t)e * 250000 + (size_t)v1 * 500 + m] : 0.f;
        g_Asp[e][kp][m] = bf16x2_of(lo, hi);
    }
}

// ---------------- batchnorm stats (layer 0 / input x only) ----------------
__global__ void bn_partial(const float* __restrict__ x) {
    int c = blockIdx.x, b = blockIdx.y;
    float s = 0.f, q = 0.f;
    const float* p = x + (size_t)(b * 32 + c) * 32000;
    for (int i = threadIdx.x; i < 32000; i += 256) {
        float v = __ldg(p + i);
        s += v; q += v * v;
    }
    for (int o = 16; o; o >>= 1) {
        s += __shfl_down_sync(0xffffffffu, s, o);
        q += __shfl_down_sync(0xffffffffu, q, o);
    }
    __shared__ float ss[8], qq[8];
    int w = threadIdx.x >> 5;
    if ((threadIdx.x & 31) == 0) { ss[w] = s; qq[w] = q; }
    __syncthreads();
    if (threadIdx.x == 0) {
        float S = 0.f, Q = 0.f;
        for (int i = 0; i < 8; i++) { S += ss[i]; Q += qq[i]; }
        g_bnsum[c * 16 + b] = S;
        g_bnsq[c * 16 + b] = Q;
    }
}

__global__ void bn_finalize(const float* __restrict__ gamma, const float* __restrict__ beta) {
    int c = threadIdx.x;
    float S = 0.f, Q = 0.f;
    for (int b = 0; b < 16; b++) { S += g_bnsum[c * 16 + b]; Q += g_bnsq[c * 16 + b]; }
    const float inv = 1.0f / 512000.0f;
    float m = S * inv;
    float var = Q * inv - m * m;
    float rstd = rsqrtf(var + 1e-5f);
    float sc = gamma[c] * rstd;
    g_scale[c] = sc;
    g_shift[c] = beta[c] - m * sc;
}

// finalize from fused atomic stats (layers >= 1)
__global__ void bn_finalize2(const float* __restrict__ gamma, const float* __restrict__ beta) {
    int c = threadIdx.x;
    float S = g_bnS[c], Q = g_bnQ[c];
    const float inv = 1.0f / 512000.0f;
    float m = S * inv;
    float var = Q * inv - m * m;
    float rstd = rsqrtf(var + 1e-5f);
    float sc = gamma[c] * rstd;
    g_scale[c] = sc;
    g_shift[c] = beta[c] - m * sc;
}

// ---------------- fused front: bn+relu, res 1x1, causal convs, gate, gc pre-projection ----------------
__global__ __launch_bounds__(256, 2) void st_front(
    const float* __restrict__ x, int layer,
    const float* __restrict__ rb, const float* __restrict__ ab,
    const float* __restrict__ gb, const float* __restrict__ gcb) {
    extern __shared__ float sm[];
    float* sw = sm;             // 10240 weights
    float* xs = sm + 10240;     // 4 x 2048 (raw x; later x1)
    float* ys = sm + 18432;     // 4 x (32*72), index i=t+2

    int tid = threadIdx.x;
    int b = blockIdx.x / 125, n0 = (blockIdx.x % 125) * 4;

    // zero fused-bn accumulators for this layer's graph_mma (stream-ordered)
    if (blockIdx.x == 0 && tid < 32) { g_bnS[tid] = 0.f; g_bnQ[tid] = 0.f; }

    {
        const float4* wp = (const float4*)g_wpack[layer];
        float4* swd = (float4*)sw;
        for (int i = tid; i < 2560; i += 256) swd[i] = wp[i];
    }
    // zero ys pads: cols {0,1} and {66..71} — disjoint from data cols 2..65
    for (int i = tid; i < 1024; i += 256) {
        int nl = i >> 8, r = (i >> 3) & 31, p = i & 7;
        int col = (p < 2) ? p : (p + 64);
        ys[nl * 2304 + r * 72 + col] = 0.f;
    }

    if (layer == 0) {
        const float* xb = x + (size_t)b * 1024000;
        for (int i = tid; i < 8192; i += 256) {
            int nl = i >> 11, idx = i & 2047;
            int c = idx >> 6, t = idx & 63;
            float xv = __ldg(xb + (size_t)c * 32000 + (n0 + nl) * 64 + t);
            xs[nl * 2048 + idx] = xv;
            ys[nl * 2304 + c * 72 + t + 2] = fmaxf(g_scale[c] * xv + g_shift[c], 0.f);
        }
    } else {
        const float* hb = g_h[layer - 1] + ((size_t)b * 500 + n0) * 2048;
        for (int i = tid; i < 8192; i += 256) {
            int nl = i >> 11, idx = i & 2047;
            int c = idx >> 6, t = idx & 63;
            float xv = hb[(size_t)nl * 2048 + idx];
            xs[nl * 2048 + idx] = xv;
            ys[nl * 2304 + c * 72 + t + 2] = fmaxf(g_scale[c] * xv + g_shift[c], 0.f);
        }
    }
    __syncthreads();

    int nl = tid >> 6;
    int wt = tid & 63;
    int og = wt >> 3, tg = wt & 7;
    int o0 = og * 4, t0 = tg * 8;
    const float* xsn = xs + nl * 2048;
    const float* ysn = ys + nl * 2304;
    const float* rs  = sw;
    const float* as_ = sw + 1024;
    const float* gs  = sw + 4096;

    u64 ua[4][4], ug[4][4];
#pragma unroll
    for (int i = 0; i < 4; i++) {
        u64 ba = pkb(ab[o0 + i] + rb[o0 + i]);
        u64 bg = pkb(gb[o0 + i]);
#pragma unroll
        for (int j = 0; j < 4; j++) { ua[i][j] = ba; ug[i][j] = bg; }
    }

#pragma unroll 2
    for (int c = 0; c < 32; c++) {
        float4 wr = *(const float4*)&rs[c * 32 + o0];
        float4 xa = *(const float4*)&xsn[c * 64 + t0];
        float4 xb2 = *(const float4*)&xsn[c * 64 + t0 + 4];
        u64 px[4] = { pk2(xa.x, xa.y), pk2(xa.z, xa.w), pk2(xb2.x, xb2.y), pk2(xb2.z, xb2.w) };
        float wri[4] = { wr.x, wr.y, wr.z, wr.w };
#pragma unroll
        for (int i = 0; i < 4; i++) {
            u64 w2 = pkb(wri[i]);
#pragma unroll
            for (int j = 0; j < 4; j++) fma2(ua[i][j], w2, px[j]);
        }
        float v[12];
        *(float4*)&v[0] = *(const float4*)&ysn[c * 72 + t0];
        *(float4*)&v[4] = *(const float4*)&ysn[c * 72 + t0 + 4];
        *(float4*)&v[8] = *(const float4*)&ysn[c * 72 + t0 + 8];
#pragma unroll
        for (int kk = 0; kk < 3; kk++) {
            u64 pw[4];
#pragma unroll
            for (int j = 0; j < 4; j++) pw[j] = pk2(v[kk + 2 * j], v[kk + 2 * j + 1]);
            float4 wa = *(const float4*)&as_[(c * 3 + kk) * 32 + o0];
            float4 wg = *(const float4*)&gs[(c * 3 + kk) * 32 + o0];
            float wai[4] = { wa.x, wa.y, wa.z, wa.w };
            float wgi[4] = { wg.x, wg.y, wg.z, wg.w };
#pragma unroll
            for (int i = 0; i < 4; i++) {
                u64 a2 = pkb(wai[i]);
                u64 g2 = pkb(wgi[i]);
#pragma unroll
                for (int j = 0; j < 4; j++) { fma2(ua[i][j], a2, pw[j]); fma2(ug[i][j], g2, pw[j]); }
            }
        }
    }

    float x1v[4][8];
#pragma unroll
    for (int i = 0; i < 4; i++)
#pragma unroll
        for (int j = 0; j < 4; j++) {
            float2 a = up2(ua[i][j]);
            float2 g = up2(ug[i][j]);
            x1v[i][2 * j]     = tanhf(a.x) * (1.f / (1.f + expf(-g.x)));
            x1v[i][2 * j + 1] = tanhf(a.y) * (1.f / (1.f + expf(-g.y)));
        }
    __syncthreads();
    float* x1n = xs + nl * 2048;
#pragma unroll
    for (int i = 0; i < 4; i++) {
        *(float4*)&x1n[(o0 + i) * 64 + t0]     = *(float4*)&x1v[i][0];
        *(float4*)&x1n[(o0 + i) * 64 + t0 + 4] = *(float4*)&x1v[i][4];
    }
    __syncthreads();

    const float* cs = sw + 7168;
    float gcbv[4];
#pragma unroll
    for (int i = 0; i < 4; i++) gcbv[i] = gcb[o0 + i];
    size_t obase0 = ((size_t)b * 500 + n0 + nl) * 2048 + t0;

#pragma unroll
    for (int jc = 0; jc < 2; jc++) {
        u64 uy[4][2], uz1[4][2], uz2[4][2];
#pragma unroll
        for (int i = 0; i < 4; i++) {
            u64 by = pkb(gcbv[i]);
            uy[i][0] = by; uy[i][1] = by;
            uz1[i][0] = 0ull; uz1[i][1] = 0ull;
            uz2[i][0] = 0ull; uz2[i][1] = 0ull;
        }
#pragma unroll 2
        for (int c = 0; c < 32; c++) {
            float4 xa = *(const float4*)&x1n[c * 64 + t0 + jc * 4];
            u64 px0 = pk2(xa.x, xa.y), px1 = pk2(xa.z, xa.w);
            float4 w0 = *(const float4*)&cs[c * 32 + o0];
            float4 w1 = *(const float4*)&cs[(32 + c) * 32 + o0];
            float4 w2 = *(const float4*)&cs[(64 + c) * 32 + o0];
            float w0i[4] = { w0.x, w0.y, w0.z, w0.w };
            float w1i[4] = { w1.x, w1.y, w1.z, w1.w };
            float w2i[4] = { w2.x, w2.y, w2.z, w2.w };
#pragma unroll
            for (int i = 0; i < 4; i++) {
                u64 a0 = pkb(w0i[i]), a1 = pkb(w1i[i]), a2 = pkb(w2i[i]);
                fma2(uy[i][0], a0, px0);  fma2(uy[i][1], a0, px1);
                fma2(uz1[i][0], a1, px0); fma2(uz1[i][1], a1, px1);
                fma2(uz2[i][0], a2, px0); fma2(uz2[i][1], a2, px1);
            }
        }
#pragma unroll
        for (int i = 0; i < 4; i++) {
            size_t oidx = obase0 + (size_t)(o0 + i) * 64 + jc * 4;
            float buf[4];
            float2 f;
            f = up2(uy[i][0]);  buf[0] = f.x; buf[1] = f.y;
            f = up2(uy[i][1]);  buf[2] = f.x; buf[3] = f.y;
            *(float4*)(g_y0 + oidx) = *(float4*)buf;
            float2 z0 = up2(uz1[i][0]), z1 = up2(uz1[i][1]);
            uint2 uz;
            uz.x = bf16x2_of(z0.x, z0.y); uz.y = bf16x2_of(z1.x, z1.y);
            *(uint2*)(g_z1h + oidx) = uz;
            z0 = up2(uz2[i][0]); z1 = up2(uz2[i][1]);
            uz.x = bf16x2_of(z0.x, z0.y); uz.y = bf16x2_of(z1.x, z1.y);
            *(uint2*)(g_z2h + oidx) = uz;
        }
    }
}

// ---------------- graph diffusion with bf16 tensor cores ----------------
__device__ __forceinline__ void mma_bf16(float& d0, float& d1, float& d2, float& d3,
                                         uint32_t a0, uint32_t a1, uint32_t a2, uint32_t a3,
                                         uint32_t b0, uint32_t b1) {
    asm volatile(
        "mma.sync.aligned.m16n8k16.row.col.f32.bf16.bf16.f32 "
        "{%0,%1,%2,%3},{%4,%5,%6,%7},{%8,%9},{%0,%1,%2,%3};"
        : "+f"(d0), "+f"(d1), "+f"(d2), "+f"(d3)
        : "r"(a0), "r"(a1), "r"(a2), "r"(a3), "r"(b0), "r"(b1));
}
__device__ __forceinline__ void mma_tf32(float& d0, float& d1, float& d2, float& d3,
                                         uint32_t a0, uint32_t a1, uint32_t a2, uint32_t a3,
                                         uint32_t b0, uint32_t b1) {
    asm volatile(
        "mma.sync.aligned.m16n8k8.row.col.f32.tf32.tf32.f32 "
        "{%0,%1,%2,%3},{%4,%5,%6,%7},{%8,%9},{%0,%1,%2,%3};"
        : "+f"(d0), "+f"(d1), "+f"(d2), "+f"(d3)
        : "r"(a0), "r"(a1), "r"(a2), "r"(a3), "r"(b0), "r"(b1));
}

// out[b](500x2048) = A1^T Z1[b] + A2^T Z2[b] + Y0[b]; also accumulates bn stats of h
__global__ __launch_bounds__(256) void graph_mma(int layer) {
    __shared__ __align__(16) uint32_t Asp[2][16][136];   // [kp][m] bf16x2 pairs
    __shared__ __align__(16) uint32_t Zsp[2][16][136];   // [kp][n] bf16x2 pairs

    int tid = threadIdx.x;
    int m0 = blockIdx.x * 128;
    int n0 = blockIdx.y * 128;
    int bb = blockIdx.z;
    int lane = tid & 31, wid = tid >> 5;
    int wm = wid & 1, wn = wid >> 1;
    int mbase = wm * 64, nbase = wn * 32;
    int g = lane >> 2, tig = lane & 3;

    int r = tid >> 4;              // kp row 0..15
    int seg = (tid & 15) * 8;      // 8-word segment

    float acc[4][4][4];
#pragma unroll
    for (int i = 0; i < 4; i++)
#pragma unroll
        for (int j = 0; j < 4; j++)
#pragma unroll
            for (int k = 0; k < 4; k++) acc[i][j][k] = 0.f;

    auto load_stage = [&](int st, int buf) {
        int e = st >> 4, s = st & 15;
        int kpg = s * 16 + r;                 // global pair index 0..255
        const uint4* ap = (const uint4*)&g_Asp[e][kpg][m0 + seg];
        *(uint4*)&Asp[buf][r][seg]     = ap[0];
        *(uint4*)&Asp[buf][r][seg + 4] = ap[1];
        int v0 = 2 * kpg, v1 = v0 + 1;
        const __nv_bfloat16* zb = e ? g_z2h : g_z1h;
        size_t zoff = (size_t)bb * 1024000 + n0 + seg;
        uint4 lo = make_uint4(0, 0, 0, 0), hi = make_uint4(0, 0, 0, 0);
        if (v0 < 500) lo = *(const uint4*)(zb + zoff + (size_t)v0 * 2048);
        if (v1 < 500) hi = *(const uint4*)(zb + zoff + (size_t)v1 * 2048);
        uint4 o0, o1;
        o0.x = __byte_perm(lo.x, hi.x, 0x5410); o0.y = __byte_perm(lo.x, hi.x, 0x7632);
        o0.z = __byte_perm(lo.y, hi.y, 0x5410); o0.w = __byte_perm(lo.y, hi.y, 0x7632);
        o1.x = __byte_perm(lo.z, hi.z, 0x5410); o1.y = __byte_perm(lo.z, hi.z, 0x7632);
        o1.z = __byte_perm(lo.w, hi.w, 0x5410); o1.w = __byte_perm(lo.w, hi.w, 0x7632);
        *(uint4*)&Zsp[buf][r][seg]     = o0;
        *(uint4*)&Zsp[buf][r][seg + 4] = o1;
    };

    load_stage(0, 0);
    __syncthreads();

    for (int st = 0; st < 32; st++) {
        int cur = st & 1;
        if (st + 1 < 32) load_stage(st + 1, cur ^ 1);
#pragma unroll
        for (int ch = 0; ch < 2; ch++) {
            int k0 = ch * 8;
            uint32_t bfr[4][2];
#pragma unroll
            for (int nt = 0; nt < 4; nt++) {
                bfr[nt][0] = Zsp[cur][k0 + tig][nbase + nt * 8 + g];
                bfr[nt][1] = Zsp[cur][k0 + tig + 4][nbase + nt * 8 + g];
            }
#pragma unroll
            for (int mt = 0; mt < 4; mt++) {
                int mr = mbase + mt * 16 + g;
                uint32_t a0 = Asp[cur][k0 + tig][mr];
                uint32_t a1 = Asp[cur][k0 + tig][mr + 8];
                uint32_t a2 = Asp[cur][k0 + tig + 4][mr];
                uint32_t a3 = Asp[cur][k0 + tig + 4][mr + 8];
#pragma unroll
                for (int nt = 0; nt < 4; nt++)
                    mma_bf16(acc[mt][nt][0], acc[mt][nt][1], acc[mt][nt][2], acc[mt][nt][3],
                             a0, a1, a2, a3, bfr[nt][0], bfr[nt][1]);
            }
        }
        __syncthreads();
    }

    float* hout = g_h[layer];
    size_t bbase = (size_t)bb * 1024000;
    float s = 0.f, q = 0.f;
#pragma unroll
    for (int mt = 0; mt < 4; mt++) {
#pragma unroll
        for (int nt = 0; nt < 4; nt++) {
            int w0 = m0 + mbase + mt * 16 + g;
            int j = n0 + nbase + nt * 8 + 2 * tig;
            if (w0 < 500) {
                size_t idx = bbase + (size_t)w0 * 2048 + j;
                float2 y = *(const float2*)(g_y0 + idx);
                float2 rres;
                rres.x = acc[mt][nt][0] + y.x;
                rres.y = acc[mt][nt][1] + y.y;
                *(float2*)(hout + idx) = rres;
                s += rres.x + rres.y;
                q += rres.x * rres.x + rres.y * rres.y;
            }
            if (w0 + 8 < 500) {
                size_t idx = bbase + (size_t)(w0 + 8) * 2048 + j;
                float2 y = *(const float2*)(g_y0 + idx);
                float2 rres;
                rres.x = acc[mt][nt][2] + y.x;
                rres.y = acc[mt][nt][3] + y.y;
                *(float2*)(hout + idx) = rres;
                s += rres.x + rres.y;
                q += rres.x * rres.x + rres.y * rres.y;
            }
        }
    }
    // fused bn stats: each warp's columns live in one channel (n0+nbase is 32-aligned)
    for (int o = 16; o; o >>= 1) {
        s += __shfl_down_sync(0xffffffffu, s, o);
        q += __shfl_down_sync(0xffffffffu, q, o);
    }
    if (lane == 0) {
        int cw = (n0 + nbase) >> 6;
        atomicAdd(&g_bnS[cw], s);
        atomicAdd(&g_bnQ[cw], q);
    }
}

// ---------------- attention logits via tf32 tensor cores ----------------
// per block: one (b,n). 8 warps = 4 m-tiles x 2 n-halves. W1/W2 fragments in regs across layers.
__global__ __launch_bounds__(256) void attn_logits(
    const float* __restrict__ x,
    const float* __restrict__ w1, const float* __restrict__ b1,
    const float* __restrict__ w2, const float* __restrict__ b2,
    const float* __restrict__ w3, const float* __restrict__ b3) {
    __shared__ __align__(16) float vbuf[32][72];   // relu(h), tf32-rounded
    __shared__ __align__(16) float e1s[64][72];    // relu(e1), tf32-rounded
    __shared__ __align__(16) float red[4][64];

    int tid = threadIdx.x;
    int b = blockIdx.x / 500, n = blockIdx.x % 500;
    int lane = tid & 31, wid = tid >> 5;
    int wm = wid & 3;      // m-tile (d rows [wm*16, +16))
    int wn = wid >> 2;     // n-half (t cols [wn*32, +32))
    int g = lane >> 2, tig = lane & 3;
    float b3v = b3[0];

    // preload A fragments (row-major M x K): W1 [64][32], W2 [64][64]
    uint32_t a1f[4][4], a2f[8][4];
#pragma unroll
    for (int kk = 0; kk < 4; kk++) {
        a1f[kk][0] = tf32_bits(__ldg(w1 + (wm * 16 + g) * 32 + kk * 8 + tig));
        a1f[kk][1] = tf32_bits(__ldg(w1 + (wm * 16 + g + 8) * 32 + kk * 8 + tig));
        a1f[kk][2] = tf32_bits(__ldg(w1 + (wm * 16 + g) * 32 + kk * 8 + tig + 4));
        a1f[kk][3] = tf32_bits(__ldg(w1 + (wm * 16 + g + 8) * 32 + kk * 8 + tig + 4));
    }
#pragma unroll
    for (int kk = 0; kk < 8; kk++) {
        a2f[kk][0] = tf32_bits(__ldg(w2 + (wm * 16 + g) * 64 + kk * 8 + tig));
        a2f[kk][1] = tf32_bits(__ldg(w2 + (wm * 16 + g + 8) * 64 + kk * 8 + tig));
        a2f[kk][2] = tf32_bits(__ldg(w2 + (wm * 16 + g) * 64 + kk * 8 + tig + 4));
        a2f[kk][3] = tf32_bits(__ldg(w2 + (wm * 16 + g + 8) * 64 + kk * 8 + tig + 4));
    }
    float b1r0 = b1[wm * 16 + g], b1r1 = b1[wm * 16 + g + 8];
    float b2r0 = b2[wm * 16 + g], b2r1 = b2[wm * 16 + g + 8];
    float w3r0 = w3[wm * 16 + g], w3r1 = w3[wm * 16 + g + 8];

    for (int l = 0; l < 5; l++) {
        __syncthreads();
        if (l == 0) {
            const float* xb = x + (size_t)b * 1024000 + n * 64;
            for (int i = tid; i < 2048; i += 256) {
                int c = i >> 6, t = i & 63;
                vbuf[c][t] = to_tf32(fmaxf(__ldg(xb + (size_t)c * 32000 + t), 0.f));
            }
        } else {
            const float* hb = g_h[l - 1] + ((size_t)b * 500 + n) * 2048;
            for (int i = tid; i < 2048; i += 256) {
                int c = i >> 6, t = i & 63;
                vbuf[c][t] = to_tf32(fmaxf(hb[i], 0.f));
            }
        }
        __syncthreads();

        // e1 = W1 * V   (M=64 d, N=64 t, K=32 c)
        float c1[4][4];
#pragma unroll
        for (int sub = 0; sub < 4; sub++)
#pragma unroll
            for (int k = 0; k < 4; k++) c1[sub][k] = 0.f;
#pragma unroll
        for (int kk = 0; kk < 4; kk++) {
#pragma unroll
            for (int sub = 0; sub < 4; sub++) {
                uint32_t bb0 = __float_as_uint(vbuf[kk * 8 + tig][wn * 32 + sub * 8 + g]);
                uint32_t bb1 = __float_as_uint(vbuf[kk * 8 + tig + 4][wn * 32 + sub * 8 + g]);
                mma_tf32(c1[sub][0], c1[sub][1], c1[sub][2], c1[sub][3],
                         a1f[kk][0], a1f[kk][1], a1f[kk][2], a1f[kk][3], bb0, bb1);
            }
        }
#pragma unroll
        for (int sub = 0; sub < 4; sub++) {
            int col = wn * 32 + sub * 8 + 2 * tig;
            e1s[wm * 16 + g][col]     = to_tf32(fmaxf(c1[sub][0] + b1r0, 0.f));
            e1s[wm * 16 + g][col + 1] = to_tf32(fmaxf(c1[sub][1] + b1r0, 0.f));
            e1s[wm * 16 + g + 8][col]     = to_tf32(fmaxf(c1[sub][2] + b1r1, 0.f));
            e1s[wm * 16 + g + 8][col + 1] = to_tf32(fmaxf(c1[sub][3] + b1r1, 0.f));
        }
        __syncthreads();

        // e2 = W2 * e1  (K=64)
        float c2[4][4];
#pragma unroll
        for (int sub = 0; sub < 4; sub++)
#pragma unroll
            for (int k = 0; k < 4; k++) c2[sub][k] = 0.f;
#pragma unroll
        for (int kk = 0; kk < 8; kk++) {
#pragma unroll
            for (int sub = 0; sub < 4; sub++) {
                uint32_t bb0 = __float_as_uint(e1s[kk * 8 + tig][wn * 32 + sub * 8 + g]);
                uint32_t bb1 = __float_as_uint(e1s[kk * 8 + tig + 4][wn * 32 + sub * 8 + g]);
                mma_tf32(c2[sub][0], c2[sub][1], c2[sub][2], c2[sub][3],
                         a2f[kk][0], a2f[kk][1], a2f[kk][2], a2f[kk][3], bb0, bb1);
            }
        }
        // e3 partials: sum over this warp's 16 d2-rows with w3 weights
        float p[4][2];
#pragma unroll
        for (int sub = 0; sub < 4; sub++) {
            p[sub][0] = w3r0 * fmaxf(c2[sub][0] + b2r0, 0.f) + w3r1 * fmaxf(c2[sub][2] + b2r1, 0.f);
            p[sub][1] = w3r0 * fmaxf(c2[sub][1] + b2r0, 0.f) + w3r1 * fmaxf(c2[sub][3] + b2r1, 0.f);
        }
        // reduce across g (lane bits 2..4)
#pragma unroll
        for (int off = 4; off <= 16; off <<= 1) {
#pragma unroll
            for (int sub = 0; sub < 4; sub++) {
                p[sub][0] += __shfl_xor_sync(0xffffffffu, p[sub][0], off);
                p[sub][1] += __shfl_xor_sync(0xffffffffu, p[sub][1], off);
            }
        }
        if (g == 0) {
#pragma unroll
            for (int sub = 0; sub < 4; sub++) {
                int col = wn * 32 + sub * 8 + 2 * tig;
                red[wm][col] = p[sub][0];
                red[wm][col + 1] = p[sub][1];
            }
        }
        __syncthreads();
        if (tid < 64) {
            float sv = red[0][tid] + red[1][tid] + red[2][tid] + red[3][tid] + b3v;
            g_logits[(((size_t)b * 5 + l) * 500 + n) * 64 + tid] = sv;
        }
    }
}

// ---------------- softmax over L+1 and weighted sum ----------------
__global__ __launch_bounds__(256) void attn_out(const float* __restrict__ x, float* __restrict__ out) {
    __shared__ float wts[5][64];
    int tid = threadIdx.x;
    int b = blockIdx.x / 500, n = blockIdx.x % 500;
    if (tid < 64) {
        float lg[5];
        float m = -1e30f;
#pragma unroll
        for (int l = 0; l < 5; l++) {
            lg[l] = g_logits[(((size_t)b * 5 + l) * 500 + n) * 64 + tid];
            m = fmaxf(m, lg[l]);
        }
        float s = 0.f;
#pragma unroll
        for (int l = 0; l < 5; l++) { lg[l] = expf(lg[l] - m); s += lg[l]; }
        float inv = 1.f / s;
#pragma unroll
        for (int l = 0; l < 5; l++) wts[l][tid] = lg[l] * inv;
    }
    __syncthreads();
    size_t hbase = ((size_t)b * 500 + n) * 2048;
    const float* xb = x + (size_t)b * 1024000 + n * 64;
    for (int i = tid; i < 2048; i += 256) {
        int c = i >> 6, t = i & 63;
        float s = wts[0][t] * fmaxf(__ldg(xb + (size_t)c * 32000 + t), 0.f);
        s += wts[1][t] * fmaxf(g_h[0][hbase + i], 0.f);
        s += wts[2][t] * fmaxf(g_h[1][hbase + i], 0.f);
        s += wts[3][t] * fmaxf(g_h[2][hbase + i], 0.f);
        s += wts[4][t] * fmaxf(g_h[3][hbase + i], 0.f);
        out[((size_t)(b * 32 + c) * 500 + n) * 64 + t] = s;
    }
}

// ---------------- launch ----------------
extern "C" void kernel_launch(void* const* d_in, const int* in_sizes, int n_in,
                              void* d_out, int out_size) {
    (void)in_sizes; (void)n_in; (void)out_size;
    const float* x        = (const float*)d_in[0];
    const float* supports = (const float*)d_in[1];
    const float* bn_gamma = (const float*)d_in[2];
    const float* bn_beta  = (const float*)d_in[3];
    const float* res_w    = (const float*)d_in[4];
    const float* res_b    = (const float*)d_in[5];
    const float* aff_w    = (const float*)d_in[6];
    const float* aff_b    = (const float*)d_in[7];
    const float* gate_w   = (const float*)d_in[8];
    const float* gate_b   = (const float*)d_in[9];
    const float* gc_w     = (const float*)d_in[10];
    const float* gc_b     = (const float*)d_in[11];
    const float* attn_w1  = (const float*)d_in[12];
    const float* attn_b1  = (const float*)d_in[13];
    const float* attn_w2  = (const float*)d_in[14];
    const float* attn_b2  = (const float*)d_in[15];
    const float* attn_w3  = (const float*)d_in[16];
    const float* attn_b3  = (const float*)d_in[17];
    float* out = (float*)d_out;

    cudaFuncSetAttribute(st_front, cudaFuncAttributeMaxDynamicSharedMemorySize, 110592);

    prep_weights<<<32, 256>>>(res_w, aff_w, gate_w, gc_w, supports);

    for (int l = 0; l < 4; l++) {
        if (l == 0) {
            bn_partial<<<dim3(32, 16), 256>>>(x);
            bn_finalize<<<1, 32>>>(bn_gamma, bn_beta);
        } else {
            bn_finalize2<<<1, 32>>>(bn_gamma + l * 32, bn_beta + l * 32);
        }
        st_front<<<2000, 256, 110592>>>(x, l, res_b + l * 32, aff_b + l * 32,
                                        gate_b + l * 32, gc_b + l * 32);
        graph_mma<<<dim3(4, 16, 16), 256>>>(l);
    }
    attn_logits<<<8000, 256>>>(x, attn_w1, attn_b1, attn_w2, attn_b2, attn_w3, attn_b3);
    attn_out<<<8000, 256>>>(x, out);
}

// round 8
// speedup vs baseline: 3.7609x; 1.2618x over previous
#include <cuda_runtime.h>
#include <cuda_bf16.h>
#include <cstdint>

// ---------------- scratch (static __device__, no allocations) ----------------
// n-major activation layout: [b][n][c*64+t], b-stride 1,024,000
__device__ __align__(16) float g_h[4][16384000];
__device__ __align__(16) float g_y0[16384000];
__device__ __align__(16) __nv_bfloat16 g_z1h[16384000];
__device__ __align__(16) __nv_bfloat16 g_z2h[16384000];
__device__ __align__(16) uint32_t g_Asp[2][256][512];   // bf16x2 k-pair packed A, zero-padded
__device__ __align__(16) float g_logits[16 * 5 * 500 * 64];
__device__ float g_bnsum[32 * 16], g_bnsq[32 * 16];
__device__ float g_bnS[32], g_bnQ[32];                  // fused stats (layers >= 1)
__device__ float g_scale[32], g_shift[32];
// fragment-packed tf32 weights for st_front MMA
__device__ __align__(16) uint32_t g_w1f[4][4][16][128]; // [l][mt][kc][lane*4+reg]
__device__ __align__(16) uint32_t g_w2f[4][12][4][64];  // [l][nsub][kc][lane*2+reg]

// ---------------- helpers ----------------
__device__ __forceinline__ uint32_t bf16x2_of(float lo, float hi) {
    uint32_t r; asm("cvt.rn.bf16x2.f32 %0,%1,%2;" : "=r"(r) : "f"(hi), "f"(lo)); return r;
}
__device__ __forceinline__ float to_tf32(float x) {
    asm("cvt.rna.tf32.f32 %0, %1;" : "=f"(x) : "f"(x));
    return x;
}
__device__ __forceinline__ uint32_t tf32_bits(float x) { return __float_as_uint(to_tf32(x)); }

__device__ __forceinline__ void mma_bf16(float& d0, float& d1, float& d2, float& d3,
                                         uint32_t a0, uint32_t a1, uint32_t a2, uint32_t a3,
                                         uint32_t b0, uint32_t b1) {
    asm volatile(
        "mma.sync.aligned.m16n8k16.row.col.f32.bf16.bf16.f32 "
        "{%0,%1,%2,%3},{%4,%5,%6,%7},{%8,%9},{%0,%1,%2,%3};"
        : "+f"(d0), "+f"(d1), "+f"(d2), "+f"(d3)
        : "r"(a0), "r"(a1), "r"(a2), "r"(a3), "r"(b0), "r"(b1));
}
__device__ __forceinline__ void mma_tf32(float& d0, float& d1, float& d2, float& d3,
                                         uint32_t a0, uint32_t a1, uint32_t a2, uint32_t a3,
                                         uint32_t b0, uint32_t b1) {
    asm volatile(
        "mma.sync.aligned.m16n8k8.row.col.f32.tf32.tf32.f32 "
        "{%0,%1,%2,%3},{%4,%5,%6,%7},{%8,%9},{%0,%1,%2,%3};"
        : "+f"(d0), "+f"(d1), "+f"(d2), "+f"(d3)
        : "r"(a0), "r"(a1), "r"(a2), "r"(a3), "r"(b0), "r"(b1));
}

// ---------------- weight packing ----------------
__global__ void prep_weights(const float* __restrict__ rw, const float* __restrict__ aw,
                             const float* __restrict__ gw, const float* __restrict__ gcw,
                             const float* __restrict__ A) {
    int tid = blockIdx.x * blockDim.x + threadIdx.x;
    int nt = gridDim.x * blockDim.x;

    // GEMM1 fragments: A' rows: tile mt, local row lr<8 -> aff o=mt*8+lr; lr>=8 -> gate o=mt*8+lr-8
    // k<96: conv weight (c=k/3, kk=k%3); k>=96: res weight (aff) / 0 (gate)
    for (int i = tid; i < 4 * 4 * 16 * 32; i += nt) {
        int l = i >> 11;
        int r = i & 2047;
        int mt = r >> 9;
        int r2 = r & 511;
        int kc = r2 >> 5;
        int lane = r2 & 31;
        int g = lane >> 2, tg = lane & 3;
        int o = mt * 8 + g;
        uint32_t* dst = &g_w1f[l][mt][kc][lane * 4];
#pragma unroll
        for (int half = 0; half < 2; half++) {
            int k = kc * 8 + tg + half * 4;
            float va, vg;
            if (k < 96) {
                va = aw[l * 3072 + o * 96 + k];
                vg = gw[l * 3072 + o * 96 + k];
            } else {
                va = rw[l * 1024 + o * 32 + (k - 96)];
                vg = 0.f;
            }
            dst[half * 2 + 0] = tf32_bits(va);
            dst[half * 2 + 1] = tf32_bits(vg);
        }
    }
    // GEMM2 fragments (B = W2^T): rows o'<32 -> y0 (gcw[o][0:32]); 32..63 -> z1; 64..95 -> z2
    for (int i = tid; i < 4 * 12 * 4 * 32; i += nt) {
        int l = i / 1536;
        int r = i % 1536;
        int nsub = r / 128;
        int r2 = r % 128;
        int kc = r2 >> 5;
        int lane = r2 & 31;
        int g = lane >> 2, tg = lane & 3;
        int o = nsub * 8 + g;
        int grp = o >> 5, oo = o & 31;
        uint32_t* dst = &g_w2f[l][nsub][kc][lane * 2];
        dst[0] = tf32_bits(gcw[l * 3072 + oo * 96 + grp * 32 + kc * 8 + tg]);
        dst[1] = tf32_bits(gcw[l * 3072 + oo * 96 + grp * 32 + kc * 8 + tg + 4]);
    }
    // pack A supports into bf16x2 k-pairs
    for (int i = tid; i < 2 * 256 * 512; i += nt) {
        int e = i >> 17, kp = (i >> 9) & 255, m = i & 511;
        int v0 = 2 * kp, v1 = v0 + 1;
        float lo = (v0 < 500 && m < 500) ? A[(size_t)e * 250000 + (size_t)v0 * 500 + m] : 0.f;
        float hi = (v1 < 500 && m < 500) ? A[(size_t)e * 250000 + (size_t)v1 * 500 + m] : 0.f;
        g_Asp[e][kp][m] = bf16x2_of(lo, hi);
    }
}

// ---------------- batchnorm stats (input x only) ----------------
__global__ void bn_partial(const float* __restrict__ x) {
    int c = blockIdx.x, b = blockIdx.y;
    float s = 0.f, q = 0.f;
    const float* p = x + (size_t)(b * 32 + c) * 32000;
    for (int i = threadIdx.x; i < 32000; i += 256) {
        float v = __ldg(p + i);
        s += v; q += v * v;
    }
    for (int o = 16; o; o >>= 1) {
        s += __shfl_down_sync(0xffffffffu, s, o);
        q += __shfl_down_sync(0xffffffffu, q, o);
    }
    __shared__ float ss[8], qq[8];
    int w = threadIdx.x >> 5;
    if ((threadIdx.x & 31) == 0) { ss[w] = s; qq[w] = q; }
    __syncthreads();
    if (threadIdx.x == 0) {
        float S = 0.f, Q = 0.f;
        for (int i = 0; i < 8; i++) { S += ss[i]; Q += qq[i]; }
        g_bnsum[c * 16 + b] = S;
        g_bnsq[c * 16 + b] = Q;
    }
}

__global__ void bn_finalize(const float* __restrict__ gamma, const float* __restrict__ beta) {
    int c = threadIdx.x;
    float S = 0.f, Q = 0.f;
    for (int b = 0; b < 16; b++) { S += g_bnsum[c * 16 + b]; Q += g_bnsq[c * 16 + b]; }
    const float inv = 1.0f / 512000.0f;
    float m = S * inv;
    float var = Q * inv - m * m;
    float rstd = rsqrtf(var + 1e-5f);
    float sc = gamma[c] * rstd;
    g_scale[c] = sc;
    g_shift[c] = beta[c] - m * sc;
}

__global__ void bn_finalize2(const float* __restrict__ gamma, const float* __restrict__ beta) {
    int c = threadIdx.x;
    float S = g_bnS[c], Q = g_bnQ[c];
    const float inv = 1.0f / 512000.0f;
    float m = S * inv;
    float var = Q * inv - m * m;
    float rstd = rsqrtf(var + 1e-5f);
    float sc = gamma[c] * rstd;
    g_scale[c] = sc;
    g_shift[c] = beta[c] - m * sc;
}

// ---------------- st_front via tf32 tensor cores ----------------
// one (b,n) per block, 256 threads = 8 warps.
// GEMM1: e[64 out][64 t] = W1'[64][128] * B1[128][64]; rows interleaved aff/gate per m-tile.
// GEMM2: C[64 t][96 out] = x1T[64][32] * W2T[32][96]  (y0|z1|z2 stacked).
__global__ __launch_bounds__(256) void st_front(
    const float* __restrict__ x, int layer,
    const float* __restrict__ rb, const float* __restrict__ ab,
    const float* __restrict__ gb, const float* __restrict__ gcb) {
    __shared__ __align__(16) float B1[128][72];   // K x t (conv windows + raw x)
    __shared__ __align__(16) float x1T[64][36];   // t x c

    int tid = threadIdx.x;
    int b = blockIdx.x / 500, n = blockIdx.x % 500;

    if (blockIdx.x == 0 && tid < 32) { g_bnS[tid] = 0.f; g_bnQ[tid] = 0.f; }

    // zero causal left-edge of conv windows
    if (tid < 96) {
        int c = tid / 3, w = tid % 3;
        if (w == 0) B1[3 * c][0] = 0.f;
        else if (w == 1) B1[3 * c][1] = 0.f;
        else B1[3 * c + 1][0] = 0.f;
    }

    // load activations; build conv-window rows (bn+relu, tf32) + raw-x rows (tf32)
    if (layer == 0) {
        const float* xb = x + (size_t)b * 1024000 + n * 64;
        for (int i = tid; i < 2048; i += 256) {
            int c = i >> 6, t = i & 63;
            float xv = __ldg(xb + (size_t)c * 32000 + t);
            float y = to_tf32(fmaxf(g_scale[c] * xv + g_shift[c], 0.f));
            B1[96 + c][t] = to_tf32(xv);
            B1[3 * c + 2][t] = y;
            B1[3 * c + 1][t + 1] = y;
            B1[3 * c][t + 2] = y;
        }
    } else {
        const float* hb = g_h[layer - 1] + ((size_t)b * 500 + n) * 2048;
        for (int i = tid; i < 2048; i += 256) {
            int c = i >> 6, t = i & 63;
            float xv = hb[i];
            float y = to_tf32(fmaxf(g_scale[c] * xv + g_shift[c], 0.f));
            B1[96 + c][t] = to_tf32(xv);
            B1[3 * c + 2][t] = y;
            B1[3 * c + 1][t + 1] = y;
            B1[3 * c][t + 2] = y;
        }
    }
    __syncthreads();

    int lane = tid & 31, wid = tid >> 5;
    int g = lane >> 2, tig = lane & 3;
    int wm = wid & 3, wn = wid >> 2;
    int nbase = wn * 32;

    // ---- GEMM1 ----
    float c1[4][4];
#pragma unroll
    for (int s = 0; s < 4; s++)
#pragma unroll
        for (int k = 0; k < 4; k++) c1[s][k] = 0.f;

#pragma unroll 4
    for (int kc = 0; kc < 16; kc++) {
        uint4 af = __ldg((const uint4*)&g_w1f[layer][wm][kc][lane * 4]);
#pragma unroll
        for (int s = 0; s < 4; s++) {
            int col = nbase + s * 8 + g;
            uint32_t b0 = __float_as_uint(B1[kc * 8 + tig][col]);
            uint32_t b1 = __float_as_uint(B1[kc * 8 + tig + 4][col]);
            mma_tf32(c1[s][0], c1[s][1], c1[s][2], c1[s][3],
                     af.x, af.y, af.z, af.w, b0, b1);
        }
    }

    // ---- x1 = tanh(aff+res+b) * sigmoid(gate+b); rows g=aff, g+8=gate of same o ----
    {
        int o = wm * 8 + g;
        float abrb = __ldg(ab + o) + __ldg(rb + o);
        float gbv = __ldg(gb + o);
#pragma unroll
        for (int s = 0; s < 4; s++) {
            int col = nbase + s * 8 + 2 * tig;
            float v0 = tanhf(c1[s][0] + abrb) * (1.f / (1.f + expf(-(c1[s][2] + gbv))));
            float v1 = tanhf(c1[s][1] + abrb) * (1.f / (1.f + expf(-(c1[s][3] + gbv))));
            x1T[col][o] = to_tf32(v0);
            x1T[col + 1][o] = to_tf32(v1);
        }
    }
    __syncthreads();

    // ---- GEMM2: C[t][o'] = x1T * W2T ----
    float c2[6][4];
#pragma unroll
    for (int s = 0; s < 6; s++)
#pragma unroll
        for (int k = 0; k < 4; k++) c2[s][k] = 0.f;

    int tm = wm * 16;
#pragma unroll
    for (int kc = 0; kc < 4; kc++) {
        uint32_t a0 = __float_as_uint(x1T[tm + g][kc * 8 + tig]);
        uint32_t a1 = __float_as_uint(x1T[tm + g + 8][kc * 8 + tig]);
        uint32_t a2 = __float_as_uint(x1T[tm + g][kc * 8 + tig + 4]);
        uint32_t a3 = __float_as_uint(x1T[tm + g + 8][kc * 8 + tig + 4]);
#pragma unroll
        for (int s = 0; s < 6; s++) {
            int nsub = wn * 6 + s;
            uint2 bf = __ldg((const uint2*)&g_w2f[layer][nsub][kc][lane * 2]);
            mma_tf32(c2[s][0], c2[s][1], c2[s][2], c2[s][3],
                     a0, a1, a2, a3, bf.x, bf.y);
        }
    }

    // ---- epilogue: y0 (fp32+bias) / z1,z2 (bf16) ----
    size_t obase = ((size_t)b * 500 + n) * 2048;
    int t0 = tm + g;
#pragma unroll
    for (int s = 0; s < 6; s++) {
        int nsub = wn * 6 + s;
        int o0 = nsub * 8 + 2 * tig;
        if (o0 < 32) {
            float bz0 = __ldg(gcb + o0), bz1 = __ldg(gcb + o0 + 1);
            g_y0[obase + (size_t)o0 * 64 + t0] = c2[s][0] + bz0;
            g_y0[obase + (size_t)(o0 + 1) * 64 + t0] = c2[s][1] + bz1;
            g_y0[obase + (size_t)o0 * 64 + t0 + 8] = c2[s][2] + bz0;
            g_y0[obase + (size_t)(o0 + 1) * 64 + t0 + 8] = c2[s][3] + bz1;
        } else if (o0 < 64) {
            int oz = o0 - 32;
            g_z1h[obase + (size_t)oz * 64 + t0] = __float2bfloat16(c2[s][0]);
            g_z1h[obase + (size_t)(oz + 1) * 64 + t0] = __float2bfloat16(c2[s][1]);
            g_z1h[obase + (size_t)oz * 64 + t0 + 8] = __float2bfloat16(c2[s][2]);
            g_z1h[obase + (size_t)(oz + 1) * 64 + t0 + 8] = __float2bfloat16(c2[s][3]);
        } else {
            int oz = o0 - 64;
            g_z2h[obase + (size_t)oz * 64 + t0] = __float2bfloat16(c2[s][0]);
            g_z2h[obase + (size_t)(oz + 1) * 64 + t0] = __float2bfloat16(c2[s][1]);
            g_z2h[obase + (size_t)oz * 64 + t0 + 8] = __float2bfloat16(c2[s][2]);
            g_z2h[obase + (size_t)(oz + 1) * 64 + t0 + 8] = __float2bfloat16(c2[s][3]);
        }
    }
}

// ---------------- graph diffusion with bf16 tensor cores ----------------
__global__ __launch_bounds__(256) void graph_mma(int layer) {
    __shared__ __align__(16) uint32_t Asp[2][16][136];
    __shared__ __align__(16) uint32_t Zsp[2][16][136];

    int tid = threadIdx.x;
    int m0 = blockIdx.x * 128;
    int n0 = blockIdx.y * 128;
    int bb = blockIdx.z;
    int lane = tid & 31, wid = tid >> 5;
    int wm = wid & 1, wn = wid >> 1;
    int mbase = wm * 64, nbase = wn * 32;
    int g = lane >> 2, tig = lane & 3;

    int r = tid >> 4;
    int seg = (tid & 15) * 8;

    float acc[4][4][4];
#pragma unroll
    for (int i = 0; i < 4; i++)
#pragma unroll
        for (int j = 0; j < 4; j++)
#pragma unroll
            for (int k = 0; k < 4; k++) acc[i][j][k] = 0.f;

    auto load_stage = [&](int st, int buf) {
        int e = st >> 4, s = st & 15;
        int kpg = s * 16 + r;
        const uint4* ap = (const uint4*)&g_Asp[e][kpg][m0 + seg];
        *(uint4*)&Asp[buf][r][seg]     = ap[0];
        *(uint4*)&Asp[buf][r][seg + 4] = ap[1];
        int v0 = 2 * kpg, v1 = v0 + 1;
        const __nv_bfloat16* zb = e ? g_z2h : g_z1h;
        size_t zoff = (size_t)bb * 1024000 + n0 + seg;
        uint4 lo = make_uint4(0, 0, 0, 0), hi = make_uint4(0, 0, 0, 0);
        if (v0 < 500) lo = *(const uint4*)(zb + zoff + (size_t)v0 * 2048);
        if (v1 < 500) hi = *(const uint4*)(zb + zoff + (size_t)v1 * 2048);
        uint4 o0, o1;
        o0.x = __byte_perm(lo.x, hi.x, 0x5410); o0.y = __byte_perm(lo.x, hi.x, 0x7632);
        o0.z = __byte_perm(lo.y, hi.y, 0x5410); o0.w = __byte_perm(lo.y, hi.y, 0x7632);
        o1.x = __byte_perm(lo.z, hi.z, 0x5410); o1.y = __byte_perm(lo.z, hi.z, 0x7632);
        o1.z = __byte_perm(lo.w, hi.w, 0x5410); o1.w = __byte_perm(lo.w, hi.w, 0x7632);
        *(uint4*)&Zsp[buf][r][seg]     = o0;
        *(uint4*)&Zsp[buf][r][seg + 4] = o1;
    };

    load_stage(0, 0);
    __syncthreads();

    for (int st = 0; st < 32; st++) {
        int cur = st & 1;
        if (st + 1 < 32) load_stage(st + 1, cur ^ 1);
#pragma unroll
        for (int ch = 0; ch < 2; ch++) {
            int k0 = ch * 8;
            uint32_t bfr[4][2];
#pragma unroll
            for (int nt = 0; nt < 4; nt++) {
                bfr[nt][0] = Zsp[cur][k0 + tig][nbase + nt * 8 + g];
                bfr[nt][1] = Zsp[cur][k0 + tig + 4][nbase + nt * 8 + g];
            }
#pragma unroll
            for (int mt = 0; mt < 4; mt++) {
                int mr = mbase + mt * 16 + g;
                uint32_t a0 = Asp[cur][k0 + tig][mr];
                uint32_t a1 = Asp[cur][k0 + tig][mr + 8];
                uint32_t a2 = Asp[cur][k0 + tig + 4][mr];
                uint32_t a3 = Asp[cur][k0 + tig + 4][mr + 8];
#pragma unroll
                for (int nt = 0; nt < 4; nt++)
                    mma_bf16(acc[mt][nt][0], acc[mt][nt][1], acc[mt][nt][2], acc[mt][nt][3],
                             a0, a1, a2, a3, bfr[nt][0], bfr[nt][1]);
            }
        }
        __syncthreads();
    }

    float* hout = g_h[layer];
    size_t bbase = (size_t)bb * 1024000;
    float s = 0.f, q = 0.f;
#pragma unroll
    for (int mt = 0; mt < 4; mt++) {
#pragma unroll
        for (int nt = 0; nt < 4; nt++) {
            int w0 = m0 + mbase + mt * 16 + g;
            int j = n0 + nbase + nt * 8 + 2 * tig;
            if (w0 < 500) {
                size_t idx = bbase + (size_t)w0 * 2048 + j;
                float2 y = *(const float2*)(g_y0 + idx);
                float2 rres;
                rres.x = acc[mt][nt][0] + y.x;
                rres.y = acc[mt][nt][1] + y.y;
                *(float2*)(hout + idx) = rres;
                s += rres.x + rres.y;
                q += rres.x * rres.x + rres.y * rres.y;
            }
            if (w0 + 8 < 500) {
                size_t idx = bbase + (size_t)(w0 + 8) * 2048 + j;
                float2 y = *(const float2*)(g_y0 + idx);
                float2 rres;
                rres.x = acc[mt][nt][2] + y.x;
                rres.y = acc[mt][nt][3] + y.y;
                *(float2*)(hout + idx) = rres;
                s += rres.x + rres.y;
                q += rres.x * rres.x + rres.y * rres.y;
            }
        }
    }
    for (int o = 16; o; o >>= 1) {
        s += __shfl_down_sync(0xffffffffu, s, o);
        q += __shfl_down_sync(0xffffffffu, q, o);
    }
    if (lane == 0) {
        int cw = (n0 + nbase) >> 6;
        atomicAdd(&g_bnS[cw], s);
        atomicAdd(&g_bnQ[cw], q);
    }
}

// ---------------- attention logits via tf32 tensor cores ----------------
__global__ __launch_bounds__(256) void attn_logits(
    const float* __restrict__ x,
    const float* __restrict__ w1, const float* __restrict__ b1,
    const float* __restrict__ w2, const float* __restrict__ b2,
    const float* __restrict__ w3, const float* __restrict__ b3) {
    __shared__ __align__(16) float vbuf[32][72];
    __shared__ __align__(16) float e1s[64][72];
    __shared__ __align__(16) float red[4][64];

    int tid = threadIdx.x;
    int b = blockIdx.x / 500, n = blockIdx.x % 500;
    int lane = tid & 31, wid = tid >> 5;
    int wm = wid & 3;
    int wn = wid >> 2;
    int g = lane >> 2, tig = lane & 3;
    float b3v = b3[0];

    uint32_t a1f[4][4], a2f[8][4];
#pragma unroll
    for (int kk = 0; kk < 4; kk++) {
        a1f[kk][0] = tf32_bits(__ldg(w1 + (wm * 16 + g) * 32 + kk * 8 + tig));
        a1f[kk][1] = tf32_bits(__ldg(w1 + (wm * 16 + g + 8) * 32 + kk * 8 + tig));
        a1f[kk][2] = tf32_bits(__ldg(w1 + (wm * 16 + g) * 32 + kk * 8 + tig + 4));
        a1f[kk][3] = tf32_bits(__ldg(w1 + (wm * 16 + g + 8) * 32 + kk * 8 + tig + 4));
    }
#pragma unroll
    for (int kk = 0; kk < 8; kk++) {
        a2f[kk][0] = tf32_bits(__ldg(w2 + (wm * 16 + g) * 64 + kk * 8 + tig));
        a2f[kk][1] = tf32_bits(__ldg(w2 + (wm * 16 + g + 8) * 64 + kk * 8 + tig));
        a2f[kk][2] = tf32_bits(__ldg(w2 + (wm * 16 + g) * 64 + kk * 8 + tig + 4));
        a2f[kk][3] = tf32_bits(__ldg(w2 + (wm * 16 + g + 8) * 64 + kk * 8 + tig + 4));
    }
    float b1r0 = b1[wm * 16 + g], b1r1 = b1[wm * 16 + g + 8];
    float b2r0 = b2[wm * 16 + g], b2r1 = b2[wm * 16 + g + 8];
    float w3r0 = w3[wm * 16 + g], w3r1 = w3[wm * 16 + g + 8];

    for (int l = 0; l < 5; l++) {
        __syncthreads();
        if (l == 0) {
            const float* xb = x + (size_t)b * 1024000 + n * 64;
            for (int i = tid; i < 2048; i += 256) {
                int c = i >> 6, t = i & 63;
                vbuf[c][t] = to_tf32(fmaxf(__ldg(xb + (size_t)c * 32000 + t), 0.f));
            }
        } else {
            const float* hb = g_h[l - 1] + ((size_t)b * 500 + n) * 2048;
            for (int i = tid; i < 2048; i += 256) {
                int c = i >> 6, t = i & 63;
                vbuf[c][t] = to_tf32(fmaxf(hb[i], 0.f));
            }
        }
        __syncthreads();

        float c1[4][4];
#pragma unroll
        for (int sub = 0; sub < 4; sub++)
#pragma unroll
            for (int k = 0; k < 4; k++) c1[sub][k] = 0.f;
#pragma unroll
        for (int kk = 0; kk < 4; kk++) {
#pragma unroll
            for (int sub = 0; sub < 4; sub++) {
                uint32_t bb0 = __float_as_uint(vbuf[kk * 8 + tig][wn * 32 + sub * 8 + g]);
                uint32_t bb1 = __float_as_uint(vbuf[kk * 8 + tig + 4][wn * 32 + sub * 8 + g]);
                mma_tf32(c1[sub][0], c1[sub][1], c1[sub][2], c1[sub][3],
                         a1f[kk][0], a1f[kk][1], a1f[kk][2], a1f[kk][3], bb0, bb1);
            }
        }
#pragma unroll
        for (int sub = 0; sub < 4; sub++) {
            int col = wn * 32 + sub * 8 + 2 * tig;
            e1s[wm * 16 + g][col]     = to_tf32(fmaxf(c1[sub][0] + b1r0, 0.f));
            e1s[wm * 16 + g][col + 1] = to_tf32(fmaxf(c1[sub][1] + b1r0, 0.f));
            e1s[wm * 16 + g + 8][col]     = to_tf32(fmaxf(c1[sub][2] + b1r1, 0.f));
            e1s[wm * 16 + g + 8][col + 1] = to_tf32(fmaxf(c1[sub][3] + b1r1, 0.f));
        }
        __syncthreads();

        float c2[4][4];
#pragma unroll
        for (int sub = 0; sub < 4; sub++)
#pragma unroll
            for (int k = 0; k < 4; k++) c2[sub][k] = 0.f;
#pragma unroll
        for (int kk = 0; kk < 8; kk++) {
#pragma unroll
            for (int sub = 0; sub < 4; sub++) {
                uint32_t bb0 = __float_as_uint(e1s[kk * 8 + tig][wn * 32 + sub * 8 + g]);
                uint32_t bb1 = __float_as_uint(e1s[kk * 8 + tig + 4][wn * 32 + sub * 8 + g]);
                mma_tf32(c2[sub][0], c2[sub][1], c2[sub][2], c2[sub][3],
                         a2f[kk][0], a2f[kk][1], a2f[kk][2], a2f[kk][3], bb0, bb1);
            }
        }
        float p[4][2];
#pragma unroll
        for (int sub = 0; sub < 4; sub++) {
            p[sub][0] = w3r0 * fmaxf(c2[sub][0] + b2r0, 0.f) + w3r1 * fmaxf(c2[sub][2] + b2r1, 0.f);
            p[sub][1] = w3r0 * fmaxf(c2[sub][1] + b2r0, 0.f) + w3r1 * fmaxf(c2[sub][3] + b2r1, 0.f);
        }
#pragma unroll
        for (int off = 4; off <= 16; off <<= 1) {
#pragma unroll
            for (int sub = 0; sub < 4; sub++) {
                p[sub][0] += __shfl_xor_sync(0xffffffffu, p[sub][0], off);
                p[sub][1] += __shfl_xor_sync(0xffffffffu, p[sub][1], off);
            }
        }
        if (g == 0) {
#pragma unroll
            for (int sub = 0; sub < 4; sub++) {
                int col = wn * 32 + sub * 8 + 2 * tig;
                red[wm][col] = p[sub][0];
                red[wm][col + 1] = p[sub][1];
            }
        }
        __syncthreads();
        if (tid < 64) {
            float sv = red[0][tid] + red[1][tid] + red[2][tid] + red[3][tid] + b3v;
            g_logits[(((size_t)b * 5 + l) * 500 + n) * 64 + tid] = sv;
        }
    }
}

// ---------------- softmax over L+1 and weighted sum ----------------
__global__ __launch_bounds__(256) void attn_out(const float* __restrict__ x, float* __restrict__ out) {
    __shared__ float wts[5][64];
    int tid = threadIdx.x;
    int b = blockIdx.x / 500, n = blockIdx.x % 500;
    if (tid < 64) {
        float lg[5];
        float m = -1e30f;
#pragma unroll
        for (int l = 0; l < 5; l++) {
            lg[l] = g_logits[(((size_t)b * 5 + l) * 500 + n) * 64 + tid];
            m = fmaxf(m, lg[l]);
        }
        float s = 0.f;
#pragma unroll
        for (int l = 0; l < 5; l++) { lg[l] = expf(lg[l] - m); s += lg[l]; }
        float inv = 1.f / s;
#pragma unroll
        for (int l = 0; l < 5; l++) wts[l][tid] = lg[l] * inv;
    }
    __syncthreads();
    size_t hbase = ((size_t)b * 500 + n) * 2048;
    const float* xb = x + (size_t)b * 1024000 + n * 64;
    for (int i = tid; i < 2048; i += 256) {
        int c = i >> 6, t = i & 63;
        float s = wts[0][t] * fmaxf(__ldg(xb + (size_t)c * 32000 + t), 0.f);
        s += wts[1][t] * fmaxf(g_h[0][hbase + i], 0.f);
        s += wts[2][t] * fmaxf(g_h[1][hbase + i], 0.f);
        s += wts[3][t] * fmaxf(g_h[2][hbase + i], 0.f);
        s += wts[4][t] * fmaxf(g_h[3][hbase + i], 0.f);
        out[((size_t)(b * 32 + c) * 500 + n) * 64 + t] = s;
    }
}

// ---------------- launch ----------------
extern "C" void kernel_launch(void* const* d_in, const int* in_sizes, int n_in,
                              void* d_out, int out_size) {
    (void)in_sizes; (void)n_in; (void)out_size;
    const float* x        = (const float*)d_in[0];
    const float* supports = (const float*)d_in[1];
    const float* bn_gamma = (const float*)d_in[2];
    const float* bn_beta  = (const float*)d_in[3];
    const float* res_w    = (const float*)d_in[4];
    const float* res_b    = (const float*)d_in[5];
    const float* aff_w    = (const float*)d_in[6];
    const float* aff_b    = (const float*)d_in[7];
    const float* gate_w   = (const float*)d_in[8];
    const float* gate_b   = (const float*)d_in[9];
    const float* gc_w     = (const float*)d_in[10];
    const float* gc_b     = (const float*)d_in[11];
    const float* attn_w1  = (const float*)d_in[12];
    const float* attn_b1  = (const float*)d_in[13];
    const float* attn_w2  = (const float*)d_in[14];
    const float* attn_b2  = (const float*)d_in[15];
    const float* attn_w3  = (const float*)d_in[16];
    const float* attn_b3  = (const float*)d_in[17];
    float* out = (float*)d_out;

    prep_weights<<<64, 256>>>(res_w, aff_w, gate_w, gc_w, supports);

    for (int l = 0; l < 4; l++) {
        if (l == 0) {
            bn_partial<<<dim3(32, 16), 256>>>(x);
            bn_finalize<<<1, 32>>>(bn_gamma, bn_beta);
        } else {
            bn_finalize2<<<1, 32>>>(bn_gamma + l * 32, bn_beta + l * 32);
        }
        st_front<<<8000, 256>>>(x, l, res_b + l * 32, aff_b + l * 32,
                                gate_b + l * 32, gc_b + l * 32);
        graph_mma<<<dim3(4, 16, 16), 256>>>(l);
    }
    attn_logits<<<8000, 256>>>(x, attn_w1, attn_b1, attn_w2, attn_b2, attn_w3, attn_b3);
    attn_out<<<8000, 256>>>(x, out);
}

// round 9
// speedup vs baseline: 3.8265x; 1.0174x over previous
#include <cuda_runtime.h>
#include <cuda_bf16.h>
#include <cstdint>

// ---------------- scratch (static __device__, no allocations) ----------------
// n-major activation layout: [b][n][c*64+t], b-stride 1,024,000
__device__ __align__(16) float g_h[4][16384000];
__device__ __align__(16) float g_y0[16384000];
__device__ __align__(16) __nv_bfloat16 g_z1h[16384000];
__device__ __align__(16) __nv_bfloat16 g_z2h[16384000];
__device__ __align__(16) uint32_t g_Asp[2][256][512];   // bf16x2 k-pair packed A, zero-padded
__device__ float g_bnsum[32 * 16], g_bnsq[32 * 16];
__device__ float g_bnS[32], g_bnQ[32];                  // fused stats (layers >= 1)
__device__ float g_scale[32], g_shift[32];
// fragment-packed tf32 weights for st_front MMA
__device__ __align__(16) uint32_t g_w1f[4][4][16][128]; // [l][mt][kc][lane*4+reg]
__device__ __align__(16) uint32_t g_w2f[4][12][4][64];  // [l][nsub][kc][lane*2+reg]

// ---------------- helpers ----------------
__device__ __forceinline__ uint32_t bf16x2_of(float lo, float hi) {
    uint32_t r; asm("cvt.rn.bf16x2.f32 %0,%1,%2;" : "=r"(r) : "f"(hi), "f"(lo)); return r;
}
__device__ __forceinline__ float to_tf32(float x) {
    asm("cvt.rna.tf32.f32 %0, %1;" : "=f"(x) : "f"(x));
    return x;
}
__device__ __forceinline__ uint32_t tf32_bits(float x) { return __float_as_uint(to_tf32(x)); }

__device__ __forceinline__ void mma_bf16(float& d0, float& d1, float& d2, float& d3,
                                         uint32_t a0, uint32_t a1, uint32_t a2, uint32_t a3,
                                         uint32_t b0, uint32_t b1) {
    asm volatile(
        "mma.sync.aligned.m16n8k16.row.col.f32.bf16.bf16.f32 "
        "{%0,%1,%2,%3},{%4,%5,%6,%7},{%8,%9},{%0,%1,%2,%3};"
        : "+f"(d0), "+f"(d1), "+f"(d2), "+f"(d3)
        : "r"(a0), "r"(a1), "r"(a2), "r"(a3), "r"(b0), "r"(b1));
}
__device__ __forceinline__ void mma_tf32(float& d0, float& d1, float& d2, float& d3,
                                         uint32_t a0, uint32_t a1, uint32_t a2, uint32_t a3,
                                         uint32_t b0, uint32_t b1) {
    asm volatile(
        "mma.sync.aligned.m16n8k8.row.col.f32.tf32.tf32.f32 "
        "{%0,%1,%2,%3},{%4,%5,%6,%7},{%8,%9},{%0,%1,%2,%3};"
        : "+f"(d0), "+f"(d1), "+f"(d2), "+f"(d3)
        : "r"(a0), "r"(a1), "r"(a2), "r"(a3), "r"(b0), "r"(b1));
}

// ---------------- weight packing ----------------
__global__ void prep_weights(const float* __restrict__ rw, const float* __restrict__ aw,
                             const float* __restrict__ gw, const float* __restrict__ gcw,
                             const float* __restrict__ A) {
    int tid = blockIdx.x * blockDim.x + threadIdx.x;
    int nt = gridDim.x * blockDim.x;

    // GEMM1 fragments. K order: k = 32*kk + c for conv taps kk=0..2; k = 96+c for res.
    // tile rows: lr<8 -> aff o=mt*8+lr; lr>=8 -> gate (same o).
    for (int i = tid; i < 4 * 4 * 16 * 32; i += nt) {
        int l = i >> 11;
        int r = i & 2047;
        int mt = r >> 9;
        int r2 = r & 511;
        int kc = r2 >> 5;
        int lane = r2 & 31;
        int g = lane >> 2, tg = lane & 3;
        int o = mt * 8 + g;
        uint32_t* dst = &g_w1f[l][mt][kc][lane * 4];
#pragma unroll
        for (int half = 0; half < 2; half++) {
            int k = kc * 8 + tg + half * 4;
            int kk = k >> 5, c = k & 31;
            float va, vg;
            if (kk < 3) {
                va = aw[l * 3072 + o * 96 + c * 3 + kk];
                vg = gw[l * 3072 + o * 96 + c * 3 + kk];
            } else {
                va = rw[l * 1024 + o * 32 + c];
                vg = 0.f;
            }
            dst[half * 2 + 0] = tf32_bits(va);
            dst[half * 2 + 1] = tf32_bits(vg);
        }
    }
    // GEMM2 fragments (B = W2^T): o'<32 -> y0; 32..63 -> z1; 64..95 -> z2
    for (int i = tid; i < 4 * 12 * 4 * 32; i += nt) {
        int l = i / 1536;
        int r = i % 1536;
        int nsub = r / 128;
        int r2 = r % 128;
        int kc = r2 >> 5;
        int lane = r2 & 31;
        int g = lane >> 2, tg = lane & 3;
        int o = nsub * 8 + g;
        int grp = o >> 5, oo = o & 31;
        uint32_t* dst = &g_w2f[l][nsub][kc][lane * 2];
        dst[0] = tf32_bits(gcw[l * 3072 + oo * 96 + grp * 32 + kc * 8 + tg]);
        dst[1] = tf32_bits(gcw[l * 3072 + oo * 96 + grp * 32 + kc * 8 + tg + 4]);
    }
    // pack A supports into bf16x2 k-pairs
    for (int i = tid; i < 2 * 256 * 512; i += nt) {
        int e = i >> 17, kp = (i >> 9) & 255, m = i & 511;
        int v0 = 2 * kp, v1 = v0 + 1;
        float lo = (v0 < 500 && m < 500) ? A[(size_t)e * 250000 + (size_t)v0 * 500 + m] : 0.f;
        float hi = (v1 < 500 && m < 500) ? A[(size_t)e * 250000 + (size_t)v1 * 500 + m] : 0.f;
        g_Asp[e][kp][m] = bf16x2_of(lo, hi);
    }
}

// ---------------- batchnorm stats (input x only) ----------------
__global__ void bn_partial(const float* __restrict__ x) {
    int c = blockIdx.x, b = blockIdx.y;
    float s = 0.f, q = 0.f;
    const float* p = x + (size_t)(b * 32 + c) * 32000;
    for (int i = threadIdx.x; i < 32000; i += 256) {
        float v = __ldg(p + i);
        s += v; q += v * v;
    }
    for (int o = 16; o; o >>= 1) {
        s += __shfl_down_sync(0xffffffffu, s, o);
        q += __shfl_down_sync(0xffffffffu, q, o);
    }
    __shared__ float ss[8], qq[8];
    int w = threadIdx.x >> 5;
    if ((threadIdx.x & 31) == 0) { ss[w] = s; qq[w] = q; }
    __syncthreads();
    if (threadIdx.x == 0) {
        float S = 0.f, Q = 0.f;
        for (int i = 0; i < 8; i++) { S += ss[i]; Q += qq[i]; }
        g_bnsum[c * 16 + b] = S;
        g_bnsq[c * 16 + b] = Q;
    }
}

__global__ void bn_finalize(const float* __restrict__ gamma, const float* __restrict__ beta) {
    int c = threadIdx.x;
    float S = 0.f, Q = 0.f;
    for (int b = 0; b < 16; b++) { S += g_bnsum[c * 16 + b]; Q += g_bnsq[c * 16 + b]; }
    const float inv = 1.0f / 512000.0f;
    float m = S * inv;
    float var = Q * inv - m * m;
    float rstd = rsqrtf(var + 1e-5f);
    float sc = gamma[c] * rstd;
    g_scale[c] = sc;
    g_shift[c] = beta[c] - m * sc;
}

__global__ void bn_finalize2(const float* __restrict__ gamma, const float* __restrict__ beta) {
    int c = threadIdx.x;
    float S = g_bnS[c], Q = g_bnQ[c];
    const float inv = 1.0f / 512000.0f;
    float m = S * inv;
    float var = Q * inv - m * m;
    float rstd = rsqrtf(var + 1e-5f);
    float sc = gamma[c] * rstd;
    g_scale[c] = sc;
    g_shift[c] = beta[c] - m * sc;
}

// ---------------- st_front via tf32 tensor cores ----------------
// one (b,n) per block, 256 threads = 8 warps.
// GEMM1: e[64 out][64 t] = W1'[64][128] * B[128][64]; B rows read from ys/xs with col offsets.
// GEMM2: C[64 t][96 out] = x1T[64][32] * W2T[32][96]  (y0|z1|z2 stacked).
__global__ __launch_bounds__(256) void st_front(
    const float* __restrict__ x, int layer,
    const float* __restrict__ rb, const float* __restrict__ ab,
    const float* __restrict__ gb, const float* __restrict__ gcb) {
    __shared__ __align__(16) float ys[32][72];    // relu(bn(x)) at index t+2
    __shared__ __align__(16) float xs[32][72];    // raw x at index t+2
    __shared__ __align__(16) float x1T[64][36];   // t x c

    int tid = threadIdx.x;
    int b = blockIdx.x / 500, n = blockIdx.x % 500;

    if (blockIdx.x == 0 && tid < 32) { g_bnS[tid] = 0.f; g_bnQ[tid] = 0.f; }

    // zero ys left pads (cols 0,1)
    if (tid < 64) ys[tid >> 1][tid & 1] = 0.f;

    if (layer == 0) {
        const float* xb = x + (size_t)b * 1024000 + n * 64;
        for (int i = tid; i < 2048; i += 256) {
            int c = i >> 6, t = i & 63;
            float xv = __ldg(xb + (size_t)c * 32000 + t);
            ys[c][t + 2] = to_tf32(fmaxf(g_scale[c] * xv + g_shift[c], 0.f));
            xs[c][t + 2] = to_tf32(xv);
        }
    } else {
        const float* hb = g_h[layer - 1] + ((size_t)b * 500 + n) * 2048;
        for (int i = tid; i < 2048; i += 256) {
            int c = i >> 6, t = i & 63;
            float xv = hb[i];
            ys[c][t + 2] = to_tf32(fmaxf(g_scale[c] * xv + g_shift[c], 0.f));
            xs[c][t + 2] = to_tf32(xv);
        }
    }
    __syncthreads();

    int lane = tid & 31, wid = tid >> 5;
    int g = lane >> 2, tig = lane & 3;
    int wm = wid & 3, wn = wid >> 2;
    int nbase = wn * 32;

    // ---- GEMM1 ----
    float c1[4][4];
#pragma unroll
    for (int s = 0; s < 4; s++)
#pragma unroll
        for (int k = 0; k < 4; k++) c1[s][k] = 0.f;

#pragma unroll
    for (int kc = 0; kc < 16; kc++) {
        uint4 af = __ldg((const uint4*)&g_w1f[layer][wm][kc][lane * 4]);
        int p = kc >> 2;                 // tap index 0..2 conv, 3 = res (compile-time)
        int cb = (kc & 3) * 8;           // channel block
        const float* base = (p < 3) ? &ys[cb][0] : &xs[cb][0];
        int off = (p < 3) ? p : 2;
#pragma unroll
        for (int s = 0; s < 4; s++) {
            int col = nbase + s * 8 + g + off;
            uint32_t b0 = __float_as_uint(base[tig * 72 + col]);
            uint32_t b1 = __float_as_uint(base[(tig + 4) * 72 + col]);
            mma_tf32(c1[s][0], c1[s][1], c1[s][2], c1[s][3],
                     af.x, af.y, af.z, af.w, b0, b1);
        }
    }

    // ---- x1 = tanh(aff+res+b) * sigmoid(gate+b) ----
    {
        int o = wm * 8 + g;
        float abrb = __ldg(ab + o) + __ldg(rb + o);
        float gbv = __ldg(gb + o);
#pragma unroll
        for (int s = 0; s < 4; s++) {
            int col = nbase + s * 8 + 2 * tig;
            float v0 = tanhf(c1[s][0] + abrb) * (1.f / (1.f + expf(-(c1[s][2] + gbv))));
            float v1 = tanhf(c1[s][1] + abrb) * (1.f / (1.f + expf(-(c1[s][3] + gbv))));
            x1T[col][o] = to_tf32(v0);
            x1T[col + 1][o] = to_tf32(v1);
        }
    }
    __syncthreads();

    // ---- GEMM2: C[t][o'] = x1T * W2T ----
    float c2[6][4];
#pragma unroll
    for (int s = 0; s < 6; s++)
#pragma unroll
        for (int k = 0; k < 4; k++) c2[s][k] = 0.f;

    int tm = wm * 16;
#pragma unroll
    for (int kc = 0; kc < 4; kc++) {
        uint32_t a0 = __float_as_uint(x1T[tm + g][kc * 8 + tig]);
        uint32_t a1 = __float_as_uint(x1T[tm + g + 8][kc * 8 + tig]);
        uint32_t a2 = __float_as_uint(x1T[tm + g][kc * 8 + tig + 4]);
        uint32_t a3 = __float_as_uint(x1T[tm + g + 8][kc * 8 + tig + 4]);
#pragma unroll
        for (int s = 0; s < 6; s++) {
            int nsub = wn * 6 + s;
            uint2 bf = __ldg((const uint2*)&g_w2f[layer][nsub][kc][lane * 2]);
            mma_tf32(c2[s][0], c2[s][1], c2[s][2], c2[s][3],
                     a0, a1, a2, a3, bf.x, bf.y);
        }
    }

    // ---- epilogue: y0 (fp32+bias) / z1,z2 (bf16) ----
    size_t obase = ((size_t)b * 500 + n) * 2048;
    int t0 = tm + g;
#pragma unroll
    for (int s = 0; s < 6; s++) {
        int nsub = wn * 6 + s;
        int o0 = nsub * 8 + 2 * tig;
        if (o0 < 32) {
            float bz0 = __ldg(gcb + o0), bz1 = __ldg(gcb + o0 + 1);
            g_y0[obase + (size_t)o0 * 64 + t0] = c2[s][0] + bz0;
            g_y0[obase + (size_t)(o0 + 1) * 64 + t0] = c2[s][1] + bz1;
            g_y0[obase + (size_t)o0 * 64 + t0 + 8] = c2[s][2] + bz0;
            g_y0[obase + (size_t)(o0 + 1) * 64 + t0 + 8] = c2[s][3] + bz1;
        } else if (o0 < 64) {
            int oz = o0 - 32;
            g_z1h[obase + (size_t)oz * 64 + t0] = __float2bfloat16(c2[s][0]);
            g_z1h[obase + (size_t)(oz + 1) * 64 + t0] = __float2bfloat16(c2[s][1]);
            g_z1h[obase + (size_t)oz * 64 + t0 + 8] = __float2bfloat16(c2[s][2]);
            g_z1h[obase + (size_t)(oz + 1) * 64 + t0 + 8] = __float2bfloat16(c2[s][3]);
        } else {
            int oz = o0 - 64;
            g_z2h[obase + (size_t)oz * 64 + t0] = __float2bfloat16(c2[s][0]);
            g_z2h[obase + (size_t)(oz + 1) * 64 + t0] = __float2bfloat16(c2[s][1]);
            g_z2h[obase + (size_t)oz * 64 + t0 + 8] = __float2bfloat16(c2[s][2]);
            g_z2h[obase + (size_t)(oz + 1) * 64 + t0 + 8] = __float2bfloat16(c2[s][3]);
        }
    }
}

// ---------------- graph diffusion with bf16 tensor cores ----------------
__global__ __launch_bounds__(256) void graph_mma(int layer) {
    __shared__ __align__(16) uint32_t Asp[2][16][136];
    __shared__ __align__(16) uint32_t Zsp[2][16][136];

    int tid = threadIdx.x;
    int m0 = blockIdx.x * 128;
    int n0 = blockIdx.y * 128;
    int bb = blockIdx.z;
    int lane = tid & 31, wid = tid >> 5;
    int wm = wid & 1, wn = wid >> 1;
    int mbase = wm * 64, nbase = wn * 32;
    int g = lane >> 2, tig = lane & 3;

    int r = tid >> 4;
    int seg = (tid & 15) * 8;

    float acc[4][4][4];
#pragma unroll
    for (int i = 0; i < 4; i++)
#pragma unroll
        for (int j = 0; j < 4; j++)
#pragma unroll
            for (int k = 0; k < 4; k++) acc[i][j][k] = 0.f;

    auto load_stage = [&](int st, int buf) {
        int e = st >> 4, s = st & 15;
        int kpg = s * 16 + r;
        const uint4* ap = (const uint4*)&g_Asp[e][kpg][m0 + seg];
        *(uint4*)&Asp[buf][r][seg]     = ap[0];
        *(uint4*)&Asp[buf][r][seg + 4] = ap[1];
        int v0 = 2 * kpg, v1 = v0 + 1;
        const __nv_bfloat16* zb = e ? g_z2h : g_z1h;
        size_t zoff = (size_t)bb * 1024000 + n0 + seg;
        uint4 lo = make_uint4(0, 0, 0, 0), hi = make_uint4(0, 0, 0, 0);
        if (v0 < 500) lo = *(const uint4*)(zb + zoff + (size_t)v0 * 2048);
        if (v1 < 500) hi = *(const uint4*)(zb + zoff + (size_t)v1 * 2048);
        uint4 o0, o1;
        o0.x = __byte_perm(lo.x, hi.x, 0x5410); o0.y = __byte_perm(lo.x, hi.x, 0x7632);
        o0.z = __byte_perm(lo.y, hi.y, 0x5410); o0.w = __byte_perm(lo.y, hi.y, 0x7632);
        o1.x = __byte_perm(lo.z, hi.z, 0x5410); o1.y = __byte_perm(lo.z, hi.z, 0x7632);
        o1.z = __byte_perm(lo.w, hi.w, 0x5410); o1.w = __byte_perm(lo.w, hi.w, 0x7632);
        *(uint4*)&Zsp[buf][r][seg]     = o0;
        *(uint4*)&Zsp[buf][r][seg + 4] = o1;
    };

    load_stage(0, 0);
    __syncthreads();

    for (int st = 0; st < 32; st++) {
        int cur = st & 1;
        if (st + 1 < 32) load_stage(st + 1, cur ^ 1);
#pragma unroll
        for (int ch = 0; ch < 2; ch++) {
            int k0 = ch * 8;
            uint32_t bfr[4][2];
#pragma unroll
            for (int nt = 0; nt < 4; nt++) {
                bfr[nt][0] = Zsp[cur][k0 + tig][nbase + nt * 8 + g];
                bfr[nt][1] = Zsp[cur][k0 + tig + 4][nbase + nt * 8 + g];
            }
#pragma unroll
            for (int mt = 0; mt < 4; mt++) {
                int mr = mbase + mt * 16 + g;
                uint32_t a0 = Asp[cur][k0 + tig][mr];
                uint32_t a1 = Asp[cur][k0 + tig][mr + 8];
                uint32_t a2 = Asp[cur][k0 + tig + 4][mr];
                uint32_t a3 = Asp[cur][k0 + tig + 4][mr + 8];
#pragma unroll
                for (int nt = 0; nt < 4; nt++)
                    mma_bf16(acc[mt][nt][0], acc[mt][nt][1], acc[mt][nt][2], acc[mt][nt][3],
                             a0, a1, a2, a3, bfr[nt][0], bfr[nt][1]);
            }
        }
        __syncthreads();
    }

    float* hout = g_h[layer];
    size_t bbase = (size_t)bb * 1024000;
    float s = 0.f, q = 0.f;
#pragma unroll
    for (int mt = 0; mt < 4; mt++) {
#pragma unroll
        for (int nt = 0; nt < 4; nt++) {
            int w0 = m0 + mbase + mt * 16 + g;
            int j = n0 + nbase + nt * 8 + 2 * tig;
            if (w0 < 500) {
                size_t idx = bbase + (size_t)w0 * 2048 + j;
                float2 y = *(const float2*)(g_y0 + idx);
                float2 rres;
                rres.x = acc[mt][nt][0] + y.x;
                rres.y = acc[mt][nt][1] + y.y;
                *(float2*)(hout + idx) = rres;
                s += rres.x + rres.y;
                q += rres.x * rres.x + rres.y * rres.y;
            }
            if (w0 + 8 < 500) {
                size_t idx = bbase + (size_t)(w0 + 8) * 2048 + j;
                float2 y = *(const float2*)(g_y0 + idx);
                float2 rres;
                rres.x = acc[mt][nt][2] + y.x;
                rres.y = acc[mt][nt][3] + y.y;
                *(float2*)(hout + idx) = rres;
                s += rres.x + rres.y;
                q += rres.x * rres.x + rres.y * rres.y;
            }
        }
    }
    for (int o = 16; o; o >>= 1) {
        s += __shfl_down_sync(0xffffffffu, s, o);
        q += __shfl_down_sync(0xffffffffu, q, o);
    }
    if (lane == 0) {
        int cw = (n0 + nbase) >> 6;
        atomicAdd(&g_bnS[cw], s);
        atomicAdd(&g_bnQ[cw], q);
    }
}

// ---------------- fused attention: logits + softmax + weighted sum ----------------
// dyn smem floats: vbuf[5][32][72] | e1s[64][72] | red[4][64] | lgs[5][64]  = 16704 fl
__global__ __launch_bounds__(256) void attn_fused(
    const float* __restrict__ x,
    const float* __restrict__ w1, const float* __restrict__ b1,
    const float* __restrict__ w2, const float* __restrict__ b2,
    const float* __restrict__ w3,
    float* __restrict__ out) {
    extern __shared__ float sm[];
    float* vbuf = sm;                // 5 x 2304 (32 rows x 72)
    float* e1s  = sm + 11520;        // 64 x 72
    float* red  = sm + 16128;        // 4 x 64
    float* lgs  = sm + 16384;        // 5 x 64

    int tid = threadIdx.x;
    int b = blockIdx.x / 500, n = blockIdx.x % 500;
    int lane = tid & 31, wid = tid >> 5;
    int wm = wid & 3;
    int wn = wid >> 2;
    int g = lane >> 2, tig = lane & 3;

    // preload weight fragments (reused for all 5 layers)
    uint32_t a1f[4][4], a2f[8][4];
#pragma unroll
    for (int kk = 0; kk < 4; kk++) {
        a1f[kk][0] = tf32_bits(__ldg(w1 + (wm * 16 + g) * 32 + kk * 8 + tig));
        a1f[kk][1] = tf32_bits(__ldg(w1 + (wm * 16 + g + 8) * 32 + kk * 8 + tig));
        a1f[kk][2] = tf32_bits(__ldg(w1 + (wm * 16 + g) * 32 + kk * 8 + tig + 4));
        a1f[kk][3] = tf32_bits(__ldg(w1 + (wm * 16 + g + 8) * 32 + kk * 8 + tig + 4));
    }
#pragma unroll
    for (int kk = 0; kk < 8; kk++) {
        a2f[kk][0] = tf32_bits(__ldg(w2 + (wm * 16 + g) * 64 + kk * 8 + tig));
        a2f[kk][1] = tf32_bits(__ldg(w2 + (wm * 16 + g + 8) * 64 + kk * 8 + tig));
        a2f[kk][2] = tf32_bits(__ldg(w2 + (wm * 16 + g) * 64 + kk * 8 + tig + 4));
        a2f[kk][3] = tf32_bits(__ldg(w2 + (wm * 16 + g + 8) * 64 + kk * 8 + tig + 4));
    }
    float b1r0 = b1[wm * 16 + g], b1r1 = b1[wm * 16 + g + 8];
    float b2r0 = b2[wm * 16 + g], b2r1 = b2[wm * 16 + g + 8];
    float w3r0 = w3[wm * 16 + g], w3r1 = w3[wm * 16 + g + 8];

    for (int l = 0; l < 5; l++) {
        float* vb = vbuf + l * 2304;
        __syncthreads();
        if (l == 0) {
            const float* xb = x + (size_t)b * 1024000 + n * 64;
            for (int i = tid; i < 2048; i += 256) {
                int c = i >> 6, t = i & 63;
                vb[c * 72 + t] = fmaxf(__ldg(xb + (size_t)c * 32000 + t), 0.f);
            }
        } else {
            const float* hb = g_h[l - 1] + ((size_t)b * 500 + n) * 2048;
            for (int i = tid; i < 2048; i += 256) {
                int c = i >> 6, t = i & 63;
                vb[c * 72 + t] = fmaxf(hb[i], 0.f);
            }
        }
        __syncthreads();

        // e1 = W1 * relu(h)  (tf32 rounding at fragment load)
        float c1[4][4];
#pragma unroll
        for (int sub = 0; sub < 4; sub++)
#pragma unroll
            for (int k = 0; k < 4; k++) c1[sub][k] = 0.f;
#pragma unroll
        for (int kk = 0; kk < 4; kk++) {
#pragma unroll
            for (int sub = 0; sub < 4; sub++) {
                int col = wn * 32 + sub * 8 + g;
                uint32_t bb0 = tf32_bits(vb[(kk * 8 + tig) * 72 + col]);
                uint32_t bb1 = tf32_bits(vb[(kk * 8 + tig + 4) * 72 + col]);
                mma_tf32(c1[sub][0], c1[sub][1], c1[sub][2], c1[sub][3],
                         a1f[kk][0], a1f[kk][1], a1f[kk][2], a1f[kk][3], bb0, bb1);
            }
        }
#pragma unroll
        for (int sub = 0; sub < 4; sub++) {
            int col = wn * 32 + sub * 8 + 2 * tig;
            e1s[(wm * 16 + g) * 72 + col]     = to_tf32(fmaxf(c1[sub][0] + b1r0, 0.f));
            e1s[(wm * 16 + g) * 72 + col + 1] = to_tf32(fmaxf(c1[sub][1] + b1r0, 0.f));
            e1s[(wm * 16 + g + 8) * 72 + col]     = to_tf32(fmaxf(c1[sub][2] + b1r1, 0.f));
            e1s[(wm * 16 + g + 8) * 72 + col + 1] = to_tf32(fmaxf(c1[sub][3] + b1r1, 0.f));
        }
        __syncthreads();

        // e2 = W2 * e1
        float c2[4][4];
#pragma unroll
        for (int sub = 0; sub < 4; sub++)
#pragma unroll
            for (int k = 0; k < 4; k++) c2[sub][k] = 0.f;
#pragma unroll
        for (int kk = 0; kk < 8; kk++) {
#pragma unroll
            for (int sub = 0; sub < 4; sub++) {
                int col = wn * 32 + sub * 8 + g;
                uint32_t bb0 = __float_as_uint(e1s[(kk * 8 + tig) * 72 + col]);
                uint32_t bb1 = __float_as_uint(e1s[(kk * 8 + tig + 4) * 72 + col]);
                mma_tf32(c2[sub][0], c2[sub][1], c2[sub][2], c2[sub][3],
                         a2f[kk][0], a2f[kk][1], a2f[kk][2], a2f[kk][3], bb0, bb1);
            }
        }
        float p[4][2];
#pragma unroll
        for (int sub = 0; sub < 4; sub++) {
            p[sub][0] = w3r0 * fmaxf(c2[sub][0] + b2r0, 0.f) + w3r1 * fmaxf(c2[sub][2] + b2r1, 0.f);
            p[sub][1] = w3r0 * fmaxf(c2[sub][1] + b2r0, 0.f) + w3r1 * fmaxf(c2[sub][3] + b2r1, 0.f);
        }
#pragma unroll
        for (int off = 4; off <= 16; off <<= 1) {
#pragma unroll
            for (int sub = 0; sub < 4; sub++) {
                p[sub][0] += __shfl_xor_sync(0xffffffffu, p[sub][0], off);
                p[sub][1] += __shfl_xor_sync(0xffffffffu, p[sub][1], off);
            }
        }
        if (g == 0) {
#pragma unroll
            for (int sub = 0; sub < 4; sub++) {
                int col = wn * 32 + sub * 8 + 2 * tig;
                red[wm * 64 + col] = p[sub][0];
                red[wm * 64 + col + 1] = p[sub][1];
            }
        }
        __syncthreads();
        if (tid < 64)
            lgs[l * 64 + tid] = red[tid] + red[64 + tid] + red[128 + tid] + red[192 + tid];
        // (b3 is a uniform shift -> softmax-invariant; omitted)
    }
    __syncthreads();

    // softmax over layers (in-place in lgs)
    if (tid < 64) {
        float lg[5];
        float m = -1e30f;
#pragma unroll
        for (int l = 0; l < 5; l++) {
            lg[l] = lgs[l * 64 + tid];
            m = fmaxf(m, lg[l]);
        }
        float s = 0.f;
#pragma unroll
        for (int l = 0; l < 5; l++) { lg[l] = expf(lg[l] - m); s += lg[l]; }
        float inv = 1.f / s;
#pragma unroll
        for (int l = 0; l < 5; l++) lgs[l * 64 + tid] = lg[l] * inv;
    }
    __syncthreads();

    // weighted sum from smem-resident relu(h)
    for (int i = tid; i < 2048; i += 256) {
        int c = i >> 6, t = i & 63;
        float s = lgs[t] * vbuf[c * 72 + t];
        s += lgs[64 + t]  * vbuf[2304 + c * 72 + t];
        s += lgs[128 + t] * vbuf[4608 + c * 72 + t];
        s += lgs[192 + t] * vbuf[6912 + c * 72 + t];
        s += lgs[256 + t] * vbuf[9216 + c * 72 + t];
        out[((size_t)(b * 32 + c) * 500 + n) * 64 + t] = s;
    }
}

// ---------------- launch ----------------
extern "C" void kernel_launch(void* const* d_in, const int* in_sizes, int n_in,
                              void* d_out, int out_size) {
    (void)in_sizes; (void)n_in; (void)out_size;
    const float* x        = (const float*)d_in[0];
    const float* supports = (const float*)d_in[1];
    const float* bn_gamma = (const float*)d_in[2];
    const float* bn_beta  = (const float*)d_in[3];
    const float* res_w    = (const float*)d_in[4];
    const float* res_b    = (const float*)d_in[5];
    const float* aff_w    = (const float*)d_in[6];
    const float* aff_b    = (const float*)d_in[7];
    const float* gate_w   = (const float*)d_in[8];
    const float* gate_b   = (const float*)d_in[9];
    const float* gc_w     = (const float*)d_in[10];
    const float* gc_b     = (const float*)d_in[11];
    const float* attn_w1  = (const float*)d_in[12];
    const float* attn_b1  = (const float*)d_in[13];
    const float* attn_w2  = (const float*)d_in[14];
    const float* attn_b2  = (const float*)d_in[15];
    const float* attn_w3  = (const float*)d_in[16];
    float* out = (float*)d_out;

    cudaFuncSetAttribute(attn_fused, cudaFuncAttributeMaxDynamicSharedMemorySize, 66816);

    prep_weights<<<64, 256>>>(res_w, aff_w, gate_w, gc_w, supports);

    for (int l = 0; l < 4; l++) {
        if (l == 0) {
            bn_partial<<<dim3(32, 16), 256>>>(x);
            bn_finalize<<<1, 32>>>(bn_gamma, bn_beta);
        } else {
            bn_finalize2<<<1, 32>>>(bn_gamma + l * 32, bn_beta + l * 32);
        }
        st_front<<<8000, 256>>>(x, l, res_b + l * 32, aff_b + l * 32,
                                gate_b + l * 32, gc_b + l * 32);
        graph_mma<<<dim3(4, 16, 16), 256>>>(l);
    }
    attn_fused<<<8000, 256, 66816>>>(x, attn_w1, attn_b1, attn_w2, attn_b2, attn_w3, out);
}

// round 10
// speedup vs baseline: 4.3027x; 1.1244x over previous
#include <cuda_runtime.h>
#include <cuda_bf16.h>
#include <cstdint>

// ---------------- scratch (static __device__, no allocations) ----------------
// n-major activation layout: [b][n][c*64+t], b-stride 1,024,000
__device__ __align__(16) float g_h[4][16384000];
__device__ __align__(16) float g_y0[16384000];
__device__ __align__(16) __nv_bfloat16 g_z1h[16384000];
__device__ __align__(16) __nv_bfloat16 g_z2h[16384000];
__device__ __align__(16) uint32_t g_Asp[2][256][512];   // bf16x2 k-pair packed A, zero-padded
__device__ float g_bnsum[32 * 16], g_bnsq[32 * 16];
__device__ float g_bnS[32], g_bnQ[32];                  // fused stats (layers >= 1)
__device__ float g_scale[32], g_shift[32];
// fragment-packed tf32 weights for st_front MMA
__device__ __align__(16) uint32_t g_w1f[4][4][16][128]; // [l][mt][kc][lane*4+reg]  (GEMM1 A)
__device__ __align__(16) uint32_t g_w2f[4][6][4][128];  // [l][mt2][kc][lane*4+reg] (GEMM2 A = W2, M=96)

// ---------------- helpers ----------------
__device__ __forceinline__ uint32_t bf16x2_of(float lo, float hi) {
    uint32_t r; asm("cvt.rn.bf16x2.f32 %0,%1,%2;" : "=r"(r) : "f"(hi), "f"(lo)); return r;
}
__device__ __forceinline__ float to_tf32(float x) {
    asm("cvt.rna.tf32.f32 %0, %1;" : "=f"(x) : "f"(x));
    return x;
}
__device__ __forceinline__ uint32_t tf32_bits(float x) { return __float_as_uint(to_tf32(x)); }

__device__ __forceinline__ void mma_bf16(float& d0, float& d1, float& d2, float& d3,
                                         uint32_t a0, uint32_t a1, uint32_t a2, uint32_t a3,
                                         uint32_t b0, uint32_t b1) {
    asm volatile(
        "mma.sync.aligned.m16n8k16.row.col.f32.bf16.bf16.f32 "
        "{%0,%1,%2,%3},{%4,%5,%6,%7},{%8,%9},{%0,%1,%2,%3};"
        : "+f"(d0), "+f"(d1), "+f"(d2), "+f"(d3)
        : "r"(a0), "r"(a1), "r"(a2), "r"(a3), "r"(b0), "r"(b1));
}
__device__ __forceinline__ void mma_tf32(float& d0, float& d1, float& d2, float& d3,
                                         uint32_t a0, uint32_t a1, uint32_t a2, uint32_t a3,
                                         uint32_t b0, uint32_t b1) {
    asm volatile(
        "mma.sync.aligned.m16n8k8.row.col.f32.tf32.tf32.f32 "
        "{%0,%1,%2,%3},{%4,%5,%6,%7},{%8,%9},{%0,%1,%2,%3};"
        : "+f"(d0), "+f"(d1), "+f"(d2), "+f"(d3)
        : "r"(a0), "r"(a1), "r"(a2), "r"(a3), "r"(b0), "r"(b1));
}

// ---------------- weight packing ----------------
__global__ void prep_weights(const float* __restrict__ rw, const float* __restrict__ aw,
                             const float* __restrict__ gw, const float* __restrict__ gcw,
                             const float* __restrict__ A) {
    int tid = blockIdx.x * blockDim.x + threadIdx.x;
    int nt = gridDim.x * blockDim.x;

    // GEMM1 fragments. K order: k = 32*kk + c for conv taps kk=0..2; k = 96+c for res.
    for (int i = tid; i < 4 * 4 * 16 * 32; i += nt) {
        int l = i >> 11;
        int r = i & 2047;
        int mt = r >> 9;
        int r2 = r & 511;
        int kc = r2 >> 5;
        int lane = r2 & 31;
        int g = lane >> 2, tg = lane & 3;
        int o = mt * 8 + g;
        uint32_t* dst = &g_w1f[l][mt][kc][lane * 4];
#pragma unroll
        for (int half = 0; half < 2; half++) {
            int k = kc * 8 + tg + half * 4;
            int kk = k >> 5, c = k & 31;
            float va, vg;
            if (kk < 3) {
                va = aw[l * 3072 + o * 96 + c * 3 + kk];
                vg = gw[l * 3072 + o * 96 + c * 3 + kk];
            } else {
                va = rw[l * 1024 + o * 32 + c];
                vg = 0.f;
            }
            dst[half * 2 + 0] = tf32_bits(va);
            dst[half * 2 + 1] = tf32_bits(vg);
        }
    }
    // GEMM2 A fragments (W2, row-major M=96 x K=32): rows o'<32 y0 | 32..63 z1 | 64..95 z2
    // a0=A[o][k], a1=A[o+8][k], a2=A[o][k+4], a3=A[o+8][k+4]
    for (int i = tid; i < 4 * 6 * 4 * 32; i += nt) {
        int l = i / 768;
        int r = i % 768;
        int mt2 = r / 128;
        int r2 = r % 128;
        int kc = r2 >> 5;
        int lane = r2 & 31;
        int g = lane >> 2, tg = lane & 3;
        uint32_t* dst = &g_w2f[l][mt2][kc][lane * 4];
#pragma unroll
        for (int half = 0; half < 2; half++) {
            int k = kc * 8 + tg + half * 4;
#pragma unroll
            for (int rr = 0; rr < 2; rr++) {
                int o = mt2 * 16 + g + rr * 8;
                int grp = o >> 5, oo = o & 31;
                dst[half * 2 + rr] = tf32_bits(gcw[l * 3072 + oo * 96 + grp * 32 + k]);
            }
        }
    }
    // pack A supports into bf16x2 k-pairs
    for (int i = tid; i < 2 * 256 * 512; i += nt) {
        int e = i >> 17, kp = (i >> 9) & 255, m = i & 511;
        int v0 = 2 * kp, v1 = v0 + 1;
        float lo = (v0 < 500 && m < 500) ? A[(size_t)e * 250000 + (size_t)v0 * 500 + m] : 0.f;
        float hi = (v1 < 500 && m < 500) ? A[(size_t)e * 250000 + (size_t)v1 * 500 + m] : 0.f;
        g_Asp[e][kp][m] = bf16x2_of(lo, hi);
    }
}

// ---------------- batchnorm stats (input x only) ----------------
__global__ void bn_partial(const float* __restrict__ x) {
    int c = blockIdx.x, b = blockIdx.y;
    float s = 0.f, q = 0.f;
    const float* p = x + (size_t)(b * 32 + c) * 32000;
    for (int i = threadIdx.x; i < 8000; i += 256) {
        float4 v = __ldg((const float4*)(p + i * 4));
        s += v.x + v.y + v.z + v.w;
        q += v.x * v.x + v.y * v.y + v.z * v.z + v.w * v.w;
    }
    for (int o = 16; o; o >>= 1) {
        s += __shfl_down_sync(0xffffffffu, s, o);
        q += __shfl_down_sync(0xffffffffu, q, o);
    }
    __shared__ float ss[8], qq[8];
    int w = threadIdx.x >> 5;
    if ((threadIdx.x & 31) == 0) { ss[w] = s; qq[w] = q; }
    __syncthreads();
    if (threadIdx.x == 0) {
        float S = 0.f, Q = 0.f;
        for (int i = 0; i < 8; i++) { S += ss[i]; Q += qq[i]; }
        g_bnsum[c * 16 + b] = S;
        g_bnsq[c * 16 + b] = Q;
    }
}

__global__ void bn_finalize(const float* __restrict__ gamma, const float* __restrict__ beta) {
    int c = threadIdx.x;
    float S = 0.f, Q = 0.f;
    for (int b = 0; b < 16; b++) { S += g_bnsum[c * 16 + b]; Q += g_bnsq[c * 16 + b]; }
    const float inv = 1.0f / 512000.0f;
    float m = S * inv;
    float var = Q * inv - m * m;
    float rstd = rsqrtf(var + 1e-5f);
    float sc = gamma[c] * rstd;
    g_scale[c] = sc;
    g_shift[c] = beta[c] - m * sc;
}

__global__ void bn_finalize2(const float* __restrict__ gamma, const float* __restrict__ beta) {
    int c = threadIdx.x;
    float S = g_bnS[c], Q = g_bnQ[c];
    const float inv = 1.0f / 512000.0f;
    float m = S * inv;
    float var = Q * inv - m * m;
    float rstd = rsqrtf(var + 1e-5f);
    float sc = gamma[c] * rstd;
    g_scale[c] = sc;
    g_shift[c] = beta[c] - m * sc;
}

// ---------------- st_front via tf32 tensor cores ----------------
// one (b,n) per block, 256 threads = 8 warps.
// GEMM1: e[64 rows][64 t] = W1'[64][128] * B[128][64]; B rows from ys/xs with col offsets.
// GEMM2: C[96 o][64 t] = W2[96][32] * x1C[32][64]; warps 0..5, t-adjacent C pairs.
__global__ __launch_bounds__(256) void st_front(
    const float* __restrict__ x, int layer,
    const float* __restrict__ rb, const float* __restrict__ ab,
    const float* __restrict__ gb, const float* __restrict__ gcb) {
    __shared__ __align__(16) float ys[32][72];    // relu(bn(x)) at index t+2
    __shared__ __align__(16) float xs[32][72];    // raw x at index t+2
    __shared__ __align__(16) float x1C[32][72];   // x1: [c][t]

    int tid = threadIdx.x;
    int b = blockIdx.x / 500, n = blockIdx.x % 500;

    if (blockIdx.x == 0 && tid < 32) { g_bnS[tid] = 0.f; g_bnQ[tid] = 0.f; }

    // zero ys left pads (cols 0,1)
    if (tid < 64) ys[tid >> 1][tid & 1] = 0.f;

    // vectorized load: 512 float4 / 256 threads = 2 each
    if (layer == 0) {
        const float* xb = x + (size_t)b * 1024000 + n * 64;
#pragma unroll
        for (int it = 0; it < 2; it++) {
            int i = tid + it * 256;
            int c = i >> 4, tq = (i & 15) * 4;
            float4 v = __ldg((const float4*)(xb + (size_t)c * 32000 + tq));
            float sc = g_scale[c], sh = g_shift[c];
            float2 ya = { to_tf32(fmaxf(sc * v.x + sh, 0.f)), to_tf32(fmaxf(sc * v.y + sh, 0.f)) };
            float2 yb = { to_tf32(fmaxf(sc * v.z + sh, 0.f)), to_tf32(fmaxf(sc * v.w + sh, 0.f)) };
            *(float2*)&ys[c][tq + 2] = ya;
            *(float2*)&ys[c][tq + 4] = yb;
            float2 xa = { to_tf32(v.x), to_tf32(v.y) };
            float2 xb2 = { to_tf32(v.z), to_tf32(v.w) };
            *(float2*)&xs[c][tq + 2] = xa;
            *(float2*)&xs[c][tq + 4] = xb2;
        }
    } else {
        const float* hb = g_h[layer - 1] + ((size_t)b * 500 + n) * 2048;
#pragma unroll
        for (int it = 0; it < 2; it++) {
            int i = tid + it * 256;
            int c = i >> 4, tq = (i & 15) * 4;
            float4 v = *(const float4*)(hb + i * 4);
            float sc = g_scale[c], sh = g_shift[c];
            float2 ya = { to_tf32(fmaxf(sc * v.x + sh, 0.f)), to_tf32(fmaxf(sc * v.y + sh, 0.f)) };
            float2 yb = { to_tf32(fmaxf(sc * v.z + sh, 0.f)), to_tf32(fmaxf(sc * v.w + sh, 0.f)) };
            *(float2*)&ys[c][tq + 2] = ya;
            *(float2*)&ys[c][tq + 4] = yb;
            float2 xa = { to_tf32(v.x), to_tf32(v.y) };
            float2 xb2 = { to_tf32(v.z), to_tf32(v.w) };
            *(float2*)&xs[c][tq + 2] = xa;
            *(float2*)&xs[c][tq + 4] = xb2;
        }
    }
    __syncthreads();

    int lane = tid & 31, wid = tid >> 5;
    int g = lane >> 2, tig = lane & 3;
    int wm = wid & 3, wn = wid >> 2;
    int nbase = wn * 32;

    // ---- GEMM1 ----
    float c1[4][4];
#pragma unroll
    for (int s = 0; s < 4; s++)
#pragma unroll
        for (int k = 0; k < 4; k++) c1[s][k] = 0.f;

#pragma unroll
    for (int kc = 0; kc < 16; kc++) {
        uint4 af = __ldg((const uint4*)&g_w1f[layer][wm][kc][lane * 4]);
        int p = kc >> 2;                 // tap 0..2 conv, 3 = res
        int cb = (kc & 3) * 8;
        const float* base = (p < 3) ? &ys[cb][0] : &xs[cb][0];
        int off = (p < 3) ? p : 2;
#pragma unroll
        for (int s = 0; s < 4; s++) {
            int col = nbase + s * 8 + g + off;
            uint32_t b0 = __float_as_uint(base[tig * 72 + col]);
            uint32_t b1 = __float_as_uint(base[(tig + 4) * 72 + col]);
            mma_tf32(c1[s][0], c1[s][1], c1[s][2], c1[s][3],
                     af.x, af.y, af.z, af.w, b0, b1);
        }
    }

    // ---- x1 = tanh(aff+res+b) * sigmoid(gate+b); store as [c][t] ----
    {
        int o = wm * 8 + g;
        float abrb = __ldg(ab + o) + __ldg(rb + o);
        float gbv = __ldg(gb + o);
#pragma unroll
        for (int s = 0; s < 4; s++) {
            int col = nbase + s * 8 + 2 * tig;
            float v0 = tanhf(c1[s][0] + abrb) * (1.f / (1.f + expf(-(c1[s][2] + gbv))));
            float v1 = tanhf(c1[s][1] + abrb) * (1.f / (1.f + expf(-(c1[s][3] + gbv))));
            float2 pr = { to_tf32(v0), to_tf32(v1) };
            *(float2*)&x1C[o][col] = pr;
        }
    }
    __syncthreads();

    // ---- GEMM2: C[96 o][64 t] = W2 * x1C (warps 0..5) ----
    if (wid < 6) {
        float c2[8][4];
#pragma unroll
        for (int s = 0; s < 8; s++)
#pragma unroll
            for (int k = 0; k < 4; k++) c2[s][k] = 0.f;

#pragma unroll
        for (int kc = 0; kc < 4; kc++) {
            uint4 af = __ldg((const uint4*)&g_w2f[layer][wid][kc][lane * 4]);
#pragma unroll
            for (int s = 0; s < 8; s++) {
                int col = s * 8 + g;
                uint32_t b0 = __float_as_uint(x1C[kc * 8 + tig][col]);
                uint32_t b1 = __float_as_uint(x1C[kc * 8 + tig + 4][col]);
                mma_tf32(c2[s][0], c2[s][1], c2[s][2], c2[s][3],
                         af.x, af.y, af.z, af.w, b0, b1);
            }
        }

        // ---- epilogue: warps 0,1 -> y0 (float2+bias); 2,3 -> z1 (bf16x2); 4,5 -> z2 ----
        size_t obase = ((size_t)b * 500 + n) * 2048;
        int o0 = wid * 16 + g, o1 = o0 + 8;
        if (wid < 2) {
            float bz0 = __ldg(gcb + o0), bz1 = __ldg(gcb + o1);
#pragma unroll
            for (int s = 0; s < 8; s++) {
                int t = s * 8 + 2 * tig;
                float2 r0 = { c2[s][0] + bz0, c2[s][1] + bz0 };
                float2 r1 = { c2[s][2] + bz1, c2[s][3] + bz1 };
                *(float2*)(g_y0 + obase + (size_t)o0 * 64 + t) = r0;
                *(float2*)(g_y0 + obase + (size_t)o1 * 64 + t) = r1;
            }
        } else if (wid < 4) {
            int z0 = o0 - 32, z1r = o1 - 32;
#pragma unroll
            for (int s = 0; s < 8; s++) {
                int t = s * 8 + 2 * tig;
                *(uint32_t*)(g_z1h + obase + (size_t)z0 * 64 + t) = bf16x2_of(c2[s][0], c2[s][1]);
                *(uint32_t*)(g_z1h + obase + (size_t)z1r * 64 + t) = bf16x2_of(c2[s][2], c2[s][3]);
            }
        } else {
            int z0 = o0 - 64, z1r = o1 - 64;
#pragma unroll
            for (int s = 0; s < 8; s++) {
                int t = s * 8 + 2 * tig;
                *(uint32_t*)(g_z2h + obase + (size_t)z0 * 64 + t) = bf16x2_of(c2[s][0], c2[s][1]);
                *(uint32_t*)(g_z2h + obase + (size_t)z1r * 64 + t) = bf16x2_of(c2[s][2], c2[s][3]);
            }
        }
    }
}

// ---------------- graph diffusion with bf16 tensor cores ----------------
__global__ __launch_bounds__(256) void graph_mma(int layer) {
    __shared__ __align__(16) uint32_t Asp[2][16][136];
    __shared__ __align__(16) uint32_t Zsp[2][16][136];

    int tid = threadIdx.x;
    int m0 = blockIdx.x * 128;
    int n0 = blockIdx.y * 128;
    int bb = blockIdx.z;
    int lane = tid & 31, wid = tid >> 5;
    int wm = wid & 1, wn = wid >> 1;
    int mbase = wm * 64, nbase = wn * 32;
    int g = lane >> 2, tig = lane & 3;

    int r = tid >> 4;
    int seg = (tid & 15) * 8;

    float acc[4][4][4];
#pragma unroll
    for (int i = 0; i < 4; i++)
#pragma unroll
        for (int j = 0; j < 4; j++)
#pragma unroll
            for (int k = 0; k < 4; k++) acc[i][j][k] = 0.f;

    auto load_stage = [&](int st, int buf) {
        int e = st >> 4, s = st & 15;
        int kpg = s * 16 + r;
        const uint4* ap = (const uint4*)&g_Asp[e][kpg][m0 + seg];
        *(uint4*)&Asp[buf][r][seg]     = ap[0];
        *(uint4*)&Asp[buf][r][seg + 4] = ap[1];
        int v0 = 2 * kpg, v1 = v0 + 1;
        const __nv_bfloat16* zb = e ? g_z2h : g_z1h;
        size_t zoff = (size_t)bb * 1024000 + n0 + seg;
        uint4 lo = make_uint4(0, 0, 0, 0), hi = make_uint4(0, 0, 0, 0);
        if (v0 < 500) lo = *(const uint4*)(zb + zoff + (size_t)v0 * 2048);
        if (v1 < 500) hi = *(const uint4*)(zb + zoff + (size_t)v1 * 2048);
        uint4 o0, o1;
        o0.x = __byte_perm(lo.x, hi.x, 0x5410); o0.y = __byte_perm(lo.x, hi.x, 0x7632);
        o0.z = __byte_perm(lo.y, hi.y, 0x5410); o0.w = __byte_perm(lo.y, hi.y, 0x7632);
        o1.x = __byte_perm(lo.z, hi.z, 0x5410); o1.y = __byte_perm(lo.z, hi.z, 0x7632);
        o1.z = __byte_perm(lo.w, hi.w, 0x5410); o1.w = __byte_perm(lo.w, hi.w, 0x7632);
        *(uint4*)&Zsp[buf][r][seg]     = o0;
        *(uint4*)&Zsp[buf][r][seg + 4] = o1;
    };

    load_stage(0, 0);
    __syncthreads();

    for (int st = 0; st < 32; st++) {
        int cur = st & 1;
        if (st + 1 < 32) load_stage(st + 1, cur ^ 1);
#pragma unroll
        for (int ch = 0; ch < 2; ch++) {
            int k0 = ch * 8;
            uint32_t bfr[4][2];
#pragma unroll
            for (int nt = 0; nt < 4; nt++) {
                bfr[nt][0] = Zsp[cur][k0 + tig][nbase + nt * 8 + g];
                bfr[nt][1] = Zsp[cur][k0 + tig + 4][nbase + nt * 8 + g];
            }
#pragma unroll
            for (int mt = 0; mt < 4; mt++) {
                int mr = mbase + mt * 16 + g;
                uint32_t a0 = Asp[cur][k0 + tig][mr];
                uint32_t a1 = Asp[cur][k0 + tig][mr + 8];
                uint32_t a2 = Asp[cur][k0 + tig + 4][mr];
                uint32_t a3 = Asp[cur][k0 + tig + 4][mr + 8];
#pragma unroll
                for (int nt = 0; nt < 4; nt++)
                    mma_bf16(acc[mt][nt][0], acc[mt][nt][1], acc[mt][nt][2], acc[mt][nt][3],
                             a0, a1, a2, a3, bfr[nt][0], bfr[nt][1]);
            }
        }
        __syncthreads();
    }

    float* hout = g_h[layer];
    size_t bbase = (size_t)bb * 1024000;
    float s = 0.f, q = 0.f;
#pragma unroll
    for (int mt = 0; mt < 4; mt++) {
#pragma unroll
        for (int nt = 0; nt < 4; nt++) {
            int w0 = m0 + mbase + mt * 16 + g;
            int j = n0 + nbase + nt * 8 + 2 * tig;
            if (w0 < 500) {
                size_t idx = bbase + (size_t)w0 * 2048 + j;
                float2 y = *(const float2*)(g_y0 + idx);
                float2 rres;
                rres.x = acc[mt][nt][0] + y.x;
                rres.y = acc[mt][nt][1] + y.y;
                *(float2*)(hout + idx) = rres;
                s += rres.x + rres.y;
                q += rres.x * rres.x + rres.y * rres.y;
            }
            if (w0 + 8 < 500) {
                size_t idx = bbase + (size_t)(w0 + 8) * 2048 + j;
                float2 y = *(const float2*)(g_y0 + idx);
                float2 rres;
                rres.x = acc[mt][nt][2] + y.x;
                rres.y = acc[mt][nt][3] + y.y;
                *(float2*)(hout + idx) = rres;
                s += rres.x + rres.y;
                q += rres.x * rres.x + rres.y * rres.y;
            }
        }
    }
    for (int o = 16; o; o >>= 1) {
        s += __shfl_down_sync(0xffffffffu, s, o);
        q += __shfl_down_sync(0xffffffffu, q, o);
    }
    if (lane == 0) {
        int cw = (n0 + nbase) >> 6;
        atomicAdd(&g_bnS[cw], s);
        atomicAdd(&g_bnQ[cw], q);
    }
}

// ---------------- fused attention: logits + softmax + weighted sum ----------------
// dyn smem floats: vbuf[5][32][72] | e1s[64][72] | red[4][64] | lgs[5][64]  = 16704 fl
__global__ __launch_bounds__(256) void attn_fused(
    const float* __restrict__ x,
    const float* __restrict__ w1, const float* __restrict__ b1,
    const float* __restrict__ w2, const float* __restrict__ b2,
    const float* __restrict__ w3,
    float* __restrict__ out) {
    extern __shared__ float sm[];
    float* vbuf = sm;                // 5 x 2304 (32 rows x 72)
    float* e1s  = sm + 11520;        // 64 x 72
    float* red  = sm + 16128;        // 4 x 64
    float* lgs  = sm + 16384;        // 5 x 64

    int tid = threadIdx.x;
    int b = blockIdx.x / 500, n = blockIdx.x % 500;
    int lane = tid & 31, wid = tid >> 5;
    int wm = wid & 3;
    int wn = wid >> 2;
    int g = lane >> 2, tig = lane & 3;

    // preload weight fragments (reused for all 5 layers)
    uint32_t a1f[4][4], a2f[8][4];
#pragma unroll
    for (int kk = 0; kk < 4; kk++) {
        a1f[kk][0] = tf32_bits(__ldg(w1 + (wm * 16 + g) * 32 + kk * 8 + tig));
        a1f[kk][1] = tf32_bits(__ldg(w1 + (wm * 16 + g + 8) * 32 + kk * 8 + tig));
        a1f[kk][2] = tf32_bits(__ldg(w1 + (wm * 16 + g) * 32 + kk * 8 + tig + 4));
        a1f[kk][3] = tf32_bits(__ldg(w1 + (wm * 16 + g + 8) * 32 + kk * 8 + tig + 4));
    }
#pragma unroll
    for (int kk = 0; kk < 8; kk++) {
        a2f[kk][0] = tf32_bits(__ldg(w2 + (wm * 16 + g) * 64 + kk * 8 + tig));
        a2f[kk][1] = tf32_bits(__ldg(w2 + (wm * 16 + g + 8) * 64 + kk * 8 + tig));
        a2f[kk][2] = tf32_bits(__ldg(w2 + (wm * 16 + g) * 64 + kk * 8 + tig + 4));
        a2f[kk][3] = tf32_bits(__ldg(w2 + (wm * 16 + g + 8) * 64 + kk * 8 + tig + 4));
    }
    float b1r0 = b1[wm * 16 + g], b1r1 = b1[wm * 16 + g + 8];
    float b2r0 = b2[wm * 16 + g], b2r1 = b2[wm * 16 + g + 8];
    float w3r0 = w3[wm * 16 + g], w3r1 = w3[wm * 16 + g + 8];

    for (int l = 0; l < 5; l++) {
        float* vb = vbuf + l * 2304;
        __syncthreads();
        if (l == 0) {
            const float* xb = x + (size_t)b * 1024000 + n * 64;
#pragma unroll
            for (int it = 0; it < 2; it++) {
                int i = tid + it * 256;
                int c = i >> 4, tq = (i & 15) * 4;
                float4 v = __ldg((const float4*)(xb + (size_t)c * 32000 + tq));
                float4 rv = { fmaxf(v.x, 0.f), fmaxf(v.y, 0.f), fmaxf(v.z, 0.f), fmaxf(v.w, 0.f) };
                *(float4*)&vb[c * 72 + tq] = rv;
            }
        } else {
            const float* hb = g_h[l - 1] + ((size_t)b * 500 + n) * 2048;
#pragma unroll
            for (int it = 0; it < 2; it++) {
                int i = tid + it * 256;
                int c = i >> 4, tq = (i & 15) * 4;
                float4 v = *(const float4*)(hb + i * 4);
                float4 rv = { fmaxf(v.x, 0.f), fmaxf(v.y, 0.f), fmaxf(v.z, 0.f), fmaxf(v.w, 0.f) };
                *(float4*)&vb[c * 72 + tq] = rv;
            }
        }
        __syncthreads();

        // e1 = W1 * relu(h)  (tf32 rounding at fragment load)
        float c1[4][4];
#pragma unroll
        for (int sub = 0; sub < 4; sub++)
#pragma unroll
            for (int k = 0; k < 4; k++) c1[sub][k] = 0.f;
#pragma unroll
        for (int kk = 0; kk < 4; kk++) {
#pragma unroll
            for (int sub = 0; sub < 4; sub++) {
                int col = wn * 32 + sub * 8 + g;
                uint32_t bb0 = tf32_bits(vb[(kk * 8 + tig) * 72 + col]);
                uint32_t bb1 = tf32_bits(vb[(kk * 8 + tig + 4) * 72 + col]);
                mma_tf32(c1[sub][0], c1[sub][1], c1[sub][2], c1[sub][3],
                         a1f[kk][0], a1f[kk][1], a1f[kk][2], a1f[kk][3], bb0, bb1);
            }
        }
#pragma unroll
        for (int sub = 0; sub < 4; sub++) {
            int col = wn * 32 + sub * 8 + 2 * tig;
            e1s[(wm * 16 + g) * 72 + col]     = to_tf32(fmaxf(c1[sub][0] + b1r0, 0.f));
            e1s[(wm * 16 + g) * 72 + col + 1] = to_tf32(fmaxf(c1[sub][1] + b1r0, 0.f));
            e1s[(wm * 16 + g + 8) * 72 + col]     = to_tf32(fmaxf(c1[sub][2] + b1r1, 0.f));
            e1s[(wm * 16 + g + 8) * 72 + col + 1] = to_tf32(fmaxf(c1[sub][3] + b1r1, 0.f));
        }
        __syncthreads();

        // e2 = W2 * e1
        float c2[4][4];
#pragma unroll
        for (int sub = 0; sub < 4; sub++)
#pragma unroll
            for (int k = 0; k < 4; k++) c2[sub][k] = 0.f;
#pragma unroll
        for (int kk = 0; kk < 8; kk++) {
#pragma unroll
            for (int sub = 0; sub < 4; sub++) {
                int col = wn * 32 + sub * 8 + g;
                uint32_t bb0 = __float_as_uint(e1s[(kk * 8 + tig) * 72 + col]);
                uint32_t bb1 = __float_as_uint(e1s[(kk * 8 + tig + 4) * 72 + col]);
                mma_tf32(c2[sub][0], c2[sub][1], c2[sub][2], c2[sub][3],
                         a2f[kk][0], a2f[kk][1], a2f[kk][2], a2f[kk][3], bb0, bb1);
            }
        }
        float p[4][2];
#pragma unroll
        for (int sub = 0; sub < 4; sub++) {
            p[sub][0] = w3r0 * fmaxf(c2[sub][0] + b2r0, 0.f) + w3r1 * fmaxf(c2[sub][2] + b2r1, 0.f);
            p[sub][1] = w3r0 * fmaxf(c2[sub][1] + b2r0, 0.f) + w3r1 * fmaxf(c2[sub][3] + b2r1, 0.f);
        }
#pragma unroll
        for (int off = 4; off <= 16; off <<= 1) {
#pragma unroll
            for (int sub = 0; sub < 4; sub++) {
                p[sub][0] += __shfl_xor_sync(0xffffffffu, p[sub][0], off);
                p[sub][1] += __shfl_xor_sync(0xffffffffu, p[sub][1], off);
            }
        }
        if (g == 0) {
#pragma unroll
            for (int sub = 0; sub < 4; sub++) {
                int col = wn * 32 + sub * 8 + 2 * tig;
                red[wm * 64 + col] = p[sub][0];
                red[wm * 64 + col + 1] = p[sub][1];
            }
        }
        __syncthreads();
        if (tid < 64)
            lgs[l * 64 + tid] = red[tid] + red[64 + tid] + red[128 + tid] + red[192 + tid];
    }
    __syncthreads();

    // softmax over layers (b3 shift is softmax-invariant; omitted)
    if (tid < 64) {
        float lg[5];
        float m = -1e30f;
#pragma unroll
        for (int l = 0; l < 5; l++) {
            lg[l] = lgs[l * 64 + tid];
            m = fmaxf(m, lg[l]);
        }
        float s = 0.f;
#pragma unroll
        for (int l = 0; l < 5; l++) { lg[l] = expf(lg[l] - m); s += lg[l]; }
        float inv = 1.f / s;
#pragma unroll
        for (int l = 0; l < 5; l++) lgs[l * 64 + tid] = lg[l] * inv;
    }
    __syncthreads();

    // weighted sum from smem-resident relu(h)
    for (int i = tid; i < 2048; i += 256) {
        int c = i >> 6, t = i & 63;
        float s = lgs[t] * vbuf[c * 72 + t];
        s += lgs[64 + t]  * vbuf[2304 + c * 72 + t];
        s += lgs[128 + t] * vbuf[4608 + c * 72 + t];
        s += lgs[192 + t] * vbuf[6912 + c * 72 + t];
        s += lgs[256 + t] * vbuf[9216 + c * 72 + t];
        out[((size_t)(b * 32 + c) * 500 + n) * 64 + t] = s;
    }
}

// ---------------- launch ----------------
extern "C" void kernel_launch(void* const* d_in, const int* in_sizes, int n_in,
                              void* d_out, int out_size) {
    (void)in_sizes; (void)n_in; (void)out_size;
    const float* x        = (const float*)d_in[0];
    const float* supports = (const float*)d_in[1];
    const float* bn_gamma = (const float*)d_in[2];
    const float* bn_beta  = (const float*)d_in[3];
    const float* res_w    = (const float*)d_in[4];
    const float* res_b    = (const float*)d_in[5];
    const float* aff_w    = (const float*)d_in[6];
    const float* aff_b    = (const float*)d_in[7];
    const float* gate_w   = (const float*)d_in[8];
    const float* gate_b   = (const float*)d_in[9];
    const float* gc_w     = (const float*)d_in[10];
    const float* gc_b     = (const float*)d_in[11];
    const float* attn_w1  = (const float*)d_in[12];
    const float* attn_b1  = (const float*)d_in[13];
    const float* attn_w2  = (const float*)d_in[14];
    const float* attn_b2  = (const float*)d_in[15];
    const float* attn_w3  = (const float*)d_in[16];
    float* out = (float*)d_out;

    cudaFuncSetAttribute(attn_fused, cudaFuncAttributeMaxDynamicSharedMemorySize, 66816);

    prep_weights<<<64, 256>>>(res_w, aff_w, gate_w, gc_w, supports);

    for (int l = 0; l < 4; l++) {
        if (l == 0) {
            bn_partial<<<dim3(32, 16), 256>>>(x);
            bn_finalize<<<1, 32>>>(bn_gamma, bn_beta);
        } else {
            bn_finalize2<<<1, 32>>>(bn_gamma + l * 32, bn_beta + l * 32);
        }
        st_front<<<8000, 256>>>(x, l, res_b + l * 32, aff_b + l * 32,
                                gate_b + l * 32, gc_b + l * 32);
        graph_mma<<<dim3(4, 16, 16), 256>>>(l);
    }
    attn_fused<<<8000, 256, 66816>>>(x, attn_w1, attn_b1, attn_w2, attn_b2, attn_w3, out);
}